// round 1
// baseline (speedup 1.0000x reference)
#include <cuda_runtime.h>
#include <math.h>

#define S_LEN 2048
#define BATCH 2
#define HID   2048
#define NH    16
#define NKV   4
#define HD    128
#define MROWS (BATCH*S_LEN)   // 4096

// ---------------- scratch (static device globals; no runtime alloc) -------
__device__ float g_q[(size_t)MROWS * (NH*HD)];    // 32 MB  [bs][h*128+d]
__device__ float g_k[(size_t)MROWS * (NKV*HD)];   //  8 MB
__device__ float g_v[(size_t)MROWS * (NKV*HD)];   //  8 MB
__device__ float g_attn[(size_t)MROWS * (NH*HD)]; // 32 MB

// ======================= SGEMM: C = A @ W + bias ==========================
// A: [M][K] row-major, W: [K][N] row-major, C: [M][N]
#define GBM 128
#define GBN 128
#define GBK 16

__global__ __launch_bounds__(256) void sgemm_bias(
    const float* __restrict__ A, const float* __restrict__ Bw,
    const float* __restrict__ bias, float* __restrict__ C,
    int M, int N, int K)
{
    __shared__ float As[GBK][GBM];
    __shared__ float Bs[GBK][GBN];

    const int tid = threadIdx.x;
    const int tx  = tid & 15;       // 0..15 -> output col group
    const int ty  = tid >> 4;       // 0..15 -> output row group
    const int bm  = blockIdx.y * GBM;
    const int bn  = blockIdx.x * GBN;

    float acc[8][8];
#pragma unroll
    for (int i = 0; i < 8; i++)
#pragma unroll
        for (int j = 0; j < 8; j++) acc[i][j] = 0.f;

    const int a_row = tid >> 2;          // 0..63 (plus +64)
    const int a_col = (tid & 3) * 4;     // 0,4,8,12
    const int b_row = tid >> 4;          // 0..15
    const int b_col = (tid & 15) * 8;    // 0..120

    for (int k0 = 0; k0 < K; k0 += GBK) {
        // A tile -> transposed As[k][m]
#pragma unroll
        for (int r = 0; r < 2; r++) {
            const int row = a_row + r * 64;
            float4 v = *(const float4*)&A[(size_t)(bm + row) * K + k0 + a_col];
            As[a_col + 0][row] = v.x;
            As[a_col + 1][row] = v.y;
            As[a_col + 2][row] = v.z;
            As[a_col + 3][row] = v.w;
        }
        // B tile -> Bs[k][n]
        {
            const float4* src = (const float4*)&Bw[(size_t)(k0 + b_row) * N + bn + b_col];
            *(float4*)&Bs[b_row][b_col]     = src[0];
            *(float4*)&Bs[b_row][b_col + 4] = src[1];
        }
        __syncthreads();

#pragma unroll
        for (int kk = 0; kk < GBK; kk++) {
            float a[8], b[8];
            *(float4*)&a[0] = *(const float4*)&As[kk][ty * 8];
            *(float4*)&a[4] = *(const float4*)&As[kk][ty * 8 + 4];
            *(float4*)&b[0] = *(const float4*)&Bs[kk][tx * 8];
            *(float4*)&b[4] = *(const float4*)&Bs[kk][tx * 8 + 4];
#pragma unroll
            for (int i = 0; i < 8; i++)
#pragma unroll
                for (int j = 0; j < 8; j++)
                    acc[i][j] = fmaf(a[i], b[j], acc[i][j]);
        }
        __syncthreads();
    }

    float bb[8];
    if (bias) {
        *(float4*)&bb[0] = *(const float4*)&bias[bn + tx * 8];
        *(float4*)&bb[4] = *(const float4*)&bias[bn + tx * 8 + 4];
    } else {
#pragma unroll
        for (int j = 0; j < 8; j++) bb[j] = 0.f;
    }

#pragma unroll
    for (int i = 0; i < 8; i++) {
        const int row = bm + ty * 8 + i;
        float* crow = C + (size_t)row * N + bn + tx * 8;
        float4 r0, r1;
        r0.x = acc[i][0] + bb[0]; r0.y = acc[i][1] + bb[1];
        r0.z = acc[i][2] + bb[2]; r0.w = acc[i][3] + bb[3];
        r1.x = acc[i][4] + bb[4]; r1.y = acc[i][5] + bb[5];
        r1.z = acc[i][6] + bb[6]; r1.w = acc[i][7] + bb[7];
        *(float4*)crow       = r0;
        *(float4*)(crow + 4) = r1;
    }
}

// ======================= RoPE (continuous time) ===========================
// X: [MROWS][nheads*128]; pairs (i, i+64) within each head.
__global__ void rope_kernel(float* __restrict__ X, const float* __restrict__ tvals,
                            const float* __restrict__ rope_w, int nheads, int total)
{
    int idx = blockIdx.x * blockDim.x + threadIdx.x;
    if (idx >= total) return;
    const int i  = idx & 63;
    const int hh = (idx >> 6) % nheads;
    const int bs = idx / (64 * nheads);

    const float t = tvals[bs];
    // inv_freq = ROPE_BASE^(-2i/128) = exp(-(2i/128)*ln(10000))
    const float inv_f = expf(-(float)(2 * i) * (9.210340371976184f / 128.0f));
    const float fr = t * inv_f * rope_w[i];
    const float c = cosf(fr);
    const float s = sinf(fr);

    float* row = X + (size_t)bs * ((size_t)nheads * HD) + hh * HD;
    const float x1 = row[i];
    const float x2 = row[i + 64];
    row[i]      = x1 * c - x2 * s;
    row[i + 64] = x2 * c + x1 * s;
}

// ======================= Flash attention (fp32, causal, GQA) ==============
#define FBM 64
#define FBN 64

__global__ __launch_bounds__(256) void flash_kernel(
    const float* __restrict__ Q, const float* __restrict__ K,
    const float* __restrict__ V, float* __restrict__ O)
{
    extern __shared__ float sm[];
    float* QsT = sm;                  // [HD][FBM]
    float* KsT = QsT + HD * FBM;      // [HD][FBN]
    float* Vs  = KsT + HD * FBN;      // [FBN][HD]
    float* PsT = Vs + FBN * HD;       // [FBN][FBM]

    const int qb = blockIdx.x;
    const int bh = blockIdx.y;
    const int b  = bh >> 4;
    const int h  = bh & 15;
    const int kvh = h >> 2;
    const int tid = threadIdx.x;
    const int tx = tid & 15;         // 0..15 -> S cols (4 each) / O cols (8 each)
    const int ty = tid >> 4;         // 0..15 -> rows (4 each)
    const int q0 = qb * FBM;
    const int rowbase = b * S_LEN;

    // ---- load Q tile transposed ----
    {
        const int r  = tid >> 2;
        const int c0 = (tid & 3) * 4;
        const float* qrow = Q + (size_t)(rowbase + q0 + r) * (NH * HD) + h * HD;
#pragma unroll
        for (int c = 0; c < 8; c++) {
            const int col = c0 + c * 16;
            float4 v = *(const float4*)(qrow + col);
            QsT[(col + 0) * FBM + r] = v.x;
            QsT[(col + 1) * FBM + r] = v.y;
            QsT[(col + 2) * FBM + r] = v.z;
            QsT[(col + 3) * FBM + r] = v.w;
        }
    }

    float m_r[4], l_r[4], o_acc[4][8];
#pragma unroll
    for (int i = 0; i < 4; i++) {
        m_r[i] = -3.0e38f;
        l_r[i] = 0.f;
#pragma unroll
        for (int j = 0; j < 8; j++) o_acc[i][j] = 0.f;
    }

    const float scale = 0.08838834764831845f; // 1/sqrt(128)

    for (int nb = 0; nb <= qb; nb++) {
        const int n0 = nb * FBN;
        __syncthreads();   // protect PsT/Vs/KsT from previous iteration (and QsT on first)
        // ---- load K (transposed) and V tiles ----
        {
            const int r  = tid >> 2;
            const int c0 = (tid & 3) * 4;
            const float* krow = K + (size_t)(rowbase + n0 + r) * (NKV * HD) + kvh * HD;
            const float* vrow = V + (size_t)(rowbase + n0 + r) * (NKV * HD) + kvh * HD;
#pragma unroll
            for (int c = 0; c < 8; c++) {
                const int col = c0 + c * 16;
                float4 kv = *(const float4*)(krow + col);
                KsT[(col + 0) * FBN + r] = kv.x;
                KsT[(col + 1) * FBN + r] = kv.y;
                KsT[(col + 2) * FBN + r] = kv.z;
                KsT[(col + 3) * FBN + r] = kv.w;
                *(float4*)(Vs + (size_t)r * HD + col) = *(const float4*)(vrow + col);
            }
        }
        __syncthreads();

        // ---- S = Q @ K^T (4x4 per thread) ----
        float s_acc[4][4];
#pragma unroll
        for (int i = 0; i < 4; i++)
#pragma unroll
            for (int j = 0; j < 4; j++) s_acc[i][j] = 0.f;

#pragma unroll 8
        for (int k = 0; k < HD; k++) {
            float4 a  = *(const float4*)(QsT + k * FBM + ty * 4);
            float4 bk = *(const float4*)(KsT + k * FBN + tx * 4);
            float ar[4] = {a.x, a.y, a.z, a.w};
            float br[4] = {bk.x, bk.y, bk.z, bk.w};
#pragma unroll
            for (int i = 0; i < 4; i++)
#pragma unroll
                for (int j = 0; j < 4; j++)
                    s_acc[i][j] = fmaf(ar[i], br[j], s_acc[i][j]);
        }

        // ---- online softmax update per row ----
#pragma unroll
        for (int i = 0; i < 4; i++) {
            float s[4];
#pragma unroll
            for (int j = 0; j < 4; j++) s[j] = s_acc[i][j] * scale;
            if (nb == qb) {
                const int rg = q0 + ty * 4 + i;
#pragma unroll
                for (int j = 0; j < 4; j++)
                    if (n0 + tx * 4 + j > rg) s[j] = -1.0e30f;
            }
            float rm = fmaxf(fmaxf(s[0], s[1]), fmaxf(s[2], s[3]));
#pragma unroll
            for (int off = 8; off >= 1; off >>= 1)
                rm = fmaxf(rm, __shfl_xor_sync(0xffffffffu, rm, off));
            const float mn = fmaxf(m_r[i], rm);
            const float alpha = expf(m_r[i] - mn);
            float p[4], rs = 0.f;
#pragma unroll
            for (int j = 0; j < 4; j++) { p[j] = expf(s[j] - mn); rs += p[j]; }
#pragma unroll
            for (int off = 8; off >= 1; off >>= 1)
                rs += __shfl_xor_sync(0xffffffffu, rs, off);
            l_r[i] = l_r[i] * alpha + rs;
            m_r[i] = mn;
#pragma unroll
            for (int j = 0; j < 8; j++) o_acc[i][j] *= alpha;
            // store P transposed: PsT[col][row]
#pragma unroll
            for (int j = 0; j < 4; j++)
                PsT[(tx * 4 + j) * FBM + ty * 4 + i] = p[j];
        }
        __syncthreads();

        // ---- O += P @ V ----
#pragma unroll 4
        for (int j = 0; j < FBN; j++) {
            float4 pv = *(const float4*)(PsT + j * FBM + ty * 4);
            float pr[4] = {pv.x, pv.y, pv.z, pv.w};
            float4 v0 = *(const float4*)(Vs + (size_t)j * HD + tx * 8);
            float4 v1 = *(const float4*)(Vs + (size_t)j * HD + tx * 8 + 4);
            float vr[8] = {v0.x, v0.y, v0.z, v0.w, v1.x, v1.y, v1.z, v1.w};
#pragma unroll
            for (int i = 0; i < 4; i++)
#pragma unroll
                for (int jj = 0; jj < 8; jj++)
                    o_acc[i][jj] = fmaf(pr[i], vr[jj], o_acc[i][jj]);
        }
    }

    // ---- write out: [bs][NH*HD] ----
#pragma unroll
    for (int i = 0; i < 4; i++) {
        const float inv = 1.f / l_r[i];
        const int row = rowbase + q0 + ty * 4 + i;
        float* orow = O + (size_t)row * (NH * HD) + h * HD + tx * 8;
        float4 r0, r1;
        r0.x = o_acc[i][0] * inv; r0.y = o_acc[i][1] * inv;
        r0.z = o_acc[i][2] * inv; r0.w = o_acc[i][3] * inv;
        r1.x = o_acc[i][4] * inv; r1.y = o_acc[i][5] * inv;
        r1.z = o_acc[i][6] * inv; r1.w = o_acc[i][7] * inv;
        *(float4*)orow       = r0;
        *(float4*)(orow + 4) = r1;
    }
}

// ======================= launch ===========================================
extern "C" void kernel_launch(void* const* d_in, const int* in_sizes, int n_in,
                              void* d_out, int out_size)
{
    const float* hidden = (const float*)d_in[0];
    const float* tvals  = (const float*)d_in[1];
    const float* wq     = (const float*)d_in[2];
    const float* bq     = (const float*)d_in[3];
    const float* wk     = (const float*)d_in[4];
    const float* bk     = (const float*)d_in[5];
    const float* wv     = (const float*)d_in[6];
    const float* bv     = (const float*)d_in[7];
    const float* wo     = (const float*)d_in[8];
    const float* rope_w = (const float*)d_in[9];
    float* out = (float*)d_out;

    float *q, *k, *v, *attn;
    cudaGetSymbolAddress((void**)&q,    g_q);
    cudaGetSymbolAddress((void**)&k,    g_k);
    cudaGetSymbolAddress((void**)&v,    g_v);
    cudaGetSymbolAddress((void**)&attn, g_attn);

    const dim3 blk(256);

    // QKV projections
    sgemm_bias<<<dim3((NH*HD)/GBN,  MROWS/GBM), blk>>>(hidden, wq, bq, q, MROWS, NH*HD,  HID);
    sgemm_bias<<<dim3((NKV*HD)/GBN, MROWS/GBM), blk>>>(hidden, wk, bk, k, MROWS, NKV*HD, HID);
    sgemm_bias<<<dim3((NKV*HD)/GBN, MROWS/GBM), blk>>>(hidden, wv, bv, v, MROWS, NKV*HD, HID);

    // RoPE on Q and K
    {
        int totq = MROWS * NH * 64;
        int totk = MROWS * NKV * 64;
        rope_kernel<<<(totq + 255) / 256, 256>>>(q, tvals, rope_w, NH,  totq);
        rope_kernel<<<(totk + 255) / 256, 256>>>(k, tvals, rope_w, NKV, totk);
    }

    // Flash attention
    {
        const int smem = (HD*FBM + HD*FBN + FBN*HD + FBN*FBM) * (int)sizeof(float); // 112 KB
        cudaFuncSetAttribute(flash_kernel, cudaFuncAttributeMaxDynamicSharedMemorySize, smem);
        flash_kernel<<<dim3(S_LEN/FBM, BATCH*NH), blk, smem>>>(q, k, v, attn);
    }

    // Output projection (no bias)
    sgemm_bias<<<dim3(HID/GBN, MROWS/GBM), blk>>>(attn, wo, nullptr, out, MROWS, HID, HID);
}

// round 3
// speedup vs baseline: 1.1532x; 1.1532x over previous
#include <cuda_runtime.h>
#include <cstdint>
#include <math.h>

#define S_LEN 2048
#define BATCH 2
#define HID   2048
#define NH    16
#define NKV   4
#define HD    128
#define MROWS (BATCH*S_LEN)   // 4096

// ---------------- scratch (static device globals; no runtime alloc) -------
__device__ float g_q[(size_t)MROWS * (NH*HD)];    // 32 MB
__device__ float g_k[(size_t)MROWS * (NKV*HD)];   //  8 MB
__device__ float g_v[(size_t)MROWS * (NKV*HD)];   //  8 MB
__device__ float g_attn[(size_t)MROWS * (NH*HD)]; // 32 MB
__device__ float g_wqt[(size_t)HID * HID];        // 16 MB  [N][K]
__device__ float g_wkt[(size_t)(NKV*HD) * HID];   //  4 MB
__device__ float g_wvt[(size_t)(NKV*HD) * HID];   //  4 MB
__device__ float g_wot[(size_t)HID * HID];        // 16 MB

// ======================= helpers ==========================================
__device__ __forceinline__ float tf32_rna(float x) {
    uint32_t u;
    asm("cvt.rna.tf32.f32 %0, %1;" : "=r"(u) : "f"(x));
    return __uint_as_float(u);
}

__device__ __forceinline__ void mma_tf32(float c[4],
    uint32_t a0, uint32_t a1, uint32_t a2, uint32_t a3,
    uint32_t b0, uint32_t b1)
{
    asm volatile(
        "mma.sync.aligned.m16n8k8.row.col.f32.tf32.tf32.f32 "
        "{%0,%1,%2,%3}, {%4,%5,%6,%7}, {%8,%9}, {%0,%1,%2,%3};"
        : "+f"(c[0]), "+f"(c[1]), "+f"(c[2]), "+f"(c[3])
        : "r"(a0), "r"(a1), "r"(a2), "r"(a3), "r"(b0), "r"(b1));
}

// ======================= weight transpose: W[K][N] -> WT[N][K] ============
__global__ void transpose_kernel(const float* __restrict__ src, float* __restrict__ dst,
                                 int K, int N)
{
    __shared__ float tile[32][33];
    const int k0 = blockIdx.x * 32;
    const int n0 = blockIdx.y * 32;
    const int x = threadIdx.x;
#pragma unroll
    for (int y = threadIdx.y; y < 32; y += 8)
        tile[y][x] = src[(size_t)(k0 + y) * N + n0 + x];
    __syncthreads();
#pragma unroll
    for (int y = threadIdx.y; y < 32; y += 8)
        dst[(size_t)(n0 + y) * K + k0 + x] = tile[x][y];
}

// ======================= mma.sync tf32 compensated GEMM ===================
// C[M][N] = A[M][2048] @ W + bias, BT = W^T stored [N][2048].
// CTA tile 128x128, warp tile 32x64, k-chunk 32, double-buffered smem.
// 3xTF32: Ahi*Bhi + Ahi*Blo + Alo*Bhi (err ~2^-22).
#define GK    HID
#define CHK   32
#define NCHK  (GK / CHK)      // 64
#define AST   36              // smem row stride (floats): conflict-free frags
#define TILE_F (128 * AST)    // 4608 floats
#define STG_F  (4 * TILE_F)   // Ahi, Alo, Bhi, Blo

__global__ __launch_bounds__(256, 1) void mma_gemm(
    const float* __restrict__ A, const float* __restrict__ BT,
    const float* __restrict__ bias, float* __restrict__ C, int N)
{
    extern __shared__ float sm[];
    const int tid  = threadIdx.x;
    const int lane = tid & 31;
    const int wid  = tid >> 5;
    const int wm   = wid & 3;    // 0..3 -> 32-row slice
    const int wn   = wid >> 2;   // 0..1 -> 64-col slice
    const int bm   = blockIdx.y * 128;
    const int bn   = blockIdx.x * 128;

    const int ar = tid >> 1;            // 0..127
    const int ac = (tid & 1) * 16;      // 0 or 16

    float c[2][8][4];
#pragma unroll
    for (int mi = 0; mi < 2; mi++)
#pragma unroll
        for (int ni = 0; ni < 8; ni++)
#pragma unroll
            for (int j = 0; j < 4; j++) c[mi][ni][j] = 0.f;

    const float* aSrc = A  + (size_t)(bm + ar) * GK + ac;
    const float* bSrc = BT + (size_t)(bn + ar) * GK + ac;

    float4 aPre[4], bPre[4];
#pragma unroll
    for (int j = 0; j < 4; j++) {
        aPre[j] = *(const float4*)(aSrc + 4 * j);
        bPre[j] = *(const float4*)(bSrc + 4 * j);
    }

    // store prefetched chunk into stage 0
    {
        float* Ah = sm;             float* Al = Ah + TILE_F;
        float* Bh = Al + TILE_F;    float* Bl = Bh + TILE_F;
        const int off = ar * AST + ac;
#pragma unroll
        for (int j = 0; j < 4; j++) {
            float4 v = aPre[j], hi, lo;
            hi.x = tf32_rna(v.x); lo.x = tf32_rna(v.x - hi.x);
            hi.y = tf32_rna(v.y); lo.y = tf32_rna(v.y - hi.y);
            hi.z = tf32_rna(v.z); lo.z = tf32_rna(v.z - hi.z);
            hi.w = tf32_rna(v.w); lo.w = tf32_rna(v.w - hi.w);
            *(float4*)(Ah + off + 4 * j) = hi;
            *(float4*)(Al + off + 4 * j) = lo;
            v = bPre[j];
            hi.x = tf32_rna(v.x); lo.x = tf32_rna(v.x - hi.x);
            hi.y = tf32_rna(v.y); lo.y = tf32_rna(v.y - hi.y);
            hi.z = tf32_rna(v.z); lo.z = tf32_rna(v.z - hi.z);
            hi.w = tf32_rna(v.w); lo.w = tf32_rna(v.w - hi.w);
            *(float4*)(Bh + off + 4 * j) = hi;
            *(float4*)(Bl + off + 4 * j) = lo;
        }
    }

    const int frag_r = lane >> 2;   // 0..7
    const int frag_k = lane & 3;    // 0..3

    for (int kt = 0; kt < NCHK; kt++) {
        __syncthreads();
        const int p = kt & 1;

        if (kt < NCHK - 1) {
            const int k0 = (kt + 1) * CHK;
#pragma unroll
            for (int j = 0; j < 4; j++) {
                aPre[j] = *(const float4*)(aSrc + k0 + 4 * j);
                bPre[j] = *(const float4*)(bSrc + k0 + 4 * j);
            }
        }

        const float* Ah = sm + p * STG_F;
        const float* Al = Ah + TILE_F;
        const float* Bh = Al + TILE_F;
        const float* Bl = Bh + TILE_F;

#pragma unroll
        for (int ks = 0; ks < 4; ks++) {
            const int kk = ks * 8 + frag_k;
            uint32_t ah[2][4], al[2][4];
#pragma unroll
            for (int mi = 0; mi < 2; mi++) {
                const int r0 = (wm * 32 + mi * 16 + frag_r) * AST + kk;
                const int r1 = r0 + 8 * AST;
                ah[mi][0] = __float_as_uint(Ah[r0]);
                ah[mi][1] = __float_as_uint(Ah[r1]);
                ah[mi][2] = __float_as_uint(Ah[r0 + 4]);
                ah[mi][3] = __float_as_uint(Ah[r1 + 4]);
                al[mi][0] = __float_as_uint(Al[r0]);
                al[mi][1] = __float_as_uint(Al[r1]);
                al[mi][2] = __float_as_uint(Al[r0 + 4]);
                al[mi][3] = __float_as_uint(Al[r1 + 4]);
            }
#pragma unroll
            for (int ni = 0; ni < 8; ni++) {
                const int nb = (wn * 64 + ni * 8 + frag_r) * AST + kk;
                const uint32_t bh0 = __float_as_uint(Bh[nb]);
                const uint32_t bh1 = __float_as_uint(Bh[nb + 4]);
                const uint32_t bl0 = __float_as_uint(Bl[nb]);
                const uint32_t bl1 = __float_as_uint(Bl[nb + 4]);
#pragma unroll
                for (int mi = 0; mi < 2; mi++) {
                    mma_tf32(c[mi][ni], ah[mi][0], ah[mi][1], ah[mi][2], ah[mi][3], bl0, bl1);
                    mma_tf32(c[mi][ni], al[mi][0], al[mi][1], al[mi][2], al[mi][3], bh0, bh1);
                    mma_tf32(c[mi][ni], ah[mi][0], ah[mi][1], ah[mi][2], ah[mi][3], bh0, bh1);
                }
            }
        }

        if (kt < NCHK - 1) {
            float* nAh = sm + (1 - p) * STG_F;
            float* nAl = nAh + TILE_F;
            float* nBh = nAl + TILE_F;
            float* nBl = nBh + TILE_F;
            const int off = ar * AST + ac;
#pragma unroll
            for (int j = 0; j < 4; j++) {
                float4 v = aPre[j], hi, lo;
                hi.x = tf32_rna(v.x); lo.x = tf32_rna(v.x - hi.x);
                hi.y = tf32_rna(v.y); lo.y = tf32_rna(v.y - hi.y);
                hi.z = tf32_rna(v.z); lo.z = tf32_rna(v.z - hi.z);
                hi.w = tf32_rna(v.w); lo.w = tf32_rna(v.w - hi.w);
                *(float4*)(nAh + off + 4 * j) = hi;
                *(float4*)(nAl + off + 4 * j) = lo;
                v = bPre[j];
                hi.x = tf32_rna(v.x); lo.x = tf32_rna(v.x - hi.x);
                hi.y = tf32_rna(v.y); lo.y = tf32_rna(v.y - hi.y);
                hi.z = tf32_rna(v.z); lo.z = tf32_rna(v.z - hi.z);
                hi.w = tf32_rna(v.w); lo.w = tf32_rna(v.w - hi.w);
                *(float4*)(nBh + off + 4 * j) = hi;
                *(float4*)(nBl + off + 4 * j) = lo;
            }
        }
    }

    // ---- epilogue ----
#pragma unroll
    for (int mi = 0; mi < 2; mi++) {
        const int row0 = bm + wm * 32 + mi * 16 + (lane >> 2);
#pragma unroll
        for (int ni = 0; ni < 8; ni++) {
            const int col = bn + wn * 64 + ni * 8 + (lane & 3) * 2;
            float b0 = 0.f, b1 = 0.f;
            if (bias) { b0 = __ldg(bias + col); b1 = __ldg(bias + col + 1); }
            float2 r0, r1;
            r0.x = c[mi][ni][0] + b0; r0.y = c[mi][ni][1] + b1;
            r1.x = c[mi][ni][2] + b0; r1.y = c[mi][ni][3] + b1;
            *(float2*)(C + (size_t)row0 * N + col)       = r0;
            *(float2*)(C + (size_t)(row0 + 8) * N + col) = r1;
        }
    }
}

// ======================= RoPE (continuous time) ===========================
__global__ void rope_kernel(float* __restrict__ X, const float* __restrict__ tvals,
                            const float* __restrict__ rope_w, int nheads, int total)
{
    int idx = blockIdx.x * blockDim.x + threadIdx.x;
    if (idx >= total) return;
    const int i  = idx & 63;
    const int hh = (idx >> 6) % nheads;
    const int bs = idx / (64 * nheads);

    const float t = tvals[bs];
    const float inv_f = expf(-(float)(2 * i) * (9.210340371976184f / 128.0f));
    const float fr = t * inv_f * rope_w[i];
    const float c = cosf(fr);
    const float s = sinf(fr);

    float* row = X + (size_t)bs * ((size_t)nheads * HD) + hh * HD;
    const float x1 = row[i];
    const float x2 = row[i + 64];
    row[i]      = x1 * c - x2 * s;
    row[i + 64] = x2 * c + x1 * s;
}

// ======================= Flash attention (fp32, causal, GQA) ==============
#define FBM 64
#define FBN 64

__global__ __launch_bounds__(256) void flash_kernel(
    const float* __restrict__ Q, const float* __restrict__ K,
    const float* __restrict__ V, float* __restrict__ O)
{
    extern __shared__ float smf[];
    float* QsT = smf;                 // [HD][FBM]
    float* KsT = QsT + HD * FBM;      // [HD][FBN]
    float* Vs  = KsT + HD * FBN;      // [FBN][HD]
    float* PsT = Vs + FBN * HD;       // [FBN][FBM]

    const int qb = blockIdx.x;
    const int bh = blockIdx.y;
    const int b  = bh >> 4;
    const int h  = bh & 15;
    const int kvh = h >> 2;
    const int tid = threadIdx.x;
    const int tx = tid & 15;
    const int ty = tid >> 4;
    const int q0 = qb * FBM;
    const int rowbase = b * S_LEN;

    {
        const int r  = tid >> 2;
        const int c0 = (tid & 3) * 4;
        const float* qrow = Q + (size_t)(rowbase + q0 + r) * (NH * HD) + h * HD;
#pragma unroll
        for (int c = 0; c < 8; c++) {
            const int col = c0 + c * 16;
            float4 v = *(const float4*)(qrow + col);
            QsT[(col + 0) * FBM + r] = v.x;
            QsT[(col + 1) * FBM + r] = v.y;
            QsT[(col + 2) * FBM + r] = v.z;
            QsT[(col + 3) * FBM + r] = v.w;
        }
    }

    float m_r[4], l_r[4], o_acc[4][8];
#pragma unroll
    for (int i = 0; i < 4; i++) {
        m_r[i] = -3.0e38f;
        l_r[i] = 0.f;
#pragma unroll
        for (int j = 0; j < 8; j++) o_acc[i][j] = 0.f;
    }

    const float scale = 0.08838834764831845f;

    for (int nb = 0; nb <= qb; nb++) {
        const int n0 = nb * FBN;
        __syncthreads();
        {
            const int r  = tid >> 2;
            const int c0 = (tid & 3) * 4;
            const float* krow = K + (size_t)(rowbase + n0 + r) * (NKV * HD) + kvh * HD;
            const float* vrow = V + (size_t)(rowbase + n0 + r) * (NKV * HD) + kvh * HD;
#pragma unroll
            for (int c = 0; c < 8; c++) {
                const int col = c0 + c * 16;
                float4 kv = *(const float4*)(krow + col);
                KsT[(col + 0) * FBN + r] = kv.x;
                KsT[(col + 1) * FBN + r] = kv.y;
                KsT[(col + 2) * FBN + r] = kv.z;
                KsT[(col + 3) * FBN + r] = kv.w;
                *(float4*)(Vs + (size_t)r * HD + col) = *(const float4*)(vrow + col);
            }
        }
        __syncthreads();

        float s_acc[4][4];
#pragma unroll
        for (int i = 0; i < 4; i++)
#pragma unroll
            for (int j = 0; j < 4; j++) s_acc[i][j] = 0.f;

#pragma unroll 8
        for (int k = 0; k < HD; k++) {
            float4 a  = *(const float4*)(QsT + k * FBM + ty * 4);
            float4 bk = *(const float4*)(KsT + k * FBN + tx * 4);
            float ar[4] = {a.x, a.y, a.z, a.w};
            float br[4] = {bk.x, bk.y, bk.z, bk.w};
#pragma unroll
            for (int i = 0; i < 4; i++)
#pragma unroll
                for (int j = 0; j < 4; j++)
                    s_acc[i][j] = fmaf(ar[i], br[j], s_acc[i][j]);
        }

#pragma unroll
        for (int i = 0; i < 4; i++) {
            float s[4];
#pragma unroll
            for (int j = 0; j < 4; j++) s[j] = s_acc[i][j] * scale;
            if (nb == qb) {
                const int rg = q0 + ty * 4 + i;
#pragma unroll
                for (int j = 0; j < 4; j++)
                    if (n0 + tx * 4 + j > rg) s[j] = -1.0e30f;
            }
            float rm = fmaxf(fmaxf(s[0], s[1]), fmaxf(s[2], s[3]));
#pragma unroll
            for (int off = 8; off >= 1; off >>= 1)
                rm = fmaxf(rm, __shfl_xor_sync(0xffffffffu, rm, off));
            const float mn = fmaxf(m_r[i], rm);
            const float alpha = expf(m_r[i] - mn);
            float p[4], rs = 0.f;
#pragma unroll
            for (int j = 0; j < 4; j++) { p[j] = expf(s[j] - mn); rs += p[j]; }
#pragma unroll
            for (int off = 8; off >= 1; off >>= 1)
                rs += __shfl_xor_sync(0xffffffffu, rs, off);
            l_r[i] = l_r[i] * alpha + rs;
            m_r[i] = mn;
#pragma unroll
            for (int j = 0; j < 8; j++) o_acc[i][j] *= alpha;
#pragma unroll
            for (int j = 0; j < 4; j++)
                PsT[(tx * 4 + j) * FBM + ty * 4 + i] = p[j];
        }
        __syncthreads();

#pragma unroll 4
        for (int j = 0; j < FBN; j++) {
            float4 pv = *(const float4*)(PsT + j * FBM + ty * 4);
            float pr[4] = {pv.x, pv.y, pv.z, pv.w};
            float4 v0 = *(const float4*)(Vs + (size_t)j * HD + tx * 8);
            float4 v1 = *(const float4*)(Vs + (size_t)j * HD + tx * 8 + 4);
            float vr[8] = {v0.x, v0.y, v0.z, v0.w, v1.x, v1.y, v1.z, v1.w};
#pragma unroll
            for (int i = 0; i < 4; i++)
#pragma unroll
                for (int jj = 0; jj < 8; jj++)
                    o_acc[i][jj] = fmaf(pr[i], vr[jj], o_acc[i][jj]);
        }
    }

#pragma unroll
    for (int i = 0; i < 4; i++) {
        const float inv = 1.f / l_r[i];
        const int row = rowbase + q0 + ty * 4 + i;
        float* orow = O + (size_t)row * (NH * HD) + h * HD + tx * 8;
        float4 r0, r1;
        r0.x = o_acc[i][0] * inv; r0.y = o_acc[i][1] * inv;
        r0.z = o_acc[i][2] * inv; r0.w = o_acc[i][3] * inv;
        r1.x = o_acc[i][4] * inv; r1.y = o_acc[i][5] * inv;
        r1.z = o_acc[i][6] * inv; r1.w = o_acc[i][7] * inv;
        *(float4*)orow       = r0;
        *(float4*)(orow + 4) = r1;
    }
}

// ======================= launch ===========================================
extern "C" void kernel_launch(void* const* d_in, const int* in_sizes, int n_in,
                              void* d_out, int out_size)
{
    const float* hidden = (const float*)d_in[0];
    const float* tvals  = (const float*)d_in[1];
    const float* wq     = (const float*)d_in[2];
    const float* bq     = (const float*)d_in[3];
    const float* wk     = (const float*)d_in[4];
    const float* bk     = (const float*)d_in[5];
    const float* wv     = (const float*)d_in[6];
    const float* bv     = (const float*)d_in[7];
    const float* wo     = (const float*)d_in[8];
    const float* rope_w = (const float*)d_in[9];
    float* out = (float*)d_out;

    float *q, *k, *v, *attn, *wqt, *wkt, *wvt, *wot;
    cudaGetSymbolAddress((void**)&q,    g_q);
    cudaGetSymbolAddress((void**)&k,    g_k);
    cudaGetSymbolAddress((void**)&v,    g_v);
    cudaGetSymbolAddress((void**)&attn, g_attn);
    cudaGetSymbolAddress((void**)&wqt,  g_wqt);
    cudaGetSymbolAddress((void**)&wkt,  g_wkt);
    cudaGetSymbolAddress((void**)&wvt,  g_wvt);
    cudaGetSymbolAddress((void**)&wot,  g_wot);

    // ---- transpose weights: W[K][N] -> WT[N][K] ----
    {
        dim3 blk(32, 8);
        transpose_kernel<<<dim3(HID/32, HID/32),      blk>>>(wq, wqt, HID, HID);
        transpose_kernel<<<dim3(HID/32, (NKV*HD)/32), blk>>>(wk, wkt, HID, NKV*HD);
        transpose_kernel<<<dim3(HID/32, (NKV*HD)/32), blk>>>(wv, wvt, HID, NKV*HD);
        transpose_kernel<<<dim3(HID/32, HID/32),      blk>>>(wo, wot, HID, HID);
    }

    // ---- mma.sync tf32 GEMMs: QKV projections ----
    const int dyn = 2 * STG_F * (int)sizeof(float);  // 147456 B
    cudaFuncSetAttribute(mma_gemm, cudaFuncAttributeMaxDynamicSharedMemorySize, dyn);
    mma_gemm<<<dim3((NH*HD)/128,  MROWS/128), 256, dyn>>>(hidden, wqt, bq, q, NH*HD);
    mma_gemm<<<dim3((NKV*HD)/128, MROWS/128), 256, dyn>>>(hidden, wkt, bk, k, NKV*HD);
    mma_gemm<<<dim3((NKV*HD)/128, MROWS/128), 256, dyn>>>(hidden, wvt, bv, v, NKV*HD);

    // ---- RoPE on Q and K ----
    {
        int totq = MROWS * NH * 64;
        int totk = MROWS * NKV * 64;
        rope_kernel<<<(totq + 255) / 256, 256>>>(q, tvals, rope_w, NH,  totq);
        rope_kernel<<<(totk + 255) / 256, 256>>>(k, tvals, rope_w, NKV, totk);
    }

    // ---- Flash attention ----
    {
        const int smem = (HD*FBM + HD*FBN + FBN*HD + FBN*FBM) * (int)sizeof(float);
        cudaFuncSetAttribute(flash_kernel, cudaFuncAttributeMaxDynamicSharedMemorySize, smem);
        flash_kernel<<<dim3(S_LEN/FBM, BATCH*NH), 256, smem>>>(q, k, v, attn);
    }

    // ---- Output projection ----
    mma_gemm<<<dim3(HID/128, MROWS/128), 256, dyn>>>(attn, wot, nullptr, out, MROWS == 0 ? HID : HID);
}

// round 4
// speedup vs baseline: 2.2515x; 1.9523x over previous
#include <cuda_runtime.h>
#include <cuda_bf16.h>
#include <cstdint>
#include <math.h>

#define S_LEN 2048
#define BATCH 2
#define HID   2048
#define NH    16
#define NKV   4
#define HD    128
#define MROWS (BATCH*S_LEN)   // 4096

// ---------------- scratch (static device globals; no runtime alloc) -------
__device__ float g_q[(size_t)MROWS * (NH*HD)];
__device__ float g_k[(size_t)MROWS * (NKV*HD)];
__device__ float g_v[(size_t)MROWS * (NKV*HD)];
__device__ float g_attn[(size_t)MROWS * (NH*HD)];
// bf16 split copies for attention
__device__ __nv_bfloat16 g_qh[(size_t)MROWS * (NH*HD)];
__device__ __nv_bfloat16 g_ql[(size_t)MROWS * (NH*HD)];
__device__ __nv_bfloat16 g_kh[(size_t)MROWS * (NKV*HD)];
__device__ __nv_bfloat16 g_kl[(size_t)MROWS * (NKV*HD)];
__device__ __nv_bfloat16 g_vh[(size_t)MROWS * (NKV*HD)];
__device__ __nv_bfloat16 g_vl[(size_t)MROWS * (NKV*HD)];
// bf16 split, transposed weights [N][K]
__device__ __nv_bfloat16 g_wqh[(size_t)HID * HID];
__device__ __nv_bfloat16 g_wql[(size_t)HID * HID];
__device__ __nv_bfloat16 g_wkh[(size_t)(NKV*HD) * HID];
__device__ __nv_bfloat16 g_wkl[(size_t)(NKV*HD) * HID];
__device__ __nv_bfloat16 g_wvh[(size_t)(NKV*HD) * HID];
__device__ __nv_bfloat16 g_wvl[(size_t)(NKV*HD) * HID];
__device__ __nv_bfloat16 g_woh[(size_t)HID * HID];
__device__ __nv_bfloat16 g_wol[(size_t)HID * HID];

// ======================= PTX helpers ======================================
__device__ __forceinline__ uint32_t smem_u32(const void* p) {
    uint32_t a;
    asm("{ .reg .u64 t; cvta.to.shared.u64 t, %1; cvt.u32.u64 %0, t; }"
        : "=r"(a) : "l"(p));
    return a;
}
__device__ __forceinline__ void ldsm4(uint32_t* r, uint32_t addr) {
    asm volatile("ldmatrix.sync.aligned.m8n8.x4.shared.b16 {%0,%1,%2,%3}, [%4];"
        : "=r"(r[0]), "=r"(r[1]), "=r"(r[2]), "=r"(r[3]) : "r"(addr));
}
__device__ __forceinline__ void ldsm4t(uint32_t* r, uint32_t addr) {
    asm volatile("ldmatrix.sync.aligned.m8n8.x4.trans.shared.b16 {%0,%1,%2,%3}, [%4];"
        : "=r"(r[0]), "=r"(r[1]), "=r"(r[2]), "=r"(r[3]) : "r"(addr));
}
__device__ __forceinline__ void mma_bf16(float* c, const uint32_t* a,
                                         uint32_t b0, uint32_t b1) {
    asm volatile(
        "mma.sync.aligned.m16n8k16.row.col.f32.bf16.bf16.f32 "
        "{%0,%1,%2,%3}, {%4,%5,%6,%7}, {%8,%9}, {%0,%1,%2,%3};"
        : "+f"(c[0]), "+f"(c[1]), "+f"(c[2]), "+f"(c[3])
        : "r"(a[0]), "r"(a[1]), "r"(a[2]), "r"(a[3]), "r"(b0), "r"(b1));
}
__device__ __forceinline__ float ex2f(float x) {
    float y; asm("ex2.approx.f32 %0, %1;" : "=f"(y) : "f"(x)); return y;
}
__device__ __forceinline__ uint32_t packbf2(float lo, float hi) {
    __nv_bfloat162 t = __floats2bfloat162_rn(lo, hi);
    return *(uint32_t*)&t;
}
// 8 floats -> 8 hi-bf16 + 8 lo-bf16 (hi = rn(x), lo = rn(x - hi))
__device__ __forceinline__ void split8(const float4 a, const float4 b,
                                       uint4& hi4, uint4& lo4) {
    float f[8] = {a.x, a.y, a.z, a.w, b.x, b.y, b.z, b.w};
    uint32_t hw[4], lw[4];
#pragma unroll
    for (int i = 0; i < 4; i++) {
        float x0 = f[2*i], x1 = f[2*i+1];
        __nv_bfloat16 h0 = __float2bfloat16_rn(x0);
        __nv_bfloat16 h1 = __float2bfloat16_rn(x1);
        float l0 = x0 - __bfloat162float(h0);
        float l1 = x1 - __bfloat162float(h1);
        __nv_bfloat162 hp = __halves2bfloat162(h0, h1);
        hw[i] = *(uint32_t*)&hp;
        lw[i] = packbf2(l0, l1);
    }
    hi4 = make_uint4(hw[0], hw[1], hw[2], hw[3]);
    lo4 = make_uint4(lw[0], lw[1], lw[2], lw[3]);
}

// ======================= weight prep: transpose + bf16 split ==============
__global__ void wsplit_kernel(const float* __restrict__ src,
                              __nv_bfloat16* __restrict__ dh,
                              __nv_bfloat16* __restrict__ dl, int K, int N)
{
    __shared__ float tile[32][33];
    const int k0 = blockIdx.x * 32;
    const int n0 = blockIdx.y * 32;
    const int x = threadIdx.x;
#pragma unroll
    for (int y = threadIdx.y; y < 32; y += 8)
        tile[y][x] = src[(size_t)(k0 + y) * N + n0 + x];
    __syncthreads();
#pragma unroll
    for (int y = threadIdx.y; y < 32; y += 8) {
        float v = tile[x][y];
        __nv_bfloat16 h = __float2bfloat16_rn(v);
        dh[(size_t)(n0 + y) * K + k0 + x] = h;
        dl[(size_t)(n0 + y) * K + k0 + x] = __float2bfloat16_rn(v - __bfloat162float(h));
    }
}

// ======================= bf16-split mma GEMM ==============================
// C[M][N] = A[M][2048] @ W + bias; W pre-split/transposed bf16 [N][K].
// CTA 128x128, 8 warps (warp 32m x 64n), k-chunk 32, double-buffered.
#define GK   HID
#define CHK  32
#define NCHK (GK / CHK)        // 64
#define GPAD 40                // halves per smem row (32 + 8)
#define GT_H (128 * GPAD)      // halves per tile
#define GSTG_H (4 * GT_H)      // Ahi,Alo,Bhi,Blo

__global__ __launch_bounds__(256) void mma_gemm(
    const float* __restrict__ A,
    const __nv_bfloat16* __restrict__ WTh, const __nv_bfloat16* __restrict__ WTl,
    const float* __restrict__ bias, float* __restrict__ C, int N)
{
    extern __shared__ __nv_bfloat16 sg[];
    const uint32_t sbase = smem_u32(sg);

    const int tid  = threadIdx.x;
    const int lane = tid & 31;
    const int wid  = tid >> 5;
    const int wm   = wid & 3;
    const int wn   = wid >> 2;
    const int bm   = blockIdx.y * 128;
    const int bn   = blockIdx.x * 128;

    const int row = tid >> 1;           // 0..127
    const int kh  = (tid & 1) * 16;     // 0 or 16

    float c[2][8][4];
#pragma unroll
    for (int mi = 0; mi < 2; mi++)
#pragma unroll
        for (int ni = 0; ni < 8; ni++)
#pragma unroll
            for (int j = 0; j < 4; j++) c[mi][ni][j] = 0.f;

    const float* aSrc = A + (size_t)(bm + row) * GK + kh;
    const __nv_bfloat16* bhSrc = WTh + (size_t)(bn + row) * GK + kh;
    const __nv_bfloat16* blSrc = WTl + (size_t)(bn + row) * GK + kh;

    // prefetch chunk 0
    float4 aP0, aP1;
    uint4 bPh0, bPh1, bPl0, bPl1;
    aP0 = *(const float4*)(aSrc);
    aP1 = *(const float4*)(aSrc + 4);
    float4 aP2 = *(const float4*)(aSrc + 8);
    float4 aP3 = *(const float4*)(aSrc + 12);
    bPh0 = *(const uint4*)(bhSrc);
    bPh1 = *(const uint4*)(bhSrc + 8);
    bPl0 = *(const uint4*)(blSrc);
    bPl1 = *(const uint4*)(blSrc + 8);

    // store chunk 0 -> stage 0
    {
        __nv_bfloat16* Ah = sg;
        __nv_bfloat16* Al = Ah + GT_H;
        __nv_bfloat16* Bh = Al + GT_H;
        __nv_bfloat16* Bl = Bh + GT_H;
        const int off = row * GPAD + kh;
        uint4 h4, l4;
        split8(aP0, aP1, h4, l4);
        *(uint4*)(Ah + off) = h4; *(uint4*)(Al + off) = l4;
        split8(aP2, aP3, h4, l4);
        *(uint4*)(Ah + off + 8) = h4; *(uint4*)(Al + off + 8) = l4;
        *(uint4*)(Bh + off) = bPh0; *(uint4*)(Bh + off + 8) = bPh1;
        *(uint4*)(Bl + off) = bPl0; *(uint4*)(Bl + off + 8) = bPl1;
    }

    for (int kt = 0; kt < NCHK; kt++) {
        __syncthreads();
        const int p = kt & 1;

        if (kt < NCHK - 1) {
            const int k0 = (kt + 1) * CHK;
            aP0 = *(const float4*)(aSrc + k0);
            aP1 = *(const float4*)(aSrc + k0 + 4);
            aP2 = *(const float4*)(aSrc + k0 + 8);
            aP3 = *(const float4*)(aSrc + k0 + 12);
            bPh0 = *(const uint4*)(bhSrc + k0);
            bPh1 = *(const uint4*)(bhSrc + k0 + 8);
            bPl0 = *(const uint4*)(blSrc + k0);
            bPl1 = *(const uint4*)(blSrc + k0 + 8);
        }

        const uint32_t stage = sbase + p * (GSTG_H * 2);   // bytes
        const uint32_t Ah = stage;
        const uint32_t Al = Ah + GT_H * 2;
        const uint32_t Bh = Al + GT_H * 2;
        const uint32_t Bl = Bh + GT_H * 2;

#pragma unroll
        for (int ks = 0; ks < 2; ks++) {
            const int k0 = ks * 16;
            uint32_t ah[8], al[8];
#pragma unroll
            for (int mi = 0; mi < 2; mi++) {
                const uint32_t aoff =
                    ((wm * 32 + mi * 16 + (lane & 7) + ((lane >> 3) & 1) * 8) * GPAD
                     + k0 + (lane >> 4) * 8) * 2;
                ldsm4(ah + 4 * mi, Ah + aoff);
                ldsm4(al + 4 * mi, Al + aoff);
            }
#pragma unroll
            for (int bg = 0; bg < 4; bg++) {
                const uint32_t boff =
                    ((wn * 64 + bg * 16 + (lane & 7) + (lane >> 4) * 8) * GPAD
                     + k0 + ((lane >> 3) & 1) * 8) * 2;
                uint32_t bh[4], bl[4];
                ldsm4(bh, Bh + boff);
                ldsm4(bl, Bl + boff);
#pragma unroll
                for (int tt = 0; tt < 2; tt++) {
                    const int ni = bg * 2 + tt;
#pragma unroll
                    for (int mi = 0; mi < 2; mi++) {
                        mma_bf16(c[mi][ni], ah + 4 * mi, bl[2*tt], bl[2*tt+1]);
                        mma_bf16(c[mi][ni], al + 4 * mi, bh[2*tt], bh[2*tt+1]);
                        mma_bf16(c[mi][ni], ah + 4 * mi, bh[2*tt], bh[2*tt+1]);
                    }
                }
            }
        }

        if (kt < NCHK - 1) {
            __nv_bfloat16* nAh = sg + (1 - p) * GSTG_H;
            __nv_bfloat16* nAl = nAh + GT_H;
            __nv_bfloat16* nBh = nAl + GT_H;
            __nv_bfloat16* nBl = nBh + GT_H;
            const int off = row * GPAD + kh;
            uint4 h4, l4;
            split8(aP0, aP1, h4, l4);
            *(uint4*)(nAh + off) = h4; *(uint4*)(nAl + off) = l4;
            split8(aP2, aP3, h4, l4);
            *(uint4*)(nAh + off + 8) = h4; *(uint4*)(nAl + off + 8) = l4;
            *(uint4*)(nBh + off) = bPh0; *(uint4*)(nBh + off + 8) = bPh1;
            *(uint4*)(nBl + off) = bPl0; *(uint4*)(nBl + off + 8) = bPl1;
        }
    }

    // ---- epilogue ----
#pragma unroll
    for (int mi = 0; mi < 2; mi++) {
        const int row0 = bm + wm * 32 + mi * 16 + (lane >> 2);
#pragma unroll
        for (int ni = 0; ni < 8; ni++) {
            const int col = bn + wn * 64 + ni * 8 + (lane & 3) * 2;
            float b0 = 0.f, b1 = 0.f;
            if (bias) { b0 = __ldg(bias + col); b1 = __ldg(bias + col + 1); }
            float2 r0, r1;
            r0.x = c[mi][ni][0] + b0; r0.y = c[mi][ni][1] + b1;
            r1.x = c[mi][ni][2] + b0; r1.y = c[mi][ni][3] + b1;
            *(float2*)(C + (size_t)row0 * N + col)       = r0;
            *(float2*)(C + (size_t)(row0 + 8) * N + col) = r1;
        }
    }
}

// ======================= RoPE + bf16 split ================================
__global__ void rope_split(const float* __restrict__ X, const float* __restrict__ tvals,
                           const float* __restrict__ rope_w,
                           __nv_bfloat16* __restrict__ Xh, __nv_bfloat16* __restrict__ Xl,
                           int nheads, int total)
{
    int idx = blockIdx.x * blockDim.x + threadIdx.x;
    if (idx >= total) return;
    const int i  = idx & 63;
    const int hh = (idx >> 6) % nheads;
    const int bs = idx / (64 * nheads);

    const float t = tvals[bs];
    const float inv_f = expf(-(float)(2 * i) * (9.210340371976184f / 128.0f));
    const float fr = t * inv_f * rope_w[i];
    const float cs = cosf(fr);
    const float sn = sinf(fr);

    const size_t base = (size_t)bs * ((size_t)nheads * HD) + hh * HD;
    const float x1 = X[base + i];
    const float x2 = X[base + i + 64];
    const float y1 = x1 * cs - x2 * sn;
    const float y2 = x2 * cs + x1 * sn;
    __nv_bfloat16 h1 = __float2bfloat16_rn(y1);
    __nv_bfloat16 h2 = __float2bfloat16_rn(y2);
    Xh[base + i]      = h1;
    Xh[base + i + 64] = h2;
    Xl[base + i]      = __float2bfloat16_rn(y1 - __bfloat162float(h1));
    Xl[base + i + 64] = __float2bfloat16_rn(y2 - __bfloat162float(h2));
}

__global__ void conv_split(const float* __restrict__ X,
                           __nv_bfloat16* __restrict__ Xh, __nv_bfloat16* __restrict__ Xl,
                           int total)
{
    int idx = blockIdx.x * blockDim.x + threadIdx.x;
    if (idx >= total) return;
    float v = X[idx];
    __nv_bfloat16 h = __float2bfloat16_rn(v);
    Xh[idx] = h;
    Xl[idx] = __float2bfloat16_rn(v - __bfloat162float(h));
}

// ======================= Flash attention (bf16-split mma) =================
// CTA: 64 q-rows, 4 warps (16 rows each). K/V blocks of 64.
#define FPAD 136                     // halves per smem row (128 + 8)
#define FT_H (64 * FPAD)             // halves per tile

__global__ __launch_bounds__(128) void flash_mma(
    const __nv_bfloat16* __restrict__ Qh, const __nv_bfloat16* __restrict__ Ql,
    const __nv_bfloat16* __restrict__ Kh, const __nv_bfloat16* __restrict__ Kl,
    const __nv_bfloat16* __restrict__ Vh, const __nv_bfloat16* __restrict__ Vl,
    float* __restrict__ O)
{
    extern __shared__ __nv_bfloat16 sf[];
    __nv_bfloat16* sQh = sf;
    __nv_bfloat16* sQl = sQh + FT_H;
    __nv_bfloat16* sKh = sQl + FT_H;
    __nv_bfloat16* sKl = sKh + FT_H;
    __nv_bfloat16* sVh = sKl + FT_H;
    __nv_bfloat16* sVl = sVh + FT_H;
    const uint32_t uQh = smem_u32(sQh);
    const uint32_t uQl = smem_u32(sQl);
    const uint32_t uKh = smem_u32(sKh);
    const uint32_t uKl = smem_u32(sKl);
    const uint32_t uVh = smem_u32(sVh);
    const uint32_t uVl = smem_u32(sVl);

    const int qb = blockIdx.x;
    const int bh = blockIdx.y;
    const int b  = bh >> 4;
    const int h  = bh & 15;
    const int kvh = h >> 2;
    const int tid = threadIdx.x;
    const int lane = tid & 31;
    const int w = tid >> 5;           // warp 0..3 -> q rows w*16..w*16+15
    const int q0 = qb * 64;
    const int rowbase = b * S_LEN;

    // ---- load Q tile (64 x 128) hi/lo ----
    {
        const int r  = tid >> 1;
        const int c0 = (tid & 1) * 64;
        const size_t g = (size_t)(rowbase + q0 + r) * (NH * HD) + h * HD + c0;
        const int s = r * FPAD + c0;
#pragma unroll
        for (int j = 0; j < 8; j++) {
            *(uint4*)(sQh + s + 8 * j) = *(const uint4*)(Qh + g + 8 * j);
            *(uint4*)(sQl + s + 8 * j) = *(const uint4*)(Ql + g + 8 * j);
        }
    }

    float o[16][4];
#pragma unroll
    for (int ni = 0; ni < 16; ni++)
#pragma unroll
        for (int j = 0; j < 4; j++) o[ni][j] = 0.f;
    float m0 = -1.0e30f, m1 = -1.0e30f, l0 = 0.f, l1 = 0.f;

    const float SC2 = 0.12751744900459843f;  // (1/sqrt(128)) * log2(e)

    for (int nb = 0; nb <= qb; nb++) {
        const int n0 = nb * 64;
        __syncthreads();
        // ---- load K/V tiles (64 x 128) hi/lo ----
        {
            const int r  = tid >> 1;
            const int c0 = (tid & 1) * 64;
            const size_t g = (size_t)(rowbase + n0 + r) * (NKV * HD) + kvh * HD + c0;
            const int s = r * FPAD + c0;
#pragma unroll
            for (int j = 0; j < 8; j++) {
                *(uint4*)(sKh + s + 8 * j) = *(const uint4*)(Kh + g + 8 * j);
                *(uint4*)(sKl + s + 8 * j) = *(const uint4*)(Kl + g + 8 * j);
                *(uint4*)(sVh + s + 8 * j) = *(const uint4*)(Vh + g + 8 * j);
                *(uint4*)(sVl + s + 8 * j) = *(const uint4*)(Vl + g + 8 * j);
            }
        }
        __syncthreads();

        // ---- S = Q K^T (split bf16, fp32 accum) ----
        float s[8][4];
#pragma unroll
        for (int ni = 0; ni < 8; ni++)
#pragma unroll
            for (int j = 0; j < 4; j++) s[ni][j] = 0.f;

#pragma unroll
        for (int ks = 0; ks < 8; ks++) {
            const int k0 = ks * 16;
            uint32_t ah[4], al[4];
            const uint32_t aoff =
                ((w * 16 + (lane & 7) + ((lane >> 3) & 1) * 8) * FPAD
                 + k0 + (lane >> 4) * 8) * 2;
            ldsm4(ah, uQh + aoff);
            ldsm4(al, uQl + aoff);
#pragma unroll
            for (int bg = 0; bg < 4; bg++) {
                const uint32_t boff =
                    ((bg * 16 + (lane & 7) + (lane >> 4) * 8) * FPAD
                     + k0 + ((lane >> 3) & 1) * 8) * 2;
                uint32_t bhF[4], blF[4];
                ldsm4(bhF, uKh + boff);
                ldsm4(blF, uKl + boff);
#pragma unroll
                for (int tt = 0; tt < 2; tt++) {
                    const int ni = bg * 2 + tt;
                    mma_bf16(s[ni], ah, blF[2*tt], blF[2*tt+1]);
                    mma_bf16(s[ni], al, bhF[2*tt], bhF[2*tt+1]);
                    mma_bf16(s[ni], ah, bhF[2*tt], bhF[2*tt+1]);
                }
            }
        }

        // ---- online softmax (log2 domain) ----
        const int r0g = q0 + w * 16 + (lane >> 2);
        const int r1g = r0g + 8;
        float rmax0 = -1.0e30f, rmax1 = -1.0e30f;
#pragma unroll
        for (int ni = 0; ni < 8; ni++) {
            const int colb = n0 + ni * 8 + (lane & 3) * 2;
#pragma unroll
            for (int j = 0; j < 4; j++) {
                float z = s[ni][j] * SC2;
                const int col = colb + (j & 1);
                const int rw  = (j < 2) ? r0g : r1g;
                if (nb == qb && col > rw) z = -1.0e30f;
                s[ni][j] = z;
            }
            rmax0 = fmaxf(rmax0, fmaxf(s[ni][0], s[ni][1]));
            rmax1 = fmaxf(rmax1, fmaxf(s[ni][2], s[ni][3]));
        }
        rmax0 = fmaxf(rmax0, __shfl_xor_sync(0xffffffffu, rmax0, 1));
        rmax0 = fmaxf(rmax0, __shfl_xor_sync(0xffffffffu, rmax0, 2));
        rmax1 = fmaxf(rmax1, __shfl_xor_sync(0xffffffffu, rmax1, 1));
        rmax1 = fmaxf(rmax1, __shfl_xor_sync(0xffffffffu, rmax1, 2));

        const float mn0 = fmaxf(m0, rmax0);
        const float mn1 = fmaxf(m1, rmax1);
        const float al0 = ex2f(m0 - mn0);
        const float al1 = ex2f(m1 - mn1);
        m0 = mn0; m1 = mn1;

        float ls0 = 0.f, ls1 = 0.f;
#pragma unroll
        for (int ni = 0; ni < 8; ni++) {
            s[ni][0] = ex2f(s[ni][0] - mn0);
            s[ni][1] = ex2f(s[ni][1] - mn0);
            s[ni][2] = ex2f(s[ni][2] - mn1);
            s[ni][3] = ex2f(s[ni][3] - mn1);
            ls0 += s[ni][0] + s[ni][1];
            ls1 += s[ni][2] + s[ni][3];
        }
        l0 = l0 * al0 + ls0;
        l1 = l1 * al1 + ls1;
#pragma unroll
        for (int ni = 0; ni < 16; ni++) {
            o[ni][0] *= al0; o[ni][1] *= al0;
            o[ni][2] *= al1; o[ni][3] *= al1;
        }

        // ---- O += P V (P split in registers, V split in smem) ----
#pragma unroll
        for (int kk = 0; kk < 4; kk++) {
            float p0 = s[2*kk][0],   p1 = s[2*kk][1],   p2 = s[2*kk][2],   p3 = s[2*kk][3];
            float q1 = s[2*kk+1][0], q2 = s[2*kk+1][1], q3 = s[2*kk+1][2], q4 = s[2*kk+1][3];
            uint32_t ph[4], pl[4];
            {
                __nv_bfloat16 h0 = __float2bfloat16_rn(p0), h1 = __float2bfloat16_rn(p1);
                __nv_bfloat16 h2 = __float2bfloat16_rn(p2), h3 = __float2bfloat16_rn(p3);
                __nv_bfloat162 t01 = __halves2bfloat162(h0, h1);
                __nv_bfloat162 t23 = __halves2bfloat162(h2, h3);
                ph[0] = *(uint32_t*)&t01; ph[1] = *(uint32_t*)&t23;
                pl[0] = packbf2(p0 - __bfloat162float(h0), p1 - __bfloat162float(h1));
                pl[1] = packbf2(p2 - __bfloat162float(h2), p3 - __bfloat162float(h3));
                h0 = __float2bfloat16_rn(q1); h1 = __float2bfloat16_rn(q2);
                h2 = __float2bfloat16_rn(q3); h3 = __float2bfloat16_rn(q4);
                t01 = __halves2bfloat162(h0, h1);
                t23 = __halves2bfloat162(h2, h3);
                ph[2] = *(uint32_t*)&t01; ph[3] = *(uint32_t*)&t23;
                pl[2] = packbf2(q1 - __bfloat162float(h0), q2 - __bfloat162float(h1));
                pl[3] = packbf2(q3 - __bfloat162float(h2), q4 - __bfloat162float(h3));
            }
#pragma unroll
            for (int vg = 0; vg < 8; vg++) {
                const int d0 = vg * 16;
                const uint32_t voff =
                    ((kk * 16 + (lane & 7) + ((lane >> 3) & 1) * 8) * FPAD
                     + d0 + (lane >> 4) * 8) * 2;
                uint32_t vh[4], vl[4];
                ldsm4t(vh, uVh + voff);
                ldsm4t(vl, uVl + voff);
#pragma unroll
                for (int tt = 0; tt < 2; tt++) {
                    const int ni = vg * 2 + tt;
                    mma_bf16(o[ni], ph, vl[2*tt], vl[2*tt+1]);
                    mma_bf16(o[ni], pl, vh[2*tt], vh[2*tt+1]);
                    mma_bf16(o[ni], ph, vh[2*tt], vh[2*tt+1]);
                }
            }
        }
    }

    // ---- finalize: reduce l across quad, normalize, write ----
    float lf0 = l0, lf1 = l1;
    lf0 += __shfl_xor_sync(0xffffffffu, lf0, 1);
    lf0 += __shfl_xor_sync(0xffffffffu, lf0, 2);
    lf1 += __shfl_xor_sync(0xffffffffu, lf1, 1);
    lf1 += __shfl_xor_sync(0xffffffffu, lf1, 2);
    const float inv0 = 1.f / lf0;
    const float inv1 = 1.f / lf1;

    const int gr0 = rowbase + q0 + w * 16 + (lane >> 2);
    const int gr1 = gr0 + 8;
#pragma unroll
    for (int ni = 0; ni < 16; ni++) {
        const int col = h * HD + ni * 8 + (lane & 3) * 2;
        float2 r0, r1;
        r0.x = o[ni][0] * inv0; r0.y = o[ni][1] * inv0;
        r1.x = o[ni][2] * inv1; r1.y = o[ni][3] * inv1;
        *(float2*)(O + (size_t)gr0 * (NH * HD) + col) = r0;
        *(float2*)(O + (size_t)gr1 * (NH * HD) + col) = r1;
    }
}

// ======================= launch ===========================================
extern "C" void kernel_launch(void* const* d_in, const int* in_sizes, int n_in,
                              void* d_out, int out_size)
{
    const float* hidden = (const float*)d_in[0];
    const float* tvals  = (const float*)d_in[1];
    const float* wq     = (const float*)d_in[2];
    const float* bq     = (const float*)d_in[3];
    const float* wk     = (const float*)d_in[4];
    const float* bk     = (const float*)d_in[5];
    const float* wv     = (const float*)d_in[6];
    const float* bv     = (const float*)d_in[7];
    const float* wo     = (const float*)d_in[8];
    const float* rope_w = (const float*)d_in[9];
    float* out = (float*)d_out;

    float *q, *k, *v, *attn;
    __nv_bfloat16 *qh, *ql, *kh, *kl, *vh, *vl;
    __nv_bfloat16 *wqh, *wql, *wkh, *wkl, *wvh, *wvl, *woh, *wol;
    cudaGetSymbolAddress((void**)&q,    g_q);
    cudaGetSymbolAddress((void**)&k,    g_k);
    cudaGetSymbolAddress((void**)&v,    g_v);
    cudaGetSymbolAddress((void**)&attn, g_attn);
    cudaGetSymbolAddress((void**)&qh,   g_qh);
    cudaGetSymbolAddress((void**)&ql,   g_ql);
    cudaGetSymbolAddress((void**)&kh,   g_kh);
    cudaGetSymbolAddress((void**)&kl,   g_kl);
    cudaGetSymbolAddress((void**)&vh,   g_vh);
    cudaGetSymbolAddress((void**)&vl,   g_vl);
    cudaGetSymbolAddress((void**)&wqh,  g_wqh);
    cudaGetSymbolAddress((void**)&wql,  g_wql);
    cudaGetSymbolAddress((void**)&wkh,  g_wkh);
    cudaGetSymbolAddress((void**)&wkl,  g_wkl);
    cudaGetSymbolAddress((void**)&wvh,  g_wvh);
    cudaGetSymbolAddress((void**)&wvl,  g_wvl);
    cudaGetSymbolAddress((void**)&woh,  g_woh);
    cudaGetSymbolAddress((void**)&wol,  g_wol);

    // ---- weight prep: transpose + bf16 split ----
    {
        dim3 blk(32, 8);
        wsplit_kernel<<<dim3(HID/32, HID/32),      blk>>>(wq, wqh, wql, HID, HID);
        wsplit_kernel<<<dim3(HID/32, (NKV*HD)/32), blk>>>(wk, wkh, wkl, HID, NKV*HD);
        wsplit_kernel<<<dim3(HID/32, (NKV*HD)/32), blk>>>(wv, wvh, wvl, HID, NKV*HD);
        wsplit_kernel<<<dim3(HID/32, HID/32),      blk>>>(wo, woh, wol, HID, HID);
    }

    // ---- QKV projections (bf16-split mma) ----
    const int gdyn = 2 * GSTG_H * 2;  // bytes: 2 stages * 4 tiles * 128*40 halves
    cudaFuncSetAttribute(mma_gemm, cudaFuncAttributeMaxDynamicSharedMemorySize, gdyn);
    mma_gemm<<<dim3((NH*HD)/128,  MROWS/128), 256, gdyn>>>(hidden, wqh, wql, bq, q, NH*HD);
    mma_gemm<<<dim3((NKV*HD)/128, MROWS/128), 256, gdyn>>>(hidden, wkh, wkl, bk, k, NKV*HD);
    mma_gemm<<<dim3((NKV*HD)/128, MROWS/128), 256, gdyn>>>(hidden, wvh, wvl, bv, v, NKV*HD);

    // ---- RoPE + bf16 split (Q, K); V convert ----
    {
        int totq = MROWS * NH * 64;
        int totk = MROWS * NKV * 64;
        int totv = MROWS * NKV * HD;
        rope_split<<<(totq + 255) / 256, 256>>>(q, tvals, rope_w, qh, ql, NH,  totq);
        rope_split<<<(totk + 255) / 256, 256>>>(k, tvals, rope_w, kh, kl, NKV, totk);
        conv_split<<<(totv + 255) / 256, 256>>>(v, vh, vl, totv);
    }

    // ---- Flash attention (bf16-split mma) ----
    {
        const int fdyn = 6 * FT_H * 2;  // 6 tiles * 64*136 halves * 2B = 104448
        cudaFuncSetAttribute(flash_mma, cudaFuncAttributeMaxDynamicSharedMemorySize, fdyn);
        flash_mma<<<dim3(S_LEN/64, BATCH*NH), 128, fdyn>>>(qh, ql, kh, kl, vh, vl, attn);
    }

    // ---- Output projection ----
    mma_gemm<<<dim3(HID/128, MROWS/128), 256, gdyn>>>(attn, woh, wol, nullptr, out, HID);
}

// round 6
// speedup vs baseline: 2.2544x; 1.0013x over previous
#include <cuda_runtime.h>
#include <cuda_bf16.h>
#include <cstdint>
#include <math.h>

#define S_LEN 2048
#define BATCH 2
#define HID   2048
#define NH    16
#define NKV   4
#define HD    128
#define MROWS (BATCH*S_LEN)   // 4096

// ---------------- scratch (static device globals; no runtime alloc) -------
__device__ float g_q[(size_t)MROWS * (NH*HD)];
__device__ float g_k[(size_t)MROWS * (NKV*HD)];
// bf16 split operands
__device__ __nv_bfloat16 g_hh[(size_t)MROWS * HID];       // hidden hi
__device__ __nv_bfloat16 g_hl[(size_t)MROWS * HID];       // hidden lo
__device__ __nv_bfloat16 g_qh[(size_t)MROWS * (NH*HD)];
__device__ __nv_bfloat16 g_ql[(size_t)MROWS * (NH*HD)];
__device__ __nv_bfloat16 g_kh[(size_t)MROWS * (NKV*HD)];
__device__ __nv_bfloat16 g_kl[(size_t)MROWS * (NKV*HD)];
__device__ __nv_bfloat16 g_vh[(size_t)MROWS * (NKV*HD)];
__device__ __nv_bfloat16 g_vl[(size_t)MROWS * (NKV*HD)];
__device__ __nv_bfloat16 g_oh[(size_t)MROWS * (NH*HD)];   // attn out hi
__device__ __nv_bfloat16 g_ol[(size_t)MROWS * (NH*HD)];   // attn out lo
// bf16 split, transposed weights [N][K]
__device__ __nv_bfloat16 g_wqh[(size_t)HID * HID];
__device__ __nv_bfloat16 g_wql[(size_t)HID * HID];
__device__ __nv_bfloat16 g_wkh[(size_t)(NKV*HD) * HID];
__device__ __nv_bfloat16 g_wkl[(size_t)(NKV*HD) * HID];
__device__ __nv_bfloat16 g_wvh[(size_t)(NKV*HD) * HID];
__device__ __nv_bfloat16 g_wvl[(size_t)(NKV*HD) * HID];
__device__ __nv_bfloat16 g_woh[(size_t)HID * HID];
__device__ __nv_bfloat16 g_wol[(size_t)HID * HID];

// ======================= PTX helpers ======================================
__device__ __forceinline__ uint32_t smem_u32(const void* p) {
    uint32_t a;
    asm("{ .reg .u64 t; cvta.to.shared.u64 t, %1; cvt.u32.u64 %0, t; }"
        : "=r"(a) : "l"(p));
    return a;
}
__device__ __forceinline__ void ldsm4(uint32_t* r, uint32_t addr) {
    asm volatile("ldmatrix.sync.aligned.m8n8.x4.shared.b16 {%0,%1,%2,%3}, [%4];"
        : "=r"(r[0]), "=r"(r[1]), "=r"(r[2]), "=r"(r[3]) : "r"(addr));
}
__device__ __forceinline__ void ldsm4t(uint32_t* r, uint32_t addr) {
    asm volatile("ldmatrix.sync.aligned.m8n8.x4.trans.shared.b16 {%0,%1,%2,%3}, [%4];"
        : "=r"(r[0]), "=r"(r[1]), "=r"(r[2]), "=r"(r[3]) : "r"(addr));
}
__device__ __forceinline__ void mma_bf16(float* c, const uint32_t* a,
                                         uint32_t b0, uint32_t b1) {
    asm volatile(
        "mma.sync.aligned.m16n8k16.row.col.f32.bf16.bf16.f32 "
        "{%0,%1,%2,%3}, {%4,%5,%6,%7}, {%8,%9}, {%0,%1,%2,%3};"
        : "+f"(c[0]), "+f"(c[1]), "+f"(c[2]), "+f"(c[3])
        : "r"(a[0]), "r"(a[1]), "r"(a[2]), "r"(a[3]), "r"(b0), "r"(b1));
}
__device__ __forceinline__ float ex2f(float x) {
    float y; asm("ex2.approx.f32 %0, %1;" : "=f"(y) : "f"(x)); return y;
}
__device__ __forceinline__ void cp16(uint32_t dst, const void* src) {
    asm volatile("cp.async.ca.shared.global [%0], [%1], 16;" :: "r"(dst), "l"(src));
}
#define CP_COMMIT() asm volatile("cp.async.commit_group;" ::: "memory")
#define CP_WAIT(N)  asm volatile("cp.async.wait_group %0;" :: "n"(N) : "memory")

__device__ __forceinline__ uint32_t packbf2(float a, float b) {
    __nv_bfloat162 t = __floats2bfloat162_rn(a, b);
    return *(uint32_t*)&t;
}
__device__ __forceinline__ void split2(float x0, float x1, uint32_t& h, uint32_t& l) {
    __nv_bfloat16 h0 = __float2bfloat16_rn(x0);
    __nv_bfloat16 h1 = __float2bfloat16_rn(x1);
    __nv_bfloat162 hp = __halves2bfloat162(h0, h1);
    h = *(uint32_t*)&hp;
    l = packbf2(x0 - __bfloat162float(h0), x1 - __bfloat162float(h1));
}

// ======================= prep kernels =====================================
__global__ void wsplit_kernel(const float* __restrict__ src,
                              __nv_bfloat16* __restrict__ dh,
                              __nv_bfloat16* __restrict__ dl, int K, int N)
{
    __shared__ float tile[32][33];
    const int k0 = blockIdx.x * 32;
    const int n0 = blockIdx.y * 32;
    const int x = threadIdx.x;
#pragma unroll
    for (int y = threadIdx.y; y < 32; y += 8)
        tile[y][x] = src[(size_t)(k0 + y) * N + n0 + x];
    __syncthreads();
#pragma unroll
    for (int y = threadIdx.y; y < 32; y += 8) {
        float v = tile[x][y];
        __nv_bfloat16 h = __float2bfloat16_rn(v);
        dh[(size_t)(n0 + y) * K + k0 + x] = h;
        dl[(size_t)(n0 + y) * K + k0 + x] = __float2bfloat16_rn(v - __bfloat162float(h));
    }
}

__global__ void hsplit_kernel(const float* __restrict__ X,
                              __nv_bfloat16* __restrict__ Xh,
                              __nv_bfloat16* __restrict__ Xl, int total)
{
    int idx = blockIdx.x * blockDim.x + threadIdx.x;
    if (idx >= total) return;
    float v = X[idx];
    __nv_bfloat16 h = __float2bfloat16_rn(v);
    Xh[idx] = h;
    Xl[idx] = __float2bfloat16_rn(v - __bfloat162float(h));
}

__global__ void rope_split(const float* __restrict__ X, const float* __restrict__ tvals,
                           const float* __restrict__ rope_w,
                           __nv_bfloat16* __restrict__ Xh, __nv_bfloat16* __restrict__ Xl,
                           int nheads, int total)
{
    int idx = blockIdx.x * blockDim.x + threadIdx.x;
    if (idx >= total) return;
    const int i  = idx & 63;
    const int hh = (idx >> 6) % nheads;
    const int bs = idx / (64 * nheads);

    const float t = tvals[bs];
    const float inv_f = expf(-(float)(2 * i) * (9.210340371976184f / 128.0f));
    const float fr = t * inv_f * rope_w[i];
    const float cs = cosf(fr);
    const float sn = sinf(fr);

    const size_t base = (size_t)bs * ((size_t)nheads * HD) + hh * HD;
    const float x1 = X[base + i];
    const float x2 = X[base + i + 64];
    const float y1 = x1 * cs - x2 * sn;
    const float y2 = x2 * cs + x1 * sn;
    __nv_bfloat16 h1 = __float2bfloat16_rn(y1);
    __nv_bfloat16 h2 = __float2bfloat16_rn(y2);
    Xh[base + i]      = h1;
    Xh[base + i + 64] = h2;
    Xl[base + i]      = __float2bfloat16_rn(y1 - __bfloat162float(h1));
    Xl[base + i + 64] = __float2bfloat16_rn(y2 - __bfloat162float(h2));
}

// ======================= bf16-split mma GEMM (cp.async 3-stage) ===========
// C = A @ W^T(+bias); A pre-split bf16 hi/lo [M][2048]; W pre-split [N][2048].
// CTA 128x128, 8 warps (32m x 64n each), k-chunk 32.
#define GK   HID
#define CHK  32
#define NCHK (GK / CHK)        // 64
#define GPAD 40                // halves per smem row
#define GT_H (128 * GPAD)      // 5120 halves per tile
#define GSTG_H (4 * GT_H)      // per stage (Ah,Al,Bh,Bl)
#define GSTG_B (GSTG_H * 2)    // 40960 bytes
#define NSTG 3

template<bool SPLIT_OUT>
__global__ __launch_bounds__(256) void mma_gemm(
    const __nv_bfloat16* __restrict__ Agh, const __nv_bfloat16* __restrict__ Agl,
    const __nv_bfloat16* __restrict__ WTh, const __nv_bfloat16* __restrict__ WTl,
    const float* __restrict__ bias, float* __restrict__ C,
    __nv_bfloat16* __restrict__ Ch, __nv_bfloat16* __restrict__ Cl, int N)
{
    extern __shared__ __nv_bfloat16 sg[];
    const uint32_t sbase = smem_u32(sg);

    const int tid  = threadIdx.x;
    const int lane = tid & 31;
    const int wid  = tid >> 5;
    const int wm   = wid & 3;
    const int wn   = wid >> 2;
    const int bm   = blockIdx.y * 128;
    const int bn   = blockIdx.x * 128;

    float c[2][8][4];
#pragma unroll
    for (int mi = 0; mi < 2; mi++)
#pragma unroll
        for (int ni = 0; ni < 8; ni++)
#pragma unroll
            for (int j = 0; j < 4; j++) c[mi][ni][j] = 0.f;

    // cp.async chunk issue: 4 tiles, each 128 rows x 4 chunks(16B); 2 per thread per tile
    auto issue = [&](int kt, int stg) {
        const uint32_t sb = sbase + stg * GSTG_B;
#pragma unroll
        for (int j = 0; j < 2; j++) {
            const int cch = tid * 2 + j;
            const int row = cch >> 2;
            const int off = (cch & 3) * 8;
            const uint32_t d = sb + (row * GPAD + off) * 2;
            const size_t gA = (size_t)(bm + row) * GK + kt * CHK + off;
            const size_t gB = (size_t)(bn + row) * GK + kt * CHK + off;
            cp16(d,                 Agh + gA);
            cp16(d + GT_H * 2,      Agl + gA);
            cp16(d + GT_H * 4,      WTh + gB);
            cp16(d + GT_H * 6,      WTl + gB);
        }
        CP_COMMIT();
    };

    issue(0, 0);
    issue(1, 1);

    for (int kt = 0; kt < NCHK; kt++) {
        CP_WAIT(1);
        __syncthreads();

        const uint32_t stage = sbase + (kt % NSTG) * GSTG_B;
        const uint32_t Ah = stage;
        const uint32_t Al = Ah + GT_H * 2;
        const uint32_t Bh = Al + GT_H * 2;
        const uint32_t Bl = Bh + GT_H * 2;

#pragma unroll
        for (int ks = 0; ks < 2; ks++) {
            const int k0 = ks * 16;
            uint32_t ah[8], al[8];
#pragma unroll
            for (int mi = 0; mi < 2; mi++) {
                const uint32_t aoff =
                    ((wm * 32 + mi * 16 + (lane & 7) + ((lane >> 3) & 1) * 8) * GPAD
                     + k0 + (lane >> 4) * 8) * 2;
                ldsm4(ah + 4 * mi, Ah + aoff);
                ldsm4(al + 4 * mi, Al + aoff);
            }
#pragma unroll
            for (int bg = 0; bg < 4; bg++) {
                const uint32_t boff =
                    ((wn * 64 + bg * 16 + (lane & 7) + (lane >> 4) * 8) * GPAD
                     + k0 + ((lane >> 3) & 1) * 8) * 2;
                uint32_t bh[4], bl[4];
                ldsm4(bh, Bh + boff);
                ldsm4(bl, Bl + boff);
#pragma unroll
                for (int tt = 0; tt < 2; tt++) {
                    const int ni = bg * 2 + tt;
#pragma unroll
                    for (int mi = 0; mi < 2; mi++) {
                        mma_bf16(c[mi][ni], ah + 4 * mi, bl[2*tt], bl[2*tt+1]);
                        mma_bf16(c[mi][ni], al + 4 * mi, bh[2*tt], bh[2*tt+1]);
                        mma_bf16(c[mi][ni], ah + 4 * mi, bh[2*tt], bh[2*tt+1]);
                    }
                }
            }
        }
        __syncthreads();
        if (kt + 2 < NCHK) issue(kt + 2, (kt + 2) % NSTG);
        else CP_COMMIT();   // keep group count advancing for CP_WAIT bookkeeping
    }

    // ---- epilogue ----
#pragma unroll
    for (int mi = 0; mi < 2; mi++) {
        const int row0 = bm + wm * 32 + mi * 16 + (lane >> 2);
#pragma unroll
        for (int ni = 0; ni < 8; ni++) {
            const int col = bn + wn * 64 + ni * 8 + (lane & 3) * 2;
            float b0 = 0.f, b1 = 0.f;
            if (bias) { b0 = __ldg(bias + col); b1 = __ldg(bias + col + 1); }
            const float y00 = c[mi][ni][0] + b0, y01 = c[mi][ni][1] + b1;
            const float y10 = c[mi][ni][2] + b0, y11 = c[mi][ni][3] + b1;
            if (SPLIT_OUT) {
                uint32_t h, l;
                split2(y00, y01, h, l);
                *(uint32_t*)(Ch + (size_t)row0 * N + col) = h;
                *(uint32_t*)(Cl + (size_t)row0 * N + col) = l;
                split2(y10, y11, h, l);
                *(uint32_t*)(Ch + (size_t)(row0 + 8) * N + col) = h;
                *(uint32_t*)(Cl + (size_t)(row0 + 8) * N + col) = l;
            } else {
                float2 r0, r1;
                r0.x = y00; r0.y = y01;
                r1.x = y10; r1.y = y11;
                *(float2*)(C + (size_t)row0 * N + col)       = r0;
                *(float2*)(C + (size_t)(row0 + 8) * N + col) = r1;
            }
        }
    }
}

// ======================= Flash attention (bf16-split mma) =================
// CTA: 128 q-rows, 8 warps (16 rows each). KV blocks of 64, double-buffered.
#define FPAD 136
#define FQT_H (128 * FPAD)           // q tile halves
#define FKT_H (64 * FPAD)            // kv tile halves
#define FKV_BUF (4 * FKT_H)          // Kh,Kl,Vh,Vl

__global__ __launch_bounds__(256) void flash_mma(
    const __nv_bfloat16* __restrict__ Qh, const __nv_bfloat16* __restrict__ Ql,
    const __nv_bfloat16* __restrict__ Kh, const __nv_bfloat16* __restrict__ Kl,
    const __nv_bfloat16* __restrict__ Vh, const __nv_bfloat16* __restrict__ Vl,
    __nv_bfloat16* __restrict__ Oh, __nv_bfloat16* __restrict__ Ol)
{
    extern __shared__ __nv_bfloat16 sf[];
    const uint32_t uQh = smem_u32(sf);
    const uint32_t uQl = uQh + FQT_H * 2;
    const uint32_t kv0 = uQl + FQT_H * 2;

    const int qb = blockIdx.x;
    const int bh = blockIdx.y;
    const int b  = bh >> 4;
    const int h  = bh & 15;
    const int kvh = h >> 2;
    const int tid = threadIdx.x;
    const int lane = tid & 31;
    const int w = tid >> 5;               // 0..7 -> q rows w*16..w*16+15
    const int q0 = qb * 128;
    const int rowbase = b * S_LEN;

    // issue Q tiles (hi+lo): 2 tiles x 2048 chunks / 256 thr = 8 each
    {
#pragma unroll
        for (int j = 0; j < 8; j++) {
            const int cch = tid * 8 + j;
            const int row = cch >> 4;
            const int off = (cch & 15) * 8;
            const size_t g = (size_t)(rowbase + q0 + row) * (NH * HD) + h * HD + off;
            const uint32_t d = (row * FPAD + off) * 2;
            cp16(uQh + d, Qh + g);
            cp16(uQl + d, Ql + g);
        }
    }
    // issue KV block 0 into buf 0 (same commit group as Q)
    auto issueKV = [&](int nb, int buf) {
        const int n0 = nb * 64;
        const uint32_t base = kv0 + buf * FKV_BUF * 2;
#pragma unroll
        for (int j = 0; j < 4; j++) {
            const int cch = tid * 4 + j;
            const int row = cch >> 4;
            const int off = (cch & 15) * 8;
            const size_t g = (size_t)(rowbase + n0 + row) * (NKV * HD) + kvh * HD + off;
            const uint32_t d = base + (row * FPAD + off) * 2;
            cp16(d,                Kh + g);
            cp16(d + FKT_H * 2,    Kl + g);
            cp16(d + FKT_H * 4,    Vh + g);
            cp16(d + FKT_H * 6,    Vl + g);
        }
    };
    issueKV(0, 0);
    CP_COMMIT();

    float o[16][4];
#pragma unroll
    for (int ni = 0; ni < 16; ni++)
#pragma unroll
        for (int j = 0; j < 4; j++) o[ni][j] = 0.f;
    float m0 = -1.0e30f, m1 = -1.0e30f, l0 = 0.f, l1 = 0.f;

    const float SC2 = 0.12751744900459843f;  // (1/sqrt(128)) * log2(e)
    const int nblocks = 2 * qb + 2;
    const int wrow0 = q0 + w * 16;

    for (int nb = 0; nb < nblocks; nb++) {
        const int n0 = nb * 64;
        CP_WAIT(0);
        __syncthreads();
        if (nb + 1 < nblocks) issueKV(nb + 1, (nb + 1) & 1);
        CP_COMMIT();

        const uint32_t bufb = kv0 + (nb & 1) * FKV_BUF * 2;
        const uint32_t uKh = bufb;
        const uint32_t uKl = bufb + FKT_H * 2;
        const uint32_t uVh = bufb + FKT_H * 4;
        const uint32_t uVl = bufb + FKT_H * 6;

        if (n0 > wrow0 + 15) continue;      // fully masked for this warp

        // ---- S = Q K^T ----
        float s[8][4];
#pragma unroll
        for (int ni = 0; ni < 8; ni++)
#pragma unroll
            for (int j = 0; j < 4; j++) s[ni][j] = 0.f;

#pragma unroll
        for (int ks = 0; ks < 8; ks++) {
            const int k0 = ks * 16;
            uint32_t ah[4], al[4];
            const uint32_t aoff =
                ((w * 16 + (lane & 7) + ((lane >> 3) & 1) * 8) * FPAD
                 + k0 + (lane >> 4) * 8) * 2;
            ldsm4(ah, uQh + aoff);
            ldsm4(al, uQl + aoff);
#pragma unroll
            for (int bg = 0; bg < 4; bg++) {
                const uint32_t boff =
                    ((bg * 16 + (lane & 7) + (lane >> 4) * 8) * FPAD
                     + k0 + ((lane >> 3) & 1) * 8) * 2;
                uint32_t bhF[4], blF[4];
                ldsm4(bhF, uKh + boff);
                ldsm4(blF, uKl + boff);
#pragma unroll
                for (int tt = 0; tt < 2; tt++) {
                    const int ni = bg * 2 + tt;
                    mma_bf16(s[ni], ah, blF[2*tt], blF[2*tt+1]);
                    mma_bf16(s[ni], al, bhF[2*tt], bhF[2*tt+1]);
                    mma_bf16(s[ni], ah, bhF[2*tt], bhF[2*tt+1]);
                }
            }
        }

        // ---- online softmax ----
        const int r0g = wrow0 + (lane >> 2);
        const int r1g = r0g + 8;
        const bool diag = (n0 + 63 > wrow0);
        float rmax0 = -1.0e30f, rmax1 = -1.0e30f;
#pragma unroll
        for (int ni = 0; ni < 8; ni++) {
            const int colb = n0 + ni * 8 + (lane & 3) * 2;
#pragma unroll
            for (int j = 0; j < 4; j++) {
                float z = s[ni][j] * SC2;
                if (diag) {
                    const int col = colb + (j & 1);
                    const int rw  = (j < 2) ? r0g : r1g;
                    if (col > rw) z = -1.0e30f;
                }
                s[ni][j] = z;
            }
            rmax0 = fmaxf(rmax0, fmaxf(s[ni][0], s[ni][1]));
            rmax1 = fmaxf(rmax1, fmaxf(s[ni][2], s[ni][3]));
        }
        rmax0 = fmaxf(rmax0, __shfl_xor_sync(0xffffffffu, rmax0, 1));
        rmax0 = fmaxf(rmax0, __shfl_xor_sync(0xffffffffu, rmax0, 2));
        rmax1 = fmaxf(rmax1, __shfl_xor_sync(0xffffffffu, rmax1, 1));
        rmax1 = fmaxf(rmax1, __shfl_xor_sync(0xffffffffu, rmax1, 2));

        const float mn0 = fmaxf(m0, rmax0);
        const float mn1 = fmaxf(m1, rmax1);
        const float al0 = ex2f(m0 - mn0);
        const float al1 = ex2f(m1 - mn1);
        m0 = mn0; m1 = mn1;

        float ls0 = 0.f, ls1 = 0.f;
#pragma unroll
        for (int ni = 0; ni < 8; ni++) {
            s[ni][0] = ex2f(s[ni][0] - mn0);
            s[ni][1] = ex2f(s[ni][1] - mn0);
            s[ni][2] = ex2f(s[ni][2] - mn1);
            s[ni][3] = ex2f(s[ni][3] - mn1);
            ls0 += s[ni][0] + s[ni][1];
            ls1 += s[ni][2] + s[ni][3];
        }
        l0 = l0 * al0 + ls0;
        l1 = l1 * al1 + ls1;
#pragma unroll
        for (int ni = 0; ni < 16; ni++) {
            o[ni][0] *= al0; o[ni][1] *= al0;
            o[ni][2] *= al1; o[ni][3] *= al1;
        }

        // ---- O += P V ----
#pragma unroll
        for (int kk = 0; kk < 4; kk++) {
            uint32_t ph[4], pl[4];
            split2(s[2*kk][0],   s[2*kk][1],   ph[0], pl[0]);
            split2(s[2*kk][2],   s[2*kk][3],   ph[1], pl[1]);
            split2(s[2*kk+1][0], s[2*kk+1][1], ph[2], pl[2]);
            split2(s[2*kk+1][2], s[2*kk+1][3], ph[3], pl[3]);
#pragma unroll
            for (int vg = 0; vg < 8; vg++) {
                const int d0 = vg * 16;
                const uint32_t voff =
                    ((kk * 16 + (lane & 7) + ((lane >> 3) & 1) * 8) * FPAD
                     + d0 + (lane >> 4) * 8) * 2;
                uint32_t vh[4], vl[4];
                ldsm4t(vh, uVh + voff);
                ldsm4t(vl, uVl + voff);
#pragma unroll
                for (int tt = 0; tt < 2; tt++) {
                    const int ni = vg * 2 + tt;
                    mma_bf16(o[ni], ph, vl[2*tt], vl[2*tt+1]);
                    mma_bf16(o[ni], pl, vh[2*tt], vh[2*tt+1]);
                    mma_bf16(o[ni], ph, vh[2*tt], vh[2*tt+1]);
                }
            }
        }
    }

    // ---- finalize ----
    float lf0 = l0, lf1 = l1;
    lf0 += __shfl_xor_sync(0xffffffffu, lf0, 1);
    lf0 += __shfl_xor_sync(0xffffffffu, lf0, 2);
    lf1 += __shfl_xor_sync(0xffffffffu, lf1, 1);
    lf1 += __shfl_xor_sync(0xffffffffu, lf1, 2);
    const float inv0 = 1.f / lf0;
    const float inv1 = 1.f / lf1;

    const int gr0 = rowbase + wrow0 + (lane >> 2);
    const int gr1 = gr0 + 8;
#pragma unroll
    for (int ni = 0; ni < 16; ni++) {
        const int col = h * HD + ni * 8 + (lane & 3) * 2;
        uint32_t hw, lw;
        split2(o[ni][0] * inv0, o[ni][1] * inv0, hw, lw);
        *(uint32_t*)(Oh + (size_t)gr0 * (NH * HD) + col) = hw;
        *(uint32_t*)(Ol + (size_t)gr0 * (NH * HD) + col) = lw;
        split2(o[ni][2] * inv1, o[ni][3] * inv1, hw, lw);
        *(uint32_t*)(Oh + (size_t)gr1 * (NH * HD) + col) = hw;
        *(uint32_t*)(Ol + (size_t)gr1 * (NH * HD) + col) = lw;
    }
}

// ======================= launch ===========================================
extern "C" void kernel_launch(void* const* d_in, const int* in_sizes, int n_in,
                              void* d_out, int out_size)
{
    const float* hidden = (const float*)d_in[0];
    const float* tvals  = (const float*)d_in[1];
    const float* wq     = (const float*)d_in[2];
    const float* bq     = (const float*)d_in[3];
    const float* wk     = (const float*)d_in[4];
    const float* bk     = (const float*)d_in[5];
    const float* wv     = (const float*)d_in[6];
    const float* bv     = (const float*)d_in[7];
    const float* wo     = (const float*)d_in[8];
    const float* rope_w = (const float*)d_in[9];
    float* out = (float*)d_out;

    float *q, *k;
    __nv_bfloat16 *hh, *hl, *qh, *ql, *kh, *kl, *vh, *vl, *oh, *ol;
    __nv_bfloat16 *wqh, *wql, *wkh, *wkl, *wvh, *wvl, *woh, *wol;
    cudaGetSymbolAddress((void**)&q,   g_q);
    cudaGetSymbolAddress((void**)&k,   g_k);
    cudaGetSymbolAddress((void**)&hh,  g_hh);
    cudaGetSymbolAddress((void**)&hl,  g_hl);
    cudaGetSymbolAddress((void**)&qh,  g_qh);
    cudaGetSymbolAddress((void**)&ql,  g_ql);
    cudaGetSymbolAddress((void**)&kh,  g_kh);
    cudaGetSymbolAddress((void**)&kl,  g_kl);
    cudaGetSymbolAddress((void**)&vh,  g_vh);
    cudaGetSymbolAddress((void**)&vl,  g_vl);
    cudaGetSymbolAddress((void**)&oh,  g_oh);
    cudaGetSymbolAddress((void**)&ol,  g_ol);
    cudaGetSymbolAddress((void**)&wqh, g_wqh);
    cudaGetSymbolAddress((void**)&wql, g_wql);
    cudaGetSymbolAddress((void**)&wkh, g_wkh);
    cudaGetSymbolAddress((void**)&wkl, g_wkl);
    cudaGetSymbolAddress((void**)&wvh, g_wvh);
    cudaGetSymbolAddress((void**)&wvl, g_wvl);
    cudaGetSymbolAddress((void**)&woh, g_woh);
    cudaGetSymbolAddress((void**)&wol, g_wol);

    // ---- prep: weight transpose+split, hidden split ----
    {
        dim3 blk(32, 8);
        wsplit_kernel<<<dim3(HID/32, HID/32),      blk>>>(wq, wqh, wql, HID, HID);
        wsplit_kernel<<<dim3(HID/32, (NKV*HD)/32), blk>>>(wk, wkh, wkl, HID, NKV*HD);
        wsplit_kernel<<<dim3(HID/32, (NKV*HD)/32), blk>>>(wv, wvh, wvl, HID, NKV*HD);
        wsplit_kernel<<<dim3(HID/32, HID/32),      blk>>>(wo, woh, wol, HID, HID);
        int tot = MROWS * HID;
        hsplit_kernel<<<(tot + 255) / 256, 256>>>(hidden, hh, hl, tot);
    }

    // ---- QKV projections ----
    const int gdyn = NSTG * GSTG_B;  // 122880
    cudaFuncSetAttribute(mma_gemm<false>, cudaFuncAttributeMaxDynamicSharedMemorySize, gdyn);
    cudaFuncSetAttribute(mma_gemm<true>,  cudaFuncAttributeMaxDynamicSharedMemorySize, gdyn);
    mma_gemm<false><<<dim3((NH*HD)/128,  MROWS/128), 256, gdyn>>>(
        hh, hl, wqh, wql, bq, q, nullptr, nullptr, NH*HD);
    mma_gemm<false><<<dim3((NKV*HD)/128, MROWS/128), 256, gdyn>>>(
        hh, hl, wkh, wkl, bk, k, nullptr, nullptr, NKV*HD);
    mma_gemm<true><<<dim3((NKV*HD)/128, MROWS/128), 256, gdyn>>>(
        hh, hl, wvh, wvl, bv, nullptr, vh, vl, NKV*HD);

    // ---- RoPE + split (Q, K) ----
    {
        int totq = MROWS * NH * 64;
        int totk = MROWS * NKV * 64;
        rope_split<<<(totq + 255) / 256, 256>>>(q, tvals, rope_w, qh, ql, NH,  totq);
        rope_split<<<(totk + 255) / 256, 256>>>(k, tvals, rope_w, kh, kl, NKV, totk);
    }

    // ---- Flash attention ----
    {
        const int fdyn = (2 * FQT_H + 2 * FKV_BUF) * 2;  // 208896 B
        cudaFuncSetAttribute(flash_mma, cudaFuncAttributeMaxDynamicSharedMemorySize, fdyn);
        flash_mma<<<dim3(S_LEN/128, BATCH*NH), 256, fdyn>>>(
            qh, ql, kh, kl, vh, vl, oh, ol);
    }

    // ---- Output projection ----
    mma_gemm<false><<<dim3(HID/128, MROWS/128), 256, gdyn>>>(
        oh, ol, woh, wol, nullptr, out, nullptr, nullptr, HID);
}

// round 8
// speedup vs baseline: 3.9187x; 1.7382x over previous
#include <cuda_runtime.h>
#include <cuda_fp16.h>
#include <cstdint>
#include <math.h>

#define S_LEN 2048
#define BATCH 2
#define HID   2048
#define NH    16
#define NKV   4
#define HD    128
#define MROWS (BATCH*S_LEN)   // 4096

// ---------------- scratch (static device globals; no runtime alloc) -------
__device__ float g_q[(size_t)MROWS * (NH*HD)];
__device__ float g_k[(size_t)MROWS * (NKV*HD)];
__device__ __half g_hh[(size_t)MROWS * HID];        // hidden hi (fp16)
__device__ __half g_hl[(size_t)MROWS * HID];        // hidden lo
__device__ __half g_qh[(size_t)MROWS * (NH*HD)];    // Q (single fp16, post-rope)
__device__ __half g_kh[(size_t)MROWS * (NKV*HD)];   // K (single)
__device__ __half g_vh[(size_t)MROWS * (NKV*HD)];   // V (single)
__device__ __half g_oh[(size_t)MROWS * (NH*HD)];    // attn out hi
__device__ __half g_ol[(size_t)MROWS * (NH*HD)];    // attn out lo
// single-fp16 transposed weights [N][K]
__device__ __half g_wqh[(size_t)HID * HID];
__device__ __half g_wkh[(size_t)(NKV*HD) * HID];
__device__ __half g_wvh[(size_t)(NKV*HD) * HID];
__device__ __half g_woh[(size_t)HID * HID];

// ======================= PTX helpers ======================================
__device__ __forceinline__ uint32_t smem_u32(const void* p) {
    uint32_t a;
    asm("{ .reg .u64 t; cvta.to.shared.u64 t, %1; cvt.u32.u64 %0, t; }"
        : "=r"(a) : "l"(p));
    return a;
}
__device__ __forceinline__ void ldsm4(uint32_t* r, uint32_t addr) {
    asm volatile("ldmatrix.sync.aligned.m8n8.x4.shared.b16 {%0,%1,%2,%3}, [%4];"
        : "=r"(r[0]), "=r"(r[1]), "=r"(r[2]), "=r"(r[3]) : "r"(addr));
}
__device__ __forceinline__ void ldsm4t(uint32_t* r, uint32_t addr) {
    asm volatile("ldmatrix.sync.aligned.m8n8.x4.trans.shared.b16 {%0,%1,%2,%3}, [%4];"
        : "=r"(r[0]), "=r"(r[1]), "=r"(r[2]), "=r"(r[3]) : "r"(addr));
}
__device__ __forceinline__ void mma_f16(float* c, const uint32_t* a,
                                        uint32_t b0, uint32_t b1) {
    asm volatile(
        "mma.sync.aligned.m16n8k16.row.col.f32.f16.f16.f32 "
        "{%0,%1,%2,%3}, {%4,%5,%6,%7}, {%8,%9}, {%0,%1,%2,%3};"
        : "+f"(c[0]), "+f"(c[1]), "+f"(c[2]), "+f"(c[3])
        : "r"(a[0]), "r"(a[1]), "r"(a[2]), "r"(a[3]), "r"(b0), "r"(b1));
}
__device__ __forceinline__ float ex2f(float x) {
    float y; asm("ex2.approx.f32 %0, %1;" : "=f"(y) : "f"(x)); return y;
}
__device__ __forceinline__ void cp16(uint32_t dst, const void* src) {
    asm volatile("cp.async.ca.shared.global [%0], [%1], 16;" :: "r"(dst), "l"(src));
}
#define CP_COMMIT() asm volatile("cp.async.commit_group;" ::: "memory")
#define CP_WAIT(N)  asm volatile("cp.async.wait_group %0;" :: "n"(N) : "memory")

__device__ __forceinline__ uint32_t packh2(float a, float b) {
    __half2 t = __floats2half2_rn(a, b);
    return *(uint32_t*)&t;
}
__device__ __forceinline__ void split2h(float x0, float x1, uint32_t& h, uint32_t& l) {
    __half h0 = __float2half_rn(x0);
    __half h1 = __float2half_rn(x1);
    __half2 hp = __halves2half2(h0, h1);
    h = *(uint32_t*)&hp;
    l = packh2(x0 - __half2float(h0), x1 - __half2float(h1));
}

// ======================= prep kernels =====================================
// transpose W[K][N] -> fp16 WT[N][K]
__global__ void wconv_kernel(const float* __restrict__ src,
                             __half* __restrict__ dh, int K, int N)
{
    __shared__ float tile[32][33];
    const int k0 = blockIdx.x * 32;
    const int n0 = blockIdx.y * 32;
    const int x = threadIdx.x;
#pragma unroll
    for (int y = threadIdx.y; y < 32; y += 8)
        tile[y][x] = src[(size_t)(k0 + y) * N + n0 + x];
    __syncthreads();
#pragma unroll
    for (int y = threadIdx.y; y < 32; y += 8)
        dh[(size_t)(n0 + y) * K + k0 + x] = __float2half_rn(tile[x][y]);
}

__global__ void hsplit_kernel(const float* __restrict__ X,
                              __half* __restrict__ Xh,
                              __half* __restrict__ Xl, int total)
{
    int idx = blockIdx.x * blockDim.x + threadIdx.x;
    if (idx >= total) return;
    float v = X[idx];
    __half h = __float2half_rn(v);
    Xh[idx] = h;
    Xl[idx] = __float2half_rn(v - __half2float(h));
}

// RoPE then single-fp16 output
__global__ void rope_half(const float* __restrict__ X, const float* __restrict__ tvals,
                          const float* __restrict__ rope_w,
                          __half* __restrict__ Xh, int nheads, int total)
{
    int idx = blockIdx.x * blockDim.x + threadIdx.x;
    if (idx >= total) return;
    const int i  = idx & 63;
    const int hh = (idx >> 6) % nheads;
    const int bs = idx / (64 * nheads);

    const float t = tvals[bs];
    const float inv_f = expf(-(float)(2 * i) * (9.210340371976184f / 128.0f));
    const float fr = t * inv_f * rope_w[i];
    const float cs = cosf(fr);
    const float sn = sinf(fr);

    const size_t base = (size_t)bs * ((size_t)nheads * HD) + hh * HD;
    const float x1 = X[base + i];
    const float x2 = X[base + i + 64];
    Xh[base + i]      = __float2half_rn(x1 * cs - x2 * sn);
    Xh[base + i + 64] = __float2half_rn(x2 * cs + x1 * sn);
}

// ======================= fp16 mma GEMM (A 2-term, W 1-term) ===============
// C = (Ah+Al) @ W^T + bias.  CTA 128x128, 8 warps (32m x 64n), k-chunk 32.
#define GK   HID
#define CHK  32
#define NCHK (GK / CHK)        // 64
#define GPAD 40                // halves per smem row
#define GT_H (128 * GPAD)      // halves per tile
#define GSTG_B (3 * GT_H * 2)  // Ah,Al,Bh per stage (30720 B)
#define NSTG 3

template<bool HALF_OUT>
__global__ __launch_bounds__(256) void mma_gemm(
    const __half* __restrict__ Agh, const __half* __restrict__ Agl,
    const __half* __restrict__ WTh,
    const float* __restrict__ bias, float* __restrict__ C,
    __half* __restrict__ Ch, int N)
{
    extern __shared__ __half sg[];
    const uint32_t sbase = smem_u32(sg);

    const int tid  = threadIdx.x;
    const int lane = tid & 31;
    const int wid  = tid >> 5;
    const int wm   = wid & 3;
    const int wn   = wid >> 2;
    const int bm   = blockIdx.y * 128;
    const int bn   = blockIdx.x * 128;

    float c[2][8][4];
#pragma unroll
    for (int mi = 0; mi < 2; mi++)
#pragma unroll
        for (int ni = 0; ni < 8; ni++)
#pragma unroll
            for (int j = 0; j < 4; j++) c[mi][ni][j] = 0.f;

    auto issue = [&](int kt, int stg) {
        const uint32_t sb = sbase + stg * GSTG_B;
#pragma unroll
        for (int j = 0; j < 2; j++) {
            const int cch = tid * 2 + j;
            const int row = cch >> 2;
            const int off = (cch & 3) * 8;
            const uint32_t d = sb + (row * GPAD + off) * 2;
            const size_t gA = (size_t)(bm + row) * GK + kt * CHK + off;
            const size_t gB = (size_t)(bn + row) * GK + kt * CHK + off;
            cp16(d,            Agh + gA);
            cp16(d + GT_H * 2, Agl + gA);
            cp16(d + GT_H * 4, WTh + gB);
        }
        CP_COMMIT();
    };

    issue(0, 0);
    issue(1, 1);

    for (int kt = 0; kt < NCHK; kt++) {
        CP_WAIT(1);
        __syncthreads();

        const uint32_t stage = sbase + (kt % NSTG) * GSTG_B;
        const uint32_t Ah = stage;
        const uint32_t Al = Ah + GT_H * 2;
        const uint32_t Bh = Al + GT_H * 2;

#pragma unroll
        for (int ks = 0; ks < 2; ks++) {
            const int k0 = ks * 16;
            uint32_t ah[8], al[8];
#pragma unroll
            for (int mi = 0; mi < 2; mi++) {
                const uint32_t aoff =
                    ((wm * 32 + mi * 16 + (lane & 7) + ((lane >> 3) & 1) * 8) * GPAD
                     + k0 + (lane >> 4) * 8) * 2;
                ldsm4(ah + 4 * mi, Ah + aoff);
                ldsm4(al + 4 * mi, Al + aoff);
            }
#pragma unroll
            for (int bg = 0; bg < 4; bg++) {
                const uint32_t boff =
                    ((wn * 64 + bg * 16 + (lane & 7) + (lane >> 4) * 8) * GPAD
                     + k0 + ((lane >> 3) & 1) * 8) * 2;
                uint32_t bh[4];
                ldsm4(bh, Bh + boff);
#pragma unroll
                for (int tt = 0; tt < 2; tt++) {
                    const int ni = bg * 2 + tt;
#pragma unroll
                    for (int mi = 0; mi < 2; mi++) {
                        mma_f16(c[mi][ni], al + 4 * mi, bh[2*tt], bh[2*tt+1]);
                        mma_f16(c[mi][ni], ah + 4 * mi, bh[2*tt], bh[2*tt+1]);
                    }
                }
            }
        }
        __syncthreads();
        if (kt + 2 < NCHK) issue(kt + 2, (kt + 2) % NSTG);
        else CP_COMMIT();
    }

    // ---- epilogue ----
#pragma unroll
    for (int mi = 0; mi < 2; mi++) {
        const int row0 = bm + wm * 32 + mi * 16 + (lane >> 2);
#pragma unroll
        for (int ni = 0; ni < 8; ni++) {
            const int col = bn + wn * 64 + ni * 8 + (lane & 3) * 2;
            float b0 = 0.f, b1 = 0.f;
            if (bias) { b0 = __ldg(bias + col); b1 = __ldg(bias + col + 1); }
            const float y00 = c[mi][ni][0] + b0, y01 = c[mi][ni][1] + b1;
            const float y10 = c[mi][ni][2] + b0, y11 = c[mi][ni][3] + b1;
            if (HALF_OUT) {
                *(uint32_t*)(Ch + (size_t)row0 * N + col)       = packh2(y00, y01);
                *(uint32_t*)(Ch + (size_t)(row0 + 8) * N + col) = packh2(y10, y11);
            } else {
                float2 r0, r1;
                r0.x = y00; r0.y = y01;
                r1.x = y10; r1.y = y11;
                *(float2*)(C + (size_t)row0 * N + col)       = r0;
                *(float2*)(C + (size_t)(row0 + 8) * N + col) = r1;
            }
        }
    }
}

// ======================= Flash attention (single fp16 mma) ================
// CTA: 128 q-rows, 8 warps (16 rows each). KV blocks of 64, single-buffered.
#define FPAD 136
#define FQT_H (128 * FPAD)
#define FKT_H (64 * FPAD)

__global__ __launch_bounds__(256) void flash_mma(
    const __half* __restrict__ Qg, const __half* __restrict__ Kg,
    const __half* __restrict__ Vg,
    __half* __restrict__ Oh, __half* __restrict__ Ol)
{
    extern __shared__ __half sf[];
    const uint32_t uQ = smem_u32(sf);
    const uint32_t uK = uQ + FQT_H * 2;
    const uint32_t uV = uK + FKT_H * 2;

    const int qb = gridDim.x - 1 - blockIdx.x;   // heavy CTAs first
    const int bh = blockIdx.y;
    const int b  = bh >> 4;
    const int h  = bh & 15;
    const int kvh = h >> 2;
    const int tid = threadIdx.x;
    const int lane = tid & 31;
    const int w = tid >> 5;
    const int q0 = qb * 128;
    const int rowbase = b * S_LEN;

    // Q tile: 128 rows x 128 halves
    {
#pragma unroll
        for (int j = 0; j < 8; j++) {
            const int cch = tid * 8 + j;
            const int row = cch >> 4;
            const int off = (cch & 15) * 8;
            const size_t g = (size_t)(rowbase + q0 + row) * (NH * HD) + h * HD + off;
            cp16(uQ + (row * FPAD + off) * 2, Qg + g);
        }
    }
    auto issueKV = [&](int nb) {
#pragma unroll
        for (int j = 0; j < 4; j++) {
            const int cch = tid * 4 + j;
            const int row = cch >> 4;
            const int off = (cch & 15) * 8;
            const size_t g = (size_t)(rowbase + nb * 64 + row) * (NKV * HD) + kvh * HD + off;
            const uint32_t d = (row * FPAD + off) * 2;
            cp16(uK + d, Kg + g);
            cp16(uV + d, Vg + g);
        }
        CP_COMMIT();
    };
    issueKV(0);

    float o[16][4];
#pragma unroll
    for (int ni = 0; ni < 16; ni++)
#pragma unroll
        for (int j = 0; j < 4; j++) o[ni][j] = 0.f;
    float m0 = -1.0e30f, m1 = -1.0e30f, l0 = 0.f, l1 = 0.f;

    const float SC2 = 0.12751744900459843f;  // (1/sqrt(128)) * log2(e)
    const int nblocks = 2 * qb + 2;
    const int wrow0 = q0 + w * 16;

    for (int nb = 0; nb < nblocks; nb++) {
        const int n0 = nb * 64;
        CP_WAIT(0);
        __syncthreads();

        if (n0 <= wrow0 + 15) {
            // ---- S = Q K^T ----
            float s[8][4];
#pragma unroll
            for (int ni = 0; ni < 8; ni++)
#pragma unroll
                for (int j = 0; j < 4; j++) s[ni][j] = 0.f;

#pragma unroll
            for (int ks = 0; ks < 8; ks++) {
                const int k0 = ks * 16;
                uint32_t a4[4];
                const uint32_t aoff =
                    ((w * 16 + (lane & 7) + ((lane >> 3) & 1) * 8) * FPAD
                     + k0 + (lane >> 4) * 8) * 2;
                ldsm4(a4, uQ + aoff);
#pragma unroll
                for (int bg = 0; bg < 4; bg++) {
                    const uint32_t boff =
                        ((bg * 16 + (lane & 7) + (lane >> 4) * 8) * FPAD
                         + k0 + ((lane >> 3) & 1) * 8) * 2;
                    uint32_t b4[4];
                    ldsm4(b4, uK + boff);
                    mma_f16(s[bg * 2],     a4, b4[0], b4[1]);
                    mma_f16(s[bg * 2 + 1], a4, b4[2], b4[3]);
                }
            }

            // ---- online softmax ----
            const int r0g = wrow0 + (lane >> 2);
            const int r1g = r0g + 8;
            const bool diag = (n0 + 63 > wrow0);
            float rmax0 = -1.0e30f, rmax1 = -1.0e30f;
#pragma unroll
            for (int ni = 0; ni < 8; ni++) {
                const int colb = n0 + ni * 8 + (lane & 3) * 2;
#pragma unroll
                for (int j = 0; j < 4; j++) {
                    float z = s[ni][j] * SC2;
                    if (diag) {
                        const int col = colb + (j & 1);
                        const int rw  = (j < 2) ? r0g : r1g;
                        if (col > rw) z = -1.0e30f;
                    }
                    s[ni][j] = z;
                }
                rmax0 = fmaxf(rmax0, fmaxf(s[ni][0], s[ni][1]));
                rmax1 = fmaxf(rmax1, fmaxf(s[ni][2], s[ni][3]));
            }
            rmax0 = fmaxf(rmax0, __shfl_xor_sync(0xffffffffu, rmax0, 1));
            rmax0 = fmaxf(rmax0, __shfl_xor_sync(0xffffffffu, rmax0, 2));
            rmax1 = fmaxf(rmax1, __shfl_xor_sync(0xffffffffu, rmax1, 1));
            rmax1 = fmaxf(rmax1, __shfl_xor_sync(0xffffffffu, rmax1, 2));

            const float mn0 = fmaxf(m0, rmax0);
            const float mn1 = fmaxf(m1, rmax1);
            const float al0 = ex2f(m0 - mn0);
            const float al1 = ex2f(m1 - mn1);
            m0 = mn0; m1 = mn1;

            float ls0 = 0.f, ls1 = 0.f;
#pragma unroll
            for (int ni = 0; ni < 8; ni++) {
                s[ni][0] = ex2f(s[ni][0] - mn0);
                s[ni][1] = ex2f(s[ni][1] - mn0);
                s[ni][2] = ex2f(s[ni][2] - mn1);
                s[ni][3] = ex2f(s[ni][3] - mn1);
                ls0 += s[ni][0] + s[ni][1];
                ls1 += s[ni][2] + s[ni][3];
            }
            l0 = l0 * al0 + ls0;
            l1 = l1 * al1 + ls1;
#pragma unroll
            for (int ni = 0; ni < 16; ni++) {
                o[ni][0] *= al0; o[ni][1] *= al0;
                o[ni][2] *= al1; o[ni][3] *= al1;
            }

            // ---- O += P V ----
#pragma unroll
            for (int kk = 0; kk < 4; kk++) {
                uint32_t ph[4];
                ph[0] = packh2(s[2*kk][0],   s[2*kk][1]);
                ph[1] = packh2(s[2*kk][2],   s[2*kk][3]);
                ph[2] = packh2(s[2*kk+1][0], s[2*kk+1][1]);
                ph[3] = packh2(s[2*kk+1][2], s[2*kk+1][3]);
#pragma unroll
                for (int vg = 0; vg < 8; vg++) {
                    const uint32_t voff =
                        ((kk * 16 + (lane & 7) + ((lane >> 3) & 1) * 8) * FPAD
                         + vg * 16 + (lane >> 4) * 8) * 2;
                    uint32_t v4[4];
                    ldsm4t(v4, uV + voff);
                    mma_f16(o[vg * 2],     ph, v4[0], v4[1]);
                    mma_f16(o[vg * 2 + 1], ph, v4[2], v4[3]);
                }
            }
        }

        __syncthreads();
        if (nb + 1 < nblocks) issueKV(nb + 1);
    }

    // ---- finalize ----
    float lf0 = l0, lf1 = l1;
    lf0 += __shfl_xor_sync(0xffffffffu, lf0, 1);
    lf0 += __shfl_xor_sync(0xffffffffu, lf0, 2);
    lf1 += __shfl_xor_sync(0xffffffffu, lf1, 1);
    lf1 += __shfl_xor_sync(0xffffffffu, lf1, 2);
    const float inv0 = 1.f / lf0;
    const float inv1 = 1.f / lf1;

    const int gr0 = rowbase + wrow0 + (lane >> 2);
    const int gr1 = gr0 + 8;
#pragma unroll
    for (int ni = 0; ni < 16; ni++) {
        const int col = h * HD + ni * 8 + (lane & 3) * 2;
        uint32_t hw, lw;
        split2h(o[ni][0] * inv0, o[ni][1] * inv0, hw, lw);
        *(uint32_t*)(Oh + (size_t)gr0 * (NH * HD) + col) = hw;
        *(uint32_t*)(Ol + (size_t)gr0 * (NH * HD) + col) = lw;
        split2h(o[ni][2] * inv1, o[ni][3] * inv1, hw, lw);
        *(uint32_t*)(Oh + (size_t)gr1 * (NH * HD) + col) = hw;
        *(uint32_t*)(Ol + (size_t)gr1 * (NH * HD) + col) = lw;
    }
}

// ======================= launch ===========================================
extern "C" void kernel_launch(void* const* d_in, const int* in_sizes, int n_in,
                              void* d_out, int out_size)
{
    const float* hidden = (const float*)d_in[0];
    const float* tvals  = (const float*)d_in[1];
    const float* wq     = (const float*)d_in[2];
    const float* bq     = (const float*)d_in[3];
    const float* wk     = (const float*)d_in[4];
    const float* bk     = (const float*)d_in[5];
    const float* wv     = (const float*)d_in[6];
    const float* bv     = (const float*)d_in[7];
    const float* wo     = (const float*)d_in[8];
    const float* rope_w = (const float*)d_in[9];
    float* out = (float*)d_out;

    float *q, *k;
    __half *hh, *hl, *qh, *kh, *vh, *oh, *ol, *wqh, *wkh, *wvh, *woh;
    cudaGetSymbolAddress((void**)&q,   g_q);
    cudaGetSymbolAddress((void**)&k,   g_k);
    cudaGetSymbolAddress((void**)&hh,  g_hh);
    cudaGetSymbolAddress((void**)&hl,  g_hl);
    cudaGetSymbolAddress((void**)&qh,  g_qh);
    cudaGetSymbolAddress((void**)&kh,  g_kh);
    cudaGetSymbolAddress((void**)&vh,  g_vh);
    cudaGetSymbolAddress((void**)&oh,  g_oh);
    cudaGetSymbolAddress((void**)&ol,  g_ol);
    cudaGetSymbolAddress((void**)&wqh, g_wqh);
    cudaGetSymbolAddress((void**)&wkh, g_wkh);
    cudaGetSymbolAddress((void**)&wvh, g_wvh);
    cudaGetSymbolAddress((void**)&woh, g_woh);

    // ---- prep ----
    {
        dim3 blk(32, 8);
        wconv_kernel<<<dim3(HID/32, HID/32),      blk>>>(wq, wqh, HID, HID);
        wconv_kernel<<<dim3(HID/32, (NKV*HD)/32), blk>>>(wk, wkh, HID, NKV*HD);
        wconv_kernel<<<dim3(HID/32, (NKV*HD)/32), blk>>>(wv, wvh, HID, NKV*HD);
        wconv_kernel<<<dim3(HID/32, HID/32),      blk>>>(wo, woh, HID, HID);
        int tot = MROWS * HID;
        hsplit_kernel<<<(tot + 255) / 256, 256>>>(hidden, hh, hl, tot);
    }

    // ---- QKV projections ----
    const int gdyn = NSTG * GSTG_B;  // 92160
    cudaFuncSetAttribute(mma_gemm<false>, cudaFuncAttributeMaxDynamicSharedMemorySize, gdyn);
    cudaFuncSetAttribute(mma_gemm<true>,  cudaFuncAttributeMaxDynamicSharedMemorySize, gdyn);
    mma_gemm<false><<<dim3((NH*HD)/128,  MROWS/128), 256, gdyn>>>(
        hh, hl, wqh, bq, q, nullptr, NH*HD);
    mma_gemm<false><<<dim3((NKV*HD)/128, MROWS/128), 256, gdyn>>>(
        hh, hl, wkh, bk, k, nullptr, NKV*HD);
    mma_gemm<true><<<dim3((NKV*HD)/128, MROWS/128), 256, gdyn>>>(
        hh, hl, wvh, bv, nullptr, vh, NKV*HD);

    // ---- RoPE (Q, K) -> fp16 ----
    {
        int totq = MROWS * NH * 64;
        int totk = MROWS * NKV * 64;
        rope_half<<<(totq + 255) / 256, 256>>>(q, tvals, rope_w, qh, NH,  totq);
        rope_half<<<(totk + 255) / 256, 256>>>(k, tvals, rope_w, kh, NKV, totk);
    }

    // ---- Flash attention ----
    {
        const int fdyn = (FQT_H + 2 * FKT_H) * 2;  // 69632 B
        cudaFuncSetAttribute(flash_mma, cudaFuncAttributeMaxDynamicSharedMemorySize, fdyn);
        flash_mma<<<dim3(S_LEN/128, BATCH*NH), 256, fdyn>>>(qh, kh, vh, oh, ol);
    }

    // ---- Output projection ----
    mma_gemm<false><<<dim3(HID/128, MROWS/128), 256, gdyn>>>(
        oh, ol, woh, nullptr, out, nullptr, HID);
}

// round 9
// speedup vs baseline: 4.6963x; 1.1985x over previous
#include <cuda_runtime.h>
#include <cuda_fp16.h>
#include <cstdint>
#include <math.h>

#define S_LEN 2048
#define BATCH 2
#define HID   2048
#define NH    16
#define NKV   4
#define HD    128
#define MROWS (BATCH*S_LEN)   // 4096

// ---------------- scratch (static device globals; no runtime alloc) -------
__device__ float g_q[(size_t)MROWS * (NH*HD)];
__device__ float g_k[(size_t)MROWS * (NKV*HD)];
__device__ __half g_hh[(size_t)MROWS * HID];        // hidden (single fp16)
__device__ __half g_qh[(size_t)MROWS * (NH*HD)];    // Q post-rope fp16
__device__ __half g_kh[(size_t)MROWS * (NKV*HD)];   // K post-rope fp16
__device__ __half g_vh[(size_t)MROWS * (NKV*HD)];   // V fp16
__device__ __half g_oh[(size_t)MROWS * (NH*HD)];    // attn out hi
__device__ __half g_ol[(size_t)MROWS * (NH*HD)];    // attn out lo
// fp16 transposed weights [N][K]
__device__ __half g_wqh[(size_t)HID * HID];
__device__ __half g_wkh[(size_t)(NKV*HD) * HID];
__device__ __half g_wvh[(size_t)(NKV*HD) * HID];
__device__ __half g_woh[(size_t)HID * HID];

// ======================= PTX helpers ======================================
__device__ __forceinline__ uint32_t smem_u32(const void* p) {
    uint32_t a;
    asm("{ .reg .u64 t; cvta.to.shared.u64 t, %1; cvt.u32.u64 %0, t; }"
        : "=r"(a) : "l"(p));
    return a;
}
__device__ __forceinline__ void ldsm4(uint32_t* r, uint32_t addr) {
    asm volatile("ldmatrix.sync.aligned.m8n8.x4.shared.b16 {%0,%1,%2,%3}, [%4];"
        : "=r"(r[0]), "=r"(r[1]), "=r"(r[2]), "=r"(r[3]) : "r"(addr));
}
__device__ __forceinline__ void ldsm4t(uint32_t* r, uint32_t addr) {
    asm volatile("ldmatrix.sync.aligned.m8n8.x4.trans.shared.b16 {%0,%1,%2,%3}, [%4];"
        : "=r"(r[0]), "=r"(r[1]), "=r"(r[2]), "=r"(r[3]) : "r"(addr));
}
__device__ __forceinline__ void mma_f16(float* c, const uint32_t* a,
                                        uint32_t b0, uint32_t b1) {
    asm volatile(
        "mma.sync.aligned.m16n8k16.row.col.f32.f16.f16.f32 "
        "{%0,%1,%2,%3}, {%4,%5,%6,%7}, {%8,%9}, {%0,%1,%2,%3};"
        : "+f"(c[0]), "+f"(c[1]), "+f"(c[2]), "+f"(c[3])
        : "r"(a[0]), "r"(a[1]), "r"(a[2]), "r"(a[3]), "r"(b0), "r"(b1));
}
__device__ __forceinline__ float ex2f(float x) {
    float y; asm("ex2.approx.f32 %0, %1;" : "=f"(y) : "f"(x)); return y;
}
__device__ __forceinline__ void cp16(uint32_t dst, const void* src) {
    asm volatile("cp.async.ca.shared.global [%0], [%1], 16;" :: "r"(dst), "l"(src));
}
#define CP_COMMIT() asm volatile("cp.async.commit_group;" ::: "memory")
#define CP_WAIT(N)  asm volatile("cp.async.wait_group %0;" :: "n"(N) : "memory")

__device__ __forceinline__ uint32_t packh2(float a, float b) {
    __half2 t = __floats2half2_rn(a, b);
    return *(uint32_t*)&t;
}
__device__ __forceinline__ void split2h(float x0, float x1, uint32_t& h, uint32_t& l) {
    __half h0 = __float2half_rn(x0);
    __half h1 = __float2half_rn(x1);
    __half2 hp = __halves2half2(h0, h1);
    h = *(uint32_t*)&hp;
    l = packh2(x0 - __half2float(h0), x1 - __half2float(h1));
}

// ======================= prep kernels =====================================
__global__ void wconv_kernel(const float* __restrict__ src,
                             __half* __restrict__ dh, int K, int N)
{
    __shared__ float tile[32][33];
    const int k0 = blockIdx.x * 32;
    const int n0 = blockIdx.y * 32;
    const int x = threadIdx.x;
#pragma unroll
    for (int y = threadIdx.y; y < 32; y += 8)
        tile[y][x] = src[(size_t)(k0 + y) * N + n0 + x];
    __syncthreads();
#pragma unroll
    for (int y = threadIdx.y; y < 32; y += 8)
        dh[(size_t)(n0 + y) * K + k0 + x] = __float2half_rn(tile[x][y]);
}

__global__ void hconv_kernel(const float* __restrict__ X,
                             __half* __restrict__ Xh, int total)
{
    int idx = blockIdx.x * blockDim.x + threadIdx.x;
    if (idx >= total) return;
    Xh[idx] = __float2half_rn(X[idx]);
}

__global__ void rope_half(const float* __restrict__ X, const float* __restrict__ tvals,
                          const float* __restrict__ rope_w,
                          __half* __restrict__ Xh, int nheads, int total)
{
    int idx = blockIdx.x * blockDim.x + threadIdx.x;
    if (idx >= total) return;
    const int i  = idx & 63;
    const int hh = (idx >> 6) % nheads;
    const int bs = idx / (64 * nheads);

    const float t = tvals[bs];
    const float inv_f = expf(-(float)(2 * i) * (9.210340371976184f / 128.0f));
    const float fr = t * inv_f * rope_w[i];
    const float cs = cosf(fr);
    const float sn = sinf(fr);

    const size_t base = (size_t)bs * ((size_t)nheads * HD) + hh * HD;
    const float x1 = X[base + i];
    const float x2 = X[base + i + 64];
    Xh[base + i]      = __float2half_rn(x1 * cs - x2 * sn);
    Xh[base + i + 64] = __float2half_rn(x2 * cs + x1 * sn);
}

// ======================= GEMM common ======================================
#define GK   HID
#define CHK  32
#define NCHK (GK / CHK)        // 64
#define GPAD 40                // halves per smem row
#define GT_H (128 * GPAD)      // halves per tile
#define NSTG 3

// ---------- merged QKV GEMM: 1-term fp16, CTA 128x128 ---------------------
#define QSTG_B (2 * GT_H * 2)  // A + B per stage (20480 B)

__global__ __launch_bounds__(256) void qkv_gemm(
    const __half* __restrict__ Ah16,
    const __half* __restrict__ wq16, const __half* __restrict__ wk16,
    const __half* __restrict__ wv16,
    const float* __restrict__ bq, const float* __restrict__ bk,
    const float* __restrict__ bv,
    float* __restrict__ Qo, float* __restrict__ Ko, __half* __restrict__ Vo)
{
    extern __shared__ __half sg[];
    const uint32_t sbase = smem_u32(sg);

    const int tid  = threadIdx.x;
    const int lane = tid & 31;
    const int wid  = tid >> 5;
    const int wm   = wid & 3;
    const int wn   = wid >> 2;
    const int bm   = blockIdx.y * 128;

    const int nx = blockIdx.x;
    const __half* WT; const float* bias;
    float* outF = nullptr; __half* outH = nullptr;
    int N, bn;
    if (nx < 16)      { WT = wq16; bias = bq; outF = Qo; N = NH*HD;  bn = nx * 128; }
    else if (nx < 20) { WT = wk16; bias = bk; outF = Ko; N = NKV*HD; bn = (nx-16) * 128; }
    else              { WT = wv16; bias = bv; outH = Vo; N = NKV*HD; bn = (nx-20) * 128; }

    float c[2][8][4];
#pragma unroll
    for (int mi = 0; mi < 2; mi++)
#pragma unroll
        for (int ni = 0; ni < 8; ni++)
#pragma unroll
            for (int j = 0; j < 4; j++) c[mi][ni][j] = 0.f;

    auto issue = [&](int kt, int stg) {
        const uint32_t sb = sbase + stg * QSTG_B;
#pragma unroll
        for (int j = 0; j < 2; j++) {
            const int cch = tid * 2 + j;
            const int row = cch >> 2;
            const int off = (cch & 3) * 8;
            const uint32_t d = sb + (row * GPAD + off) * 2;
            cp16(d,            Ah16 + (size_t)(bm + row) * GK + kt * CHK + off);
            cp16(d + GT_H * 2, WT   + (size_t)(bn + row) * GK + kt * CHK + off);
        }
        CP_COMMIT();
    };

    issue(0, 0);
    issue(1, 1);

    for (int kt = 0; kt < NCHK; kt++) {
        CP_WAIT(1);
        __syncthreads();

        const uint32_t stage = sbase + (kt % NSTG) * QSTG_B;
        const uint32_t Ahs = stage;
        const uint32_t Bhs = Ahs + GT_H * 2;

#pragma unroll
        for (int ks = 0; ks < 2; ks++) {
            const int k0 = ks * 16;
            uint32_t ah[8];
#pragma unroll
            for (int mi = 0; mi < 2; mi++) {
                const uint32_t aoff =
                    ((wm * 32 + mi * 16 + (lane & 7) + ((lane >> 3) & 1) * 8) * GPAD
                     + k0 + (lane >> 4) * 8) * 2;
                ldsm4(ah + 4 * mi, Ahs + aoff);
            }
#pragma unroll
            for (int bg = 0; bg < 4; bg++) {
                const uint32_t boff =
                    ((wn * 64 + bg * 16 + (lane & 7) + (lane >> 4) * 8) * GPAD
                     + k0 + ((lane >> 3) & 1) * 8) * 2;
                uint32_t bh[4];
                ldsm4(bh, Bhs + boff);
#pragma unroll
                for (int tt = 0; tt < 2; tt++) {
                    const int ni = bg * 2 + tt;
                    mma_f16(c[0][ni], ah,     bh[2*tt], bh[2*tt+1]);
                    mma_f16(c[1][ni], ah + 4, bh[2*tt], bh[2*tt+1]);
                }
            }
        }
        __syncthreads();
        if (kt + 2 < NCHK) issue(kt + 2, (kt + 2) % NSTG);
        else CP_COMMIT();
    }

#pragma unroll
    for (int mi = 0; mi < 2; mi++) {
        const int row0 = bm + wm * 32 + mi * 16 + (lane >> 2);
#pragma unroll
        for (int ni = 0; ni < 8; ni++) {
            const int col = bn + wn * 64 + ni * 8 + (lane & 3) * 2;
            const float b0 = __ldg(bias + col);
            const float b1 = __ldg(bias + col + 1);
            const float y00 = c[mi][ni][0] + b0, y01 = c[mi][ni][1] + b1;
            const float y10 = c[mi][ni][2] + b0, y11 = c[mi][ni][3] + b1;
            if (outH) {
                *(uint32_t*)(outH + (size_t)row0 * N + col)       = packh2(y00, y01);
                *(uint32_t*)(outH + (size_t)(row0 + 8) * N + col) = packh2(y10, y11);
            } else {
                float2 r0, r1;
                r0.x = y00; r0.y = y01;
                r1.x = y10; r1.y = y11;
                *(float2*)(outF + (size_t)row0 * N + col)       = r0;
                *(float2*)(outF + (size_t)(row0 + 8) * N + col) = r1;
            }
        }
    }
}

// ---------- WO GEMM: 2-term input (oh+ol) x 1-term W, fp32 out ------------
#define WSTG_B (3 * GT_H * 2)  // Ah, Al, B per stage (30720 B)

__global__ __launch_bounds__(256) void wo_gemm(
    const __half* __restrict__ Agh, const __half* __restrict__ Agl,
    const __half* __restrict__ WTh, float* __restrict__ C, int N)
{
    extern __shared__ __half sg[];
    const uint32_t sbase = smem_u32(sg);

    const int tid  = threadIdx.x;
    const int lane = tid & 31;
    const int wid  = tid >> 5;
    const int wm   = wid & 3;
    const int wn   = wid >> 2;
    const int bm   = blockIdx.y * 128;
    const int bn   = blockIdx.x * 128;

    float c[2][8][4];
#pragma unroll
    for (int mi = 0; mi < 2; mi++)
#pragma unroll
        for (int ni = 0; ni < 8; ni++)
#pragma unroll
            for (int j = 0; j < 4; j++) c[mi][ni][j] = 0.f;

    auto issue = [&](int kt, int stg) {
        const uint32_t sb = sbase + stg * WSTG_B;
#pragma unroll
        for (int j = 0; j < 2; j++) {
            const int cch = tid * 2 + j;
            const int row = cch >> 2;
            const int off = (cch & 3) * 8;
            const uint32_t d = sb + (row * GPAD + off) * 2;
            const size_t gA = (size_t)(bm + row) * GK + kt * CHK + off;
            cp16(d,            Agh + gA);
            cp16(d + GT_H * 2, Agl + gA);
            cp16(d + GT_H * 4, WTh + (size_t)(bn + row) * GK + kt * CHK + off);
        }
        CP_COMMIT();
    };

    issue(0, 0);
    issue(1, 1);

    for (int kt = 0; kt < NCHK; kt++) {
        CP_WAIT(1);
        __syncthreads();

        const uint32_t stage = sbase + (kt % NSTG) * WSTG_B;
        const uint32_t Ahs = stage;
        const uint32_t Als = Ahs + GT_H * 2;
        const uint32_t Bhs = Als + GT_H * 2;

#pragma unroll
        for (int ks = 0; ks < 2; ks++) {
            const int k0 = ks * 16;
            uint32_t ah[8], al[8];
#pragma unroll
            for (int mi = 0; mi < 2; mi++) {
                const uint32_t aoff =
                    ((wm * 32 + mi * 16 + (lane & 7) + ((lane >> 3) & 1) * 8) * GPAD
                     + k0 + (lane >> 4) * 8) * 2;
                ldsm4(ah + 4 * mi, Ahs + aoff);
                ldsm4(al + 4 * mi, Als + aoff);
            }
#pragma unroll
            for (int bg = 0; bg < 4; bg++) {
                const uint32_t boff =
                    ((wn * 64 + bg * 16 + (lane & 7) + (lane >> 4) * 8) * GPAD
                     + k0 + ((lane >> 3) & 1) * 8) * 2;
                uint32_t bh[4];
                ldsm4(bh, Bhs + boff);
#pragma unroll
                for (int tt = 0; tt < 2; tt++) {
                    const int ni = bg * 2 + tt;
#pragma unroll
                    for (int mi = 0; mi < 2; mi++) {
                        mma_f16(c[mi][ni], al + 4 * mi, bh[2*tt], bh[2*tt+1]);
                        mma_f16(c[mi][ni], ah + 4 * mi, bh[2*tt], bh[2*tt+1]);
                    }
                }
            }
        }
        __syncthreads();
        if (kt + 2 < NCHK) issue(kt + 2, (kt + 2) % NSTG);
        else CP_COMMIT();
    }

#pragma unroll
    for (int mi = 0; mi < 2; mi++) {
        const int row0 = bm + wm * 32 + mi * 16 + (lane >> 2);
#pragma unroll
        for (int ni = 0; ni < 8; ni++) {
            const int col = bn + wn * 64 + ni * 8 + (lane & 3) * 2;
            float2 r0, r1;
            r0.x = c[mi][ni][0]; r0.y = c[mi][ni][1];
            r1.x = c[mi][ni][2]; r1.y = c[mi][ni][3];
            *(float2*)(C + (size_t)row0 * N + col)       = r0;
            *(float2*)(C + (size_t)(row0 + 8) * N + col) = r1;
        }
    }
}

// ======================= Flash attention (single fp16 mma) ================
#define FPAD 136
#define FQT_H (128 * FPAD)
#define FKT_H (64 * FPAD)

__global__ __launch_bounds__(256) void flash_mma(
    const __half* __restrict__ Qg, const __half* __restrict__ Kg,
    const __half* __restrict__ Vg,
    __half* __restrict__ Oh, __half* __restrict__ Ol)
{
    extern __shared__ __half sf[];
    const uint32_t uQ = smem_u32(sf);
    const uint32_t uK = uQ + FQT_H * 2;
    const uint32_t uV = uK + FKT_H * 2;

    const int qb = gridDim.x - 1 - blockIdx.x;   // heavy CTAs first
    const int bh = blockIdx.y;
    const int b  = bh >> 4;
    const int h  = bh & 15;
    const int kvh = h >> 2;
    const int tid = threadIdx.x;
    const int lane = tid & 31;
    const int w = tid >> 5;
    const int q0 = qb * 128;
    const int rowbase = b * S_LEN;

    {
#pragma unroll
        for (int j = 0; j < 8; j++) {
            const int cch = tid * 8 + j;
            const int row = cch >> 4;
            const int off = (cch & 15) * 8;
            const size_t g = (size_t)(rowbase + q0 + row) * (NH * HD) + h * HD + off;
            cp16(uQ + (row * FPAD + off) * 2, Qg + g);
        }
    }
    auto issueKV = [&](int nb) {
#pragma unroll
        for (int j = 0; j < 4; j++) {
            const int cch = tid * 4 + j;
            const int row = cch >> 4;
            const int off = (cch & 15) * 8;
            const size_t g = (size_t)(rowbase + nb * 64 + row) * (NKV * HD) + kvh * HD + off;
            const uint32_t d = (row * FPAD + off) * 2;
            cp16(uK + d, Kg + g);
            cp16(uV + d, Vg + g);
        }
        CP_COMMIT();
    };
    issueKV(0);

    float o[16][4];
#pragma unroll
    for (int ni = 0; ni < 16; ni++)
#pragma unroll
        for (int j = 0; j < 4; j++) o[ni][j] = 0.f;
    float m0 = -1.0e30f, m1 = -1.0e30f, l0 = 0.f, l1 = 0.f;

    const float SC2 = 0.12751744900459843f;  // (1/sqrt(128)) * log2(e)
    const int nblocks = 2 * qb + 2;
    const int wrow0 = q0 + w * 16;

    for (int nb = 0; nb < nblocks; nb++) {
        const int n0 = nb * 64;
        CP_WAIT(0);
        __syncthreads();

        if (n0 <= wrow0 + 15) {
            float s[8][4];
#pragma unroll
            for (int ni = 0; ni < 8; ni++)
#pragma unroll
                for (int j = 0; j < 4; j++) s[ni][j] = 0.f;

#pragma unroll
            for (int ks = 0; ks < 8; ks++) {
                const int k0 = ks * 16;
                uint32_t a4[4];
                const uint32_t aoff =
                    ((w * 16 + (lane & 7) + ((lane >> 3) & 1) * 8) * FPAD
                     + k0 + (lane >> 4) * 8) * 2;
                ldsm4(a4, uQ + aoff);
#pragma unroll
                for (int bg = 0; bg < 4; bg++) {
                    const uint32_t boff =
                        ((bg * 16 + (lane & 7) + (lane >> 4) * 8) * FPAD
                         + k0 + ((lane >> 3) & 1) * 8) * 2;
                    uint32_t b4[4];
                    ldsm4(b4, uK + boff);
                    mma_f16(s[bg * 2],     a4, b4[0], b4[1]);
                    mma_f16(s[bg * 2 + 1], a4, b4[2], b4[3]);
                }
            }

            const int r0g = wrow0 + (lane >> 2);
            const int r1g = r0g + 8;
            const bool diag = (n0 + 63 > wrow0);
            float rmax0 = -1.0e30f, rmax1 = -1.0e30f;
#pragma unroll
            for (int ni = 0; ni < 8; ni++) {
                const int colb = n0 + ni * 8 + (lane & 3) * 2;
#pragma unroll
                for (int j = 0; j < 4; j++) {
                    float z = s[ni][j] * SC2;
                    if (diag) {
                        const int col = colb + (j & 1);
                        const int rw  = (j < 2) ? r0g : r1g;
                        if (col > rw) z = -1.0e30f;
                    }
                    s[ni][j] = z;
                }
                rmax0 = fmaxf(rmax0, fmaxf(s[ni][0], s[ni][1]));
                rmax1 = fmaxf(rmax1, fmaxf(s[ni][2], s[ni][3]));
            }
            rmax0 = fmaxf(rmax0, __shfl_xor_sync(0xffffffffu, rmax0, 1));
            rmax0 = fmaxf(rmax0, __shfl_xor_sync(0xffffffffu, rmax0, 2));
            rmax1 = fmaxf(rmax1, __shfl_xor_sync(0xffffffffu, rmax1, 1));
            rmax1 = fmaxf(rmax1, __shfl_xor_sync(0xffffffffu, rmax1, 2));

            const float mn0 = fmaxf(m0, rmax0);
            const float mn1 = fmaxf(m1, rmax1);
            const float al0 = ex2f(m0 - mn0);
            const float al1 = ex2f(m1 - mn1);
            m0 = mn0; m1 = mn1;

            float ls0 = 0.f, ls1 = 0.f;
#pragma unroll
            for (int ni = 0; ni < 8; ni++) {
                s[ni][0] = ex2f(s[ni][0] - mn0);
                s[ni][1] = ex2f(s[ni][1] - mn0);
                s[ni][2] = ex2f(s[ni][2] - mn1);
                s[ni][3] = ex2f(s[ni][3] - mn1);
                ls0 += s[ni][0] + s[ni][1];
                ls1 += s[ni][2] + s[ni][3];
            }
            l0 = l0 * al0 + ls0;
            l1 = l1 * al1 + ls1;
#pragma unroll
            for (int ni = 0; ni < 16; ni++) {
                o[ni][0] *= al0; o[ni][1] *= al0;
                o[ni][2] *= al1; o[ni][3] *= al1;
            }

#pragma unroll
            for (int kk = 0; kk < 4; kk++) {
                uint32_t ph[4];
                ph[0] = packh2(s[2*kk][0],   s[2*kk][1]);
                ph[1] = packh2(s[2*kk][2],   s[2*kk][3]);
                ph[2] = packh2(s[2*kk+1][0], s[2*kk+1][1]);
                ph[3] = packh2(s[2*kk+1][2], s[2*kk+1][3]);
#pragma unroll
                for (int vg = 0; vg < 8; vg++) {
                    const uint32_t voff =
                        ((kk * 16 + (lane & 7) + ((lane >> 3) & 1) * 8) * FPAD
                         + vg * 16 + (lane >> 4) * 8) * 2;
                    uint32_t v4[4];
                    ldsm4t(v4, uV + voff);
                    mma_f16(o[vg * 2],     ph, v4[0], v4[1]);
                    mma_f16(o[vg * 2 + 1], ph, v4[2], v4[3]);
                }
            }
        }

        __syncthreads();
        if (nb + 1 < nblocks) issueKV(nb + 1);
    }

    float lf0 = l0, lf1 = l1;
    lf0 += __shfl_xor_sync(0xffffffffu, lf0, 1);
    lf0 += __shfl_xor_sync(0xffffffffu, lf0, 2);
    lf1 += __shfl_xor_sync(0xffffffffu, lf1, 1);
    lf1 += __shfl_xor_sync(0xffffffffu, lf1, 2);
    const float inv0 = 1.f / lf0;
    const float inv1 = 1.f / lf1;

    const int gr0 = rowbase + wrow0 + (lane >> 2);
    const int gr1 = gr0 + 8;
#pragma unroll
    for (int ni = 0; ni < 16; ni++) {
        const int col = h * HD + ni * 8 + (lane & 3) * 2;
        uint32_t hw, lw;
        split2h(o[ni][0] * inv0, o[ni][1] * inv0, hw, lw);
        *(uint32_t*)(Oh + (size_t)gr0 * (NH * HD) + col) = hw;
        *(uint32_t*)(Ol + (size_t)gr0 * (NH * HD) + col) = lw;
        split2h(o[ni][2] * inv1, o[ni][3] * inv1, hw, lw);
        *(uint32_t*)(Oh + (size_t)gr1 * (NH * HD) + col) = hw;
        *(uint32_t*)(Ol + (size_t)gr1 * (NH * HD) + col) = lw;
    }
}

// ======================= launch ===========================================
extern "C" void kernel_launch(void* const* d_in, const int* in_sizes, int n_in,
                              void* d_out, int out_size)
{
    const float* hidden = (const float*)d_in[0];
    const float* tvals  = (const float*)d_in[1];
    const float* wq     = (const float*)d_in[2];
    const float* bq     = (const float*)d_in[3];
    const float* wk     = (const float*)d_in[4];
    const float* bk     = (const float*)d_in[5];
    const float* wv     = (const float*)d_in[6];
    const float* bv     = (const float*)d_in[7];
    const float* wo     = (const float*)d_in[8];
    const float* rope_w = (const float*)d_in[9];
    float* out = (float*)d_out;

    float *q, *k;
    __half *hh, *qh, *kh, *vh, *oh, *ol, *wqh, *wkh, *wvh, *woh;
    cudaGetSymbolAddress((void**)&q,   g_q);
    cudaGetSymbolAddress((void**)&k,   g_k);
    cudaGetSymbolAddress((void**)&hh,  g_hh);
    cudaGetSymbolAddress((void**)&qh,  g_qh);
    cudaGetSymbolAddress((void**)&kh,  g_kh);
    cudaGetSymbolAddress((void**)&vh,  g_vh);
    cudaGetSymbolAddress((void**)&oh,  g_oh);
    cudaGetSymbolAddress((void**)&ol,  g_ol);
    cudaGetSymbolAddress((void**)&wqh, g_wqh);
    cudaGetSymbolAddress((void**)&wkh, g_wkh);
    cudaGetSymbolAddress((void**)&wvh, g_wvh);
    cudaGetSymbolAddress((void**)&woh, g_woh);

    // ---- prep ----
    {
        dim3 blk(32, 8);
        wconv_kernel<<<dim3(HID/32, HID/32),      blk>>>(wq, wqh, HID, HID);
        wconv_kernel<<<dim3(HID/32, (NKV*HD)/32), blk>>>(wk, wkh, HID, NKV*HD);
        wconv_kernel<<<dim3(HID/32, (NKV*HD)/32), blk>>>(wv, wvh, HID, NKV*HD);
        wconv_kernel<<<dim3(HID/32, HID/32),      blk>>>(wo, woh, HID, HID);
        int tot = MROWS * HID;
        hconv_kernel<<<(tot + 255) / 256, 256>>>(hidden, hh, tot);
    }

    // ---- merged QKV projection (1-term fp16) ----
    {
        const int qdyn = NSTG * QSTG_B;  // 61440
        cudaFuncSetAttribute(qkv_gemm, cudaFuncAttributeMaxDynamicSharedMemorySize, qdyn);
        qkv_gemm<<<dim3(24, MROWS/128), 256, qdyn>>>(
            hh, wqh, wkh, wvh, bq, bk, bv, q, k, vh);
    }

    // ---- RoPE (Q, K) -> fp16 ----
    {
        int totq = MROWS * NH * 64;
        int totk = MROWS * NKV * 64;
        rope_half<<<(totq + 255) / 256, 256>>>(q, tvals, rope_w, qh, NH,  totq);
        rope_half<<<(totk + 255) / 256, 256>>>(k, tvals, rope_w, kh, NKV, totk);
    }

    // ---- Flash attention ----
    {
        const int fdyn = (FQT_H + 2 * FKT_H) * 2;  // 69632 B
        cudaFuncSetAttribute(flash_mma, cudaFuncAttributeMaxDynamicSharedMemorySize, fdyn);
        flash_mma<<<dim3(S_LEN/128, BATCH*NH), 256, fdyn>>>(qh, kh, vh, oh, ol);
    }

    // ---- Output projection (2-term input) ----
    {
        const int wdyn = NSTG * WSTG_B;  // 92160
        cudaFuncSetAttribute(wo_gemm, cudaFuncAttributeMaxDynamicSharedMemorySize, wdyn);
        wo_gemm<<<dim3(HID/128, MROWS/128), 256, wdyn>>>(oh, ol, woh, out, HID);
    }
}

// round 12
// speedup vs baseline: 5.6726x; 1.2079x over previous
#include <cuda_runtime.h>
#include <cuda_fp16.h>
#include <cstdint>
#include <math.h>

#define S_LEN 2048
#define BATCH 2
#define HID   2048
#define NH    16
#define NKV   4
#define HD    128
#define MROWS (BATCH*S_LEN)   // 4096

// ---------------- scratch (static device globals; no runtime alloc) -------
__device__ float g_q[(size_t)MROWS * (NH*HD)];
__device__ float g_k[(size_t)MROWS * (NKV*HD)];
__device__ __half g_hh[(size_t)MROWS * HID];        // hidden fp16
__device__ __half g_qh[(size_t)MROWS * (NH*HD)];    // Q post-rope fp16
__device__ __half g_kh[(size_t)MROWS * (NKV*HD)];   // K post-rope fp16
__device__ __half g_vh[(size_t)MROWS * (NKV*HD)];   // V fp16
__device__ __half g_oh[(size_t)MROWS * (NH*HD)];    // attn out fp16
// fp16 transposed weights [N][K]
__device__ __half g_wqh[(size_t)HID * HID];
__device__ __half g_wkh[(size_t)(NKV*HD) * HID];
__device__ __half g_wvh[(size_t)(NKV*HD) * HID];
__device__ __half g_woh[(size_t)HID * HID];

// ======================= PTX helpers ======================================
__device__ __forceinline__ uint32_t smem_u32(const void* p) {
    uint32_t a;
    asm("{ .reg .u64 t; cvta.to.shared.u64 t, %1; cvt.u32.u64 %0, t; }"
        : "=r"(a) : "l"(p));
    return a;
}
__device__ __forceinline__ void ldsm4(uint32_t* r, uint32_t addr) {
    asm volatile("ldmatrix.sync.aligned.m8n8.x4.shared.b16 {%0,%1,%2,%3}, [%4];"
        : "=r"(r[0]), "=r"(r[1]), "=r"(r[2]), "=r"(r[3]) : "r"(addr));
}
__device__ __forceinline__ void ldsm4t(uint32_t* r, uint32_t addr) {
    asm volatile("ldmatrix.sync.aligned.m8n8.x4.trans.shared.b16 {%0,%1,%2,%3}, [%4];"
        : "=r"(r[0]), "=r"(r[1]), "=r"(r[2]), "=r"(r[3]) : "r"(addr));
}
__device__ __forceinline__ void mma_f16(float* c, const uint32_t* a,
                                        uint32_t b0, uint32_t b1) {
    asm volatile(
        "mma.sync.aligned.m16n8k16.row.col.f32.f16.f16.f32 "
        "{%0,%1,%2,%3}, {%4,%5,%6,%7}, {%8,%9}, {%0,%1,%2,%3};"
        : "+f"(c[0]), "+f"(c[1]), "+f"(c[2]), "+f"(c[3])
        : "r"(a[0]), "r"(a[1]), "r"(a[2]), "r"(a[3]), "r"(b0), "r"(b1));
}
__device__ __forceinline__ float ex2f(float x) {
    float y; asm("ex2.approx.f32 %0, %1;" : "=f"(y) : "f"(x)); return y;
}
__device__ __forceinline__ void cp16(uint32_t dst, const void* src) {
    asm volatile("cp.async.ca.shared.global [%0], [%1], 16;" :: "r"(dst), "l"(src));
}
#define CP_COMMIT() asm volatile("cp.async.commit_group;" ::: "memory")
#define CP_WAIT(N)  asm volatile("cp.async.wait_group %0;" :: "n"(N) : "memory")

__device__ __forceinline__ uint32_t packh2(float a, float b) {
    __half2 t = __floats2half2_rn(a, b);
    return *(uint32_t*)&t;
}

// ======================= prep kernels =====================================
// fused transpose+fp16 convert for all four weights (one grid)
#define WQ_BLKS ((HID/32) * (HID/32))          // 4096
#define WK_BLKS ((HID/32) * ((NKV*HD)/32))     // 1024
#define WV_BLKS WK_BLKS                        // 1024
#define WO_BLKS WQ_BLKS                        // 4096
#define WALL_BLKS (WQ_BLKS + WK_BLKS + WV_BLKS + WO_BLKS)  // 10240

__global__ void wconv_all(const float* __restrict__ wq, const float* __restrict__ wk,
                          const float* __restrict__ wv, const float* __restrict__ wo,
                          __half* __restrict__ dq, __half* __restrict__ dk,
                          __half* __restrict__ dv, __half* __restrict__ dwo)
{
    __shared__ float tile[32][33];
    const int bid = blockIdx.x;
    const float* src; __half* dst; int N, lb;
    if (bid < WQ_BLKS) {
        src = wq; dst = dq;  N = HID;    lb = bid;
    } else if (bid < WQ_BLKS + WK_BLKS) {
        src = wk; dst = dk;  N = NKV*HD; lb = bid - WQ_BLKS;
    } else if (bid < WQ_BLKS + WK_BLKS + WV_BLKS) {
        src = wv; dst = dv;  N = NKV*HD; lb = bid - WQ_BLKS - WK_BLKS;
    } else {
        src = wo; dst = dwo; N = HID;    lb = bid - WQ_BLKS - WK_BLKS - WV_BLKS;
    }
    const int kb = HID / 32;             // 64 k-blocks in all weights
    const int k0 = (lb % kb) * 32;
    const int n0 = (lb / kb) * 32;
    const int x = threadIdx.x;
#pragma unroll
    for (int y = threadIdx.y; y < 32; y += 8)
        tile[y][x] = src[(size_t)(k0 + y) * N + n0 + x];
    __syncthreads();
#pragma unroll
    for (int y = threadIdx.y; y < 32; y += 8)
        dst[(size_t)(n0 + y) * HID + k0 + x] = __float2half_rn(tile[x][y]);
}

__global__ void hconv_kernel(const float* __restrict__ X,
                             __half* __restrict__ Xh, int total)
{
    int idx = blockIdx.x * blockDim.x + threadIdx.x;
    if (idx >= total) return;
    Xh[idx] = __float2half_rn(X[idx]);
}

// fused RoPE for Q and K -> fp16
__global__ void rope_both(const float* __restrict__ Qf, const float* __restrict__ Kf,
                          const float* __restrict__ tvals, const float* __restrict__ rope_w,
                          __half* __restrict__ Qh, __half* __restrict__ Kh,
                          int totq, int total)
{
    int idx = blockIdx.x * blockDim.x + threadIdx.x;
    if (idx >= total) return;
    const float* X; __half* Xh; int nheads, li;
    if (idx < totq) { X = Qf; Xh = Qh; nheads = NH;  li = idx; }
    else            { X = Kf; Xh = Kh; nheads = NKV; li = idx - totq; }

    const int i  = li & 63;
    const int hh = (li >> 6) % nheads;
    const int bs = li / (64 * nheads);

    const float t = tvals[bs];
    const float inv_f = expf(-(float)(2 * i) * (9.210340371976184f / 128.0f));
    const float fr = t * inv_f * rope_w[i];
    const float cs = cosf(fr);
    const float sn = sinf(fr);

    const size_t base = (size_t)bs * ((size_t)nheads * HD) + hh * HD;
    const float x1 = X[base + i];
    const float x2 = X[base + i + 64];
    Xh[base + i]      = __float2half_rn(x1 * cs - x2 * sn);
    Xh[base + i + 64] = __float2half_rn(x2 * cs + x1 * sn);
}

// ======================= GEMM common ======================================
#define GK   HID
#define CHK  32
#define NCHK (GK / CHK)        // 64
#define GPAD 40
#define GT_H (128 * GPAD)
#define NSTG 3
#define QSTG_B (2 * GT_H * 2)  // A + B per stage (20480 B)

// ---------- merged QKV GEMM: 1-term fp16, CTA 128x128 ---------------------
__global__ __launch_bounds__(256) void qkv_gemm(
    const __half* __restrict__ Ah16,
    const __half* __restrict__ wq16, const __half* __restrict__ wk16,
    const __half* __restrict__ wv16,
    const float* __restrict__ bq, const float* __restrict__ bk,
    const float* __restrict__ bv,
    float* __restrict__ Qo, float* __restrict__ Ko, __half* __restrict__ Vo)
{
    extern __shared__ __half sg[];
    const uint32_t sbase = smem_u32(sg);

    const int tid  = threadIdx.x;
    const int lane = tid & 31;
    const int wid  = tid >> 5;
    const int wm   = wid & 3;
    const int wn   = wid >> 2;
    const int bm   = blockIdx.y * 128;

    const int nx = blockIdx.x;
    const __half* WT; const float* bias;
    float* outF = nullptr; __half* outH = nullptr;
    int N, bn;
    if (nx < 16)      { WT = wq16; bias = bq; outF = Qo; N = NH*HD;  bn = nx * 128; }
    else if (nx < 20) { WT = wk16; bias = bk; outF = Ko; N = NKV*HD; bn = (nx-16) * 128; }
    else              { WT = wv16; bias = bv; outH = Vo; N = NKV*HD; bn = (nx-20) * 128; }

    float c[2][8][4];
#pragma unroll
    for (int mi = 0; mi < 2; mi++)
#pragma unroll
        for (int ni = 0; ni < 8; ni++)
#pragma unroll
            for (int j = 0; j < 4; j++) c[mi][ni][j] = 0.f;

    auto issue = [&](int kt, int stg) {
        const uint32_t sb = sbase + stg * QSTG_B;
#pragma unroll
        for (int j = 0; j < 2; j++) {
            const int cch = tid * 2 + j;
            const int row = cch >> 2;
            const int off = (cch & 3) * 8;
            const uint32_t d = sb + (row * GPAD + off) * 2;
            cp16(d,            Ah16 + (size_t)(bm + row) * GK + kt * CHK + off);
            cp16(d + GT_H * 2, WT   + (size_t)(bn + row) * GK + kt * CHK + off);
        }
        CP_COMMIT();
    };

    issue(0, 0);
    issue(1, 1);

    for (int kt = 0; kt < NCHK; kt++) {
        CP_WAIT(1);
        __syncthreads();

        const uint32_t stage = sbase + (kt % NSTG) * QSTG_B;
        const uint32_t Ahs = stage;
        const uint32_t Bhs = Ahs + GT_H * 2;

#pragma unroll
        for (int ks = 0; ks < 2; ks++) {
            const int k0 = ks * 16;
            uint32_t ah[8];
#pragma unroll
            for (int mi = 0; mi < 2; mi++) {
                const uint32_t aoff =
                    ((wm * 32 + mi * 16 + (lane & 7) + ((lane >> 3) & 1) * 8) * GPAD
                     + k0 + (lane >> 4) * 8) * 2;
                ldsm4(ah + 4 * mi, Ahs + aoff);
            }
#pragma unroll
            for (int bg = 0; bg < 4; bg++) {
                const uint32_t boff =
                    ((wn * 64 + bg * 16 + (lane & 7) + (lane >> 4) * 8) * GPAD
                     + k0 + ((lane >> 3) & 1) * 8) * 2;
                uint32_t bh[4];
                ldsm4(bh, Bhs + boff);
#pragma unroll
                for (int tt = 0; tt < 2; tt++) {
                    const int ni = bg * 2 + tt;
                    mma_f16(c[0][ni], ah,     bh[2*tt], bh[2*tt+1]);
                    mma_f16(c[1][ni], ah + 4, bh[2*tt], bh[2*tt+1]);
                }
            }
        }
        __syncthreads();
        if (kt + 2 < NCHK) issue(kt + 2, (kt + 2) % NSTG);
        else CP_COMMIT();
    }

#pragma unroll
    for (int mi = 0; mi < 2; mi++) {
        const int row0 = bm + wm * 32 + mi * 16 + (lane >> 2);
#pragma unroll
        for (int ni = 0; ni < 8; ni++) {
            const int col = bn + wn * 64 + ni * 8 + (lane & 3) * 2;
            const float b0 = __ldg(bias + col);
            const float b1 = __ldg(bias + col + 1);
            const float y00 = c[mi][ni][0] + b0, y01 = c[mi][ni][1] + b1;
            const float y10 = c[mi][ni][2] + b0, y11 = c[mi][ni][3] + b1;
            if (outH) {
                *(uint32_t*)(outH + (size_t)row0 * N + col)       = packh2(y00, y01);
                *(uint32_t*)(outH + (size_t)(row0 + 8) * N + col) = packh2(y10, y11);
            } else {
                float2 r0, r1;
                r0.x = y00; r0.y = y01;
                r1.x = y10; r1.y = y11;
                *(float2*)(outF + (size_t)row0 * N + col)       = r0;
                *(float2*)(outF + (size_t)(row0 + 8) * N + col) = r1;
            }
        }
    }
}

// ---------- WO GEMM: 1-term fp16 in, fp32 out -----------------------------
__global__ __launch_bounds__(256) void wo_gemm(
    const __half* __restrict__ Agh, const __half* __restrict__ WTh,
    float* __restrict__ C, int N)
{
    extern __shared__ __half sg[];
    const uint32_t sbase = smem_u32(sg);

    const int tid  = threadIdx.x;
    const int lane = tid & 31;
    const int wid  = tid >> 5;
    const int wm   = wid & 3;
    const int wn   = wid >> 2;
    const int bm   = blockIdx.y * 128;
    const int bn   = blockIdx.x * 128;

    float c[2][8][4];
#pragma unroll
    for (int mi = 0; mi < 2; mi++)
#pragma unroll
        for (int ni = 0; ni < 8; ni++)
#pragma unroll
            for (int j = 0; j < 4; j++) c[mi][ni][j] = 0.f;

    auto issue = [&](int kt, int stg) {
        const uint32_t sb = sbase + stg * QSTG_B;
#pragma unroll
        for (int j = 0; j < 2; j++) {
            const int cch = tid * 2 + j;
            const int row = cch >> 2;
            const int off = (cch & 3) * 8;
            const uint32_t d = sb + (row * GPAD + off) * 2;
            cp16(d,            Agh + (size_t)(bm + row) * GK + kt * CHK + off);
            cp16(d + GT_H * 2, WTh + (size_t)(bn + row) * GK + kt * CHK + off);
        }
        CP_COMMIT();
    };

    issue(0, 0);
    issue(1, 1);

    for (int kt = 0; kt < NCHK; kt++) {
        CP_WAIT(1);
        __syncthreads();

        const uint32_t stage = sbase + (kt % NSTG) * QSTG_B;
        const uint32_t Ahs = stage;
        const uint32_t Bhs = Ahs + GT_H * 2;

#pragma unroll
        for (int ks = 0; ks < 2; ks++) {
            const int k0 = ks * 16;
            uint32_t ah[8];
#pragma unroll
            for (int mi = 0; mi < 2; mi++) {
                const uint32_t aoff =
                    ((wm * 32 + mi * 16 + (lane & 7) + ((lane >> 3) & 1) * 8) * GPAD
                     + k0 + (lane >> 4) * 8) * 2;
                ldsm4(ah + 4 * mi, Ahs + aoff);
            }
#pragma unroll
            for (int bg = 0; bg < 4; bg++) {
                const uint32_t boff =
                    ((wn * 64 + bg * 16 + (lane & 7) + (lane >> 4) * 8) * GPAD
                     + k0 + ((lane >> 3) & 1) * 8) * 2;
                uint32_t bh[4];
                ldsm4(bh, Bhs + boff);
#pragma unroll
                for (int tt = 0; tt < 2; tt++) {
                    const int ni = bg * 2 + tt;
                    mma_f16(c[0][ni], ah,     bh[2*tt], bh[2*tt+1]);
                    mma_f16(c[1][ni], ah + 4, bh[2*tt], bh[2*tt+1]);
                }
            }
        }
        __syncthreads();
        if (kt + 2 < NCHK) issue(kt + 2, (kt + 2) % NSTG);
        else CP_COMMIT();
    }

#pragma unroll
    for (int mi = 0; mi < 2; mi++) {
        const int row0 = bm + wm * 32 + mi * 16 + (lane >> 2);
#pragma unroll
        for (int ni = 0; ni < 8; ni++) {
            const int col = bn + wn * 64 + ni * 8 + (lane & 3) * 2;
            float2 r0, r1;
            r0.x = c[mi][ni][0]; r0.y = c[mi][ni][1];
            r1.x = c[mi][ni][2]; r1.y = c[mi][ni][3];
            *(float2*)(C + (size_t)row0 * N + col)       = r0;
            *(float2*)(C + (size_t)(row0 + 8) * N + col) = r1;
        }
    }
}

// ======================= Flash attention (single fp16 mma) ================
#define FPAD 136
#define FQT_H (128 * FPAD)
#define FKT_H (64 * FPAD)

__global__ __launch_bounds__(256) void flash_mma(
    const __half* __restrict__ Qg, const __half* __restrict__ Kg,
    const __half* __restrict__ Vg, __half* __restrict__ Oh)
{
    extern __shared__ __half sf[];
    const uint32_t uQ = smem_u32(sf);
    const uint32_t uK = uQ + FQT_H * 2;
    const uint32_t uV = uK + FKT_H * 2;

    const int qb = gridDim.x - 1 - blockIdx.x;   // heavy CTAs first
    const int bh = blockIdx.y;
    const int b  = bh >> 4;
    const int h  = bh & 15;
    const int kvh = h >> 2;
    const int tid = threadIdx.x;
    const int lane = tid & 31;
    const int w = tid >> 5;
    const int q0 = qb * 128;
    const int rowbase = b * S_LEN;

    {
#pragma unroll
        for (int j = 0; j < 8; j++) {
            const int cch = tid * 8 + j;
            const int row = cch >> 4;
            const int off = (cch & 15) * 8;
            const size_t g = (size_t)(rowbase + q0 + row) * (NH * HD) + h * HD + off;
            cp16(uQ + (row * FPAD + off) * 2, Qg + g);
        }
    }
    auto issueKV = [&](int nb) {
#pragma unroll
        for (int j = 0; j < 4; j++) {
            const int cch = tid * 4 + j;
            const int row = cch >> 4;
            const int off = (cch & 15) * 8;
            const size_t g = (size_t)(rowbase + nb * 64 + row) * (NKV * HD) + kvh * HD + off;
            const uint32_t d = (row * FPAD + off) * 2;
            cp16(uK + d, Kg + g);
            cp16(uV + d, Vg + g);
        }
        CP_COMMIT();
    };
    issueKV(0);

    float o[16][4];
#pragma unroll
    for (int ni = 0; ni < 16; ni++)
#pragma unroll
        for (int j = 0; j < 4; j++) o[ni][j] = 0.f;
    float m0 = -1.0e30f, m1 = -1.0e30f, l0 = 0.f, l1 = 0.f;

    const float SC2 = 0.12751744900459843f;  // (1/sqrt(128)) * log2(e)
    const int nblocks = 2 * qb + 2;
    const int wrow0 = q0 + w * 16;

    for (int nb = 0; nb < nblocks; nb++) {
        const int n0 = nb * 64;
        CP_WAIT(0);
        __syncthreads();

        if (n0 <= wrow0 + 15) {
            float s[8][4];
#pragma unroll
            for (int ni = 0; ni < 8; ni++)
#pragma unroll
                for (int j = 0; j < 4; j++) s[ni][j] = 0.f;

#pragma unroll
            for (int ks = 0; ks < 8; ks++) {
                const int k0 = ks * 16;
                uint32_t a4[4];
                const uint32_t aoff =
                    ((w * 16 + (lane & 7) + ((lane >> 3) & 1) * 8) * FPAD
                     + k0 + (lane >> 4) * 8) * 2;
                ldsm4(a4, uQ + aoff);
#pragma unroll
                for (int bg = 0; bg < 4; bg++) {
                    const uint32_t boff =
                        ((bg * 16 + (lane & 7) + (lane >> 4) * 8) * FPAD
                         + k0 + ((lane >> 3) & 1) * 8) * 2;
                    uint32_t b4[4];
                    ldsm4(b4, uK + boff);
                    mma_f16(s[bg * 2],     a4, b4[0], b4[1]);
                    mma_f16(s[bg * 2 + 1], a4, b4[2], b4[3]);
                }
            }

            const int r0g = wrow0 + (lane >> 2);
            const int r1g = r0g + 8;
            const bool diag = (n0 + 63 > wrow0);
            float rmax0 = -1.0e30f, rmax1 = -1.0e30f;
#pragma unroll
            for (int ni = 0; ni < 8; ni++) {
                const int colb = n0 + ni * 8 + (lane & 3) * 2;
#pragma unroll
                for (int j = 0; j < 4; j++) {
                    float z = s[ni][j] * SC2;
                    if (diag) {
                        const int col = colb + (j & 1);
                        const int rw  = (j < 2) ? r0g : r1g;
                        if (col > rw) z = -1.0e30f;
                    }
                    s[ni][j] = z;
                }
                rmax0 = fmaxf(rmax0, fmaxf(s[ni][0], s[ni][1]));
                rmax1 = fmaxf(rmax1, fmaxf(s[ni][2], s[ni][3]));
            }
            rmax0 = fmaxf(rmax0, __shfl_xor_sync(0xffffffffu, rmax0, 1));
            rmax0 = fmaxf(rmax0, __shfl_xor_sync(0xffffffffu, rmax0, 2));
            rmax1 = fmaxf(rmax1, __shfl_xor_sync(0xffffffffu, rmax1, 1));
            rmax1 = fmaxf(rmax1, __shfl_xor_sync(0xffffffffu, rmax1, 2));

            const float mn0 = fmaxf(m0, rmax0);
            const float mn1 = fmaxf(m1, rmax1);
            const float al0 = ex2f(m0 - mn0);
            const float al1 = ex2f(m1 - mn1);
            m0 = mn0; m1 = mn1;

            float ls0 = 0.f, ls1 = 0.f;
#pragma unroll
            for (int ni = 0; ni < 8; ni++) {
                s[ni][0] = ex2f(s[ni][0] - mn0);
                s[ni][1] = ex2f(s[ni][1] - mn0);
                s[ni][2] = ex2f(s[ni][2] - mn1);
                s[ni][3] = ex2f(s[ni][3] - mn1);
                ls0 += s[ni][0] + s[ni][1];
                ls1 += s[ni][2] + s[ni][3];
            }
            l0 = l0 * al0 + ls0;
            l1 = l1 * al1 + ls1;
#pragma unroll
            for (int ni = 0; ni < 16; ni++) {
                o[ni][0] *= al0; o[ni][1] *= al0;
                o[ni][2] *= al1; o[ni][3] *= al1;
            }

#pragma unroll
            for (int kk = 0; kk < 4; kk++) {
                uint32_t ph[4];
                ph[0] = packh2(s[2*kk][0],   s[2*kk][1]);
                ph[1] = packh2(s[2*kk][2],   s[2*kk][3]);
                ph[2] = packh2(s[2*kk+1][0], s[2*kk+1][1]);
                ph[3] = packh2(s[2*kk+1][2], s[2*kk+1][3]);
#pragma unroll
                for (int vg = 0; vg < 8; vg++) {
                    const uint32_t voff =
                        ((kk * 16 + (lane & 7) + ((lane >> 3) & 1) * 8) * FPAD
                         + vg * 16 + (lane >> 4) * 8) * 2;
                    uint32_t v4[4];
                    ldsm4t(v4, uV + voff);
                    mma_f16(o[vg * 2],     ph, v4[0], v4[1]);
                    mma_f16(o[vg * 2 + 1], ph, v4[2], v4[3]);
                }
            }
        }

        __syncthreads();
        if (nb + 1 < nblocks) issueKV(nb + 1);
    }

    float lf0 = l0, lf1 = l1;
    lf0 += __shfl_xor_sync(0xffffffffu, lf0, 1);
    lf0 += __shfl_xor_sync(0xffffffffu, lf0, 2);
    lf1 += __shfl_xor_sync(0xffffffffu, lf1, 1);
    lf1 += __shfl_xor_sync(0xffffffffu, lf1, 2);
    const float inv0 = 1.f / lf0;
    const float inv1 = 1.f / lf1;

    const int gr0 = rowbase + wrow0 + (lane >> 2);
    const int gr1 = gr0 + 8;
#pragma unroll
    for (int ni = 0; ni < 16; ni++) {
        const int col = h * HD + ni * 8 + (lane & 3) * 2;
        *(uint32_t*)(Oh + (size_t)gr0 * (NH * HD) + col) =
            packh2(o[ni][0] * inv0, o[ni][1] * inv0);
        *(uint32_t*)(Oh + (size_t)gr1 * (NH * HD) + col) =
            packh2(o[ni][2] * inv1, o[ni][3] * inv1);
    }
}

// ======================= launch ===========================================
extern "C" void kernel_launch(void* const* d_in, const int* in_sizes, int n_in,
                              void* d_out, int out_size)
{
    const float* hidden = (const float*)d_in[0];
    const float* tvals  = (const float*)d_in[1];
    const float* wq     = (const float*)d_in[2];
    const float* bq     = (const float*)d_in[3];
    const float* wk     = (const float*)d_in[4];
    const float* bk     = (const float*)d_in[5];
    const float* wv     = (const float*)d_in[6];
    const float* bv     = (const float*)d_in[7];
    const float* wo     = (const float*)d_in[8];
    const float* rope_w = (const float*)d_in[9];
    float* out = (float*)d_out;

    float *q, *k;
    __half *hh, *qh, *kh, *vh, *oh, *wqh, *wkh, *wvh, *woh;
    cudaGetSymbolAddress((void**)&q,   g_q);
    cudaGetSymbolAddress((void**)&k,   g_k);
    cudaGetSymbolAddress((void**)&hh,  g_hh);
    cudaGetSymbolAddress((void**)&qh,  g_qh);
    cudaGetSymbolAddress((void**)&kh,  g_kh);
    cudaGetSymbolAddress((void**)&vh,  g_vh);
    cudaGetSymbolAddress((void**)&oh,  g_oh);
    cudaGetSymbolAddress((void**)&wqh, g_wqh);
    cudaGetSymbolAddress((void**)&wkh, g_wkh);
    cudaGetSymbolAddress((void**)&wvh, g_wvh);
    cudaGetSymbolAddress((void**)&woh, g_woh);

    // ---- prep: fused weight convert + hidden convert ----
    {
        dim3 blk(32, 8);
        wconv_all<<<WALL_BLKS, blk>>>(wq, wk, wv, wo, wqh, wkh, wvh, woh);
        int tot = MROWS * HID;
        hconv_kernel<<<(tot + 255) / 256, 256>>>(hidden, hh, tot);
    }

    // ---- merged QKV projection ----
    {
        const int qdyn = NSTG * QSTG_B;  // 61440
        cudaFuncSetAttribute(qkv_gemm, cudaFuncAttributeMaxDynamicSharedMemorySize, qdyn);
        qkv_gemm<<<dim3(24, MROWS/128), 256, qdyn>>>(
            hh, wqh, wkh, wvh, bq, bk, bv, q, k, vh);
    }

    // ---- fused RoPE (Q + K) -> fp16 ----
    {
        int totq = MROWS * NH * 64;
        int totk = MROWS * NKV * 64;
        int tot = totq + totk;
        rope_both<<<(tot + 255) / 256, 256>>>(q, k, tvals, rope_w, qh, kh, totq, tot);
    }

    // ---- Flash attention ----
    {
        const int fdyn = (FQT_H + 2 * FKT_H) * 2;  // 69632 B
        cudaFuncSetAttribute(flash_mma, cudaFuncAttributeMaxDynamicSharedMemorySize, fdyn);
        flash_mma<<<dim3(S_LEN/128, BATCH*NH), 256, fdyn>>>(qh, kh, vh, oh);
    }

    // ---- Output projection (1-term) ----
    {
        const int wdyn = NSTG * QSTG_B;
        cudaFuncSetAttribute(wo_gemm, cudaFuncAttributeMaxDynamicSharedMemorySize, wdyn);
        wo_gemm<<<dim3(HID/128, MROWS/128), 256, wdyn>>>(oh, woh, out, HID);
    }
}

// round 13
// speedup vs baseline: 6.0378x; 1.0644x over previous
#include <cuda_runtime.h>
#include <cuda_fp16.h>
#include <cstdint>
#include <math.h>

#define S_LEN 2048
#define BATCH 2
#define HID   2048
#define NH    16
#define NKV   4
#define HD    128
#define MROWS (BATCH*S_LEN)   // 4096

// ---------------- scratch (static device globals; no runtime alloc) -------
__device__ float g_q[(size_t)MROWS * (NH*HD)];
__device__ float g_k[(size_t)MROWS * (NKV*HD)];
__device__ __half g_hh[(size_t)MROWS * HID];        // hidden fp16
__device__ __half g_qh[(size_t)MROWS * (NH*HD)];    // Q post-rope fp16
__device__ __half g_kh[(size_t)MROWS * (NKV*HD)];   // K post-rope fp16
__device__ __half g_vh[(size_t)MROWS * (NKV*HD)];   // V fp16
__device__ __half g_oh[(size_t)MROWS * (NH*HD)];    // attn out fp16
// fp16 transposed weights [N][K]
__device__ __half g_wqh[(size_t)HID * HID];
__device__ __half g_wkh[(size_t)(NKV*HD) * HID];
__device__ __half g_wvh[(size_t)(NKV*HD) * HID];
__device__ __half g_woh[(size_t)HID * HID];

// ======================= PTX helpers ======================================
__device__ __forceinline__ uint32_t smem_u32(const void* p) {
    uint32_t a;
    asm("{ .reg .u64 t; cvta.to.shared.u64 t, %1; cvt.u32.u64 %0, t; }"
        : "=r"(a) : "l"(p));
    return a;
}
__device__ __forceinline__ void ldsm4(uint32_t* r, uint32_t addr) {
    asm volatile("ldmatrix.sync.aligned.m8n8.x4.shared.b16 {%0,%1,%2,%3}, [%4];"
        : "=r"(r[0]), "=r"(r[1]), "=r"(r[2]), "=r"(r[3]) : "r"(addr));
}
__device__ __forceinline__ void ldsm4t(uint32_t* r, uint32_t addr) {
    asm volatile("ldmatrix.sync.aligned.m8n8.x4.trans.shared.b16 {%0,%1,%2,%3}, [%4];"
        : "=r"(r[0]), "=r"(r[1]), "=r"(r[2]), "=r"(r[3]) : "r"(addr));
}
__device__ __forceinline__ void mma_f16(float* c, const uint32_t* a,
                                        uint32_t b0, uint32_t b1) {
    asm volatile(
        "mma.sync.aligned.m16n8k16.row.col.f32.f16.f16.f32 "
        "{%0,%1,%2,%3}, {%4,%5,%6,%7}, {%8,%9}, {%0,%1,%2,%3};"
        : "+f"(c[0]), "+f"(c[1]), "+f"(c[2]), "+f"(c[3])
        : "r"(a[0]), "r"(a[1]), "r"(a[2]), "r"(a[3]), "r"(b0), "r"(b1));
}
__device__ __forceinline__ float ex2f(float x) {
    float y; asm("ex2.approx.f32 %0, %1;" : "=f"(y) : "f"(x)); return y;
}
__device__ __forceinline__ void cp16(uint32_t dst, const void* src) {
    asm volatile("cp.async.ca.shared.global [%0], [%1], 16;" :: "r"(dst), "l"(src));
}
#define CP_COMMIT() asm volatile("cp.async.commit_group;" ::: "memory")
#define CP_WAIT(N)  asm volatile("cp.async.wait_group %0;" :: "n"(N) : "memory")

__device__ __forceinline__ uint32_t packh2(float a, float b) {
    __half2 t = __floats2half2_rn(a, b);
    return *(uint32_t*)&t;
}

// ======================= fused prep: weights transpose + hidden convert ===
#define WQ_BLKS ((HID/32) * (HID/32))          // 4096
#define WK_BLKS ((HID/32) * ((NKV*HD)/32))     // 1024
#define WV_BLKS WK_BLKS                        // 1024
#define WO_BLKS WQ_BLKS                        // 4096
#define WALL_BLKS (WQ_BLKS + WK_BLKS + WV_BLKS + WO_BLKS)  // 10240
#define HCONV_BLKS ((MROWS * HID) / (256 * 4)) // 8192 (float4 per thread)
#define PREP_BLKS (WALL_BLKS + HCONV_BLKS)     // 18432

__global__ void prep_all(const float* __restrict__ wq, const float* __restrict__ wk,
                         const float* __restrict__ wv, const float* __restrict__ wo,
                         const float* __restrict__ hid,
                         __half* __restrict__ dq, __half* __restrict__ dk,
                         __half* __restrict__ dv, __half* __restrict__ dwo,
                         __half* __restrict__ dh)
{
    const int bid = blockIdx.x;
    const int tid = threadIdx.x;
    if (bid >= WALL_BLKS) {
        // hidden fp32 -> fp16, float4-vectorized
        const size_t i4 = ((size_t)(bid - WALL_BLKS) * 256 + tid) * 4;
        float4 v = *(const float4*)(hid + i4);
        __half2 lo = __floats2half2_rn(v.x, v.y);
        __half2 hi = __floats2half2_rn(v.z, v.w);
        *(uint32_t*)(dh + i4)     = *(uint32_t*)&lo;
        *(uint32_t*)(dh + i4 + 2) = *(uint32_t*)&hi;
        return;
    }
    __shared__ float tile[32][33];
    const float* src; __half* dst; int N, lb;
    if (bid < WQ_BLKS) {
        src = wq; dst = dq;  N = HID;    lb = bid;
    } else if (bid < WQ_BLKS + WK_BLKS) {
        src = wk; dst = dk;  N = NKV*HD; lb = bid - WQ_BLKS;
    } else if (bid < WQ_BLKS + WK_BLKS + WV_BLKS) {
        src = wv; dst = dv;  N = NKV*HD; lb = bid - WQ_BLKS - WK_BLKS;
    } else {
        src = wo; dst = dwo; N = HID;    lb = bid - WQ_BLKS - WK_BLKS - WV_BLKS;
    }
    const int kb = HID / 32;             // 64 k-blocks in all weights
    const int k0 = (lb % kb) * 32;
    const int n0 = (lb / kb) * 32;
    const int x = tid & 31;
    const int y0 = tid >> 5;             // 0..7
#pragma unroll
    for (int y = y0; y < 32; y += 8)
        tile[y][x] = src[(size_t)(k0 + y) * N + n0 + x];
    __syncthreads();
#pragma unroll
    for (int y = y0; y < 32; y += 8)
        dst[(size_t)(n0 + y) * HID + k0 + x] = __float2half_rn(tile[x][y]);
}

// ======================= RoPE: 1 trig per (bs,i), applied to all heads ====
__global__ void rope_both(const float* __restrict__ Qf, const float* __restrict__ Kf,
                          const float* __restrict__ tvals, const float* __restrict__ rope_w,
                          __half* __restrict__ Qh, __half* __restrict__ Kh)
{
    const int idx = blockIdx.x * blockDim.x + threadIdx.x;
    if (idx >= MROWS * 64) return;
    const int i  = idx & 63;
    const int bs = idx >> 6;

    const float t = tvals[bs];
    const float inv_f = expf(-(float)(2 * i) * (9.210340371976184f / 128.0f));
    const float fr = t * inv_f * rope_w[i];
    const float cs = cosf(fr);
    const float sn = sinf(fr);

    const float* qrow = Qf + (size_t)bs * (NH * HD);
    __half* qo = Qh + (size_t)bs * (NH * HD);
#pragma unroll
    for (int h = 0; h < NH; h++) {
        const float x1 = qrow[h * HD + i];
        const float x2 = qrow[h * HD + i + 64];
        qo[h * HD + i]      = __float2half_rn(x1 * cs - x2 * sn);
        qo[h * HD + i + 64] = __float2half_rn(x2 * cs + x1 * sn);
    }
    const float* krow = Kf + (size_t)bs * (NKV * HD);
    __half* ko = Kh + (size_t)bs * (NKV * HD);
#pragma unroll
    for (int h = 0; h < NKV; h++) {
        const float x1 = krow[h * HD + i];
        const float x2 = krow[h * HD + i + 64];
        ko[h * HD + i]      = __float2half_rn(x1 * cs - x2 * sn);
        ko[h * HD + i + 64] = __float2half_rn(x2 * cs + x1 * sn);
    }
}

// ======================= GEMM common ======================================
#define GK   HID
#define CHK  32
#define NCHK (GK / CHK)        // 64
#define GPAD 40
#define GT_H (128 * GPAD)
#define NSTG 3
#define QSTG_B (2 * GT_H * 2)  // A + B per stage (20480 B)
#define GRID_PERS 444          // 148 SMs x 3 CTAs (smem-limited)

// ---------- merged QKV GEMM: 1-term fp16, grid-stride over 24x32 tiles ----
#define QKV_TILES (24 * (MROWS/128))   // 768

__global__ __launch_bounds__(256) void qkv_gemm(
    const __half* __restrict__ Ah16,
    const __half* __restrict__ wq16, const __half* __restrict__ wk16,
    const __half* __restrict__ wv16,
    const float* __restrict__ bq, const float* __restrict__ bk,
    const float* __restrict__ bv,
    float* __restrict__ Qo, float* __restrict__ Ko, __half* __restrict__ Vo)
{
    extern __shared__ __half sg[];
    const uint32_t sbase = smem_u32(sg);

    const int tid  = threadIdx.x;
    const int lane = tid & 31;
    const int wid  = tid >> 5;
    const int wm   = wid & 3;
    const int wn   = wid >> 2;

    for (int tile = blockIdx.x; tile < QKV_TILES; tile += GRID_PERS) {
        const int nx = tile % 24;
        const int bm = (tile / 24) * 128;

        const __half* WT; const float* bias;
        float* outF = nullptr; __half* outH = nullptr;
        int N, bn;
        if (nx < 16)      { WT = wq16; bias = bq; outF = Qo; N = NH*HD;  bn = nx * 128; }
        else if (nx < 20) { WT = wk16; bias = bk; outF = Ko; N = NKV*HD; bn = (nx-16) * 128; }
        else              { WT = wv16; bias = bv; outH = Vo; N = NKV*HD; bn = (nx-20) * 128; }

        float c[2][8][4];
#pragma unroll
        for (int mi = 0; mi < 2; mi++)
#pragma unroll
            for (int ni = 0; ni < 8; ni++)
#pragma unroll
                for (int j = 0; j < 4; j++) c[mi][ni][j] = 0.f;

        auto issue = [&](int kt, int stg) {
            const uint32_t sb = sbase + stg * QSTG_B;
#pragma unroll
            for (int j = 0; j < 2; j++) {
                const int cch = tid * 2 + j;
                const int row = cch >> 2;
                const int off = (cch & 3) * 8;
                const uint32_t d = sb + (row * GPAD + off) * 2;
                cp16(d,            Ah16 + (size_t)(bm + row) * GK + kt * CHK + off);
                cp16(d + GT_H * 2, WT   + (size_t)(bn + row) * GK + kt * CHK + off);
            }
            CP_COMMIT();
        };

        issue(0, 0);
        issue(1, 1);

        for (int kt = 0; kt < NCHK; kt++) {
            CP_WAIT(1);
            __syncthreads();

            const uint32_t stage = sbase + (kt % NSTG) * QSTG_B;
            const uint32_t Ahs = stage;
            const uint32_t Bhs = Ahs + GT_H * 2;

#pragma unroll
            for (int ks = 0; ks < 2; ks++) {
                const int k0 = ks * 16;
                uint32_t ah[8];
#pragma unroll
                for (int mi = 0; mi < 2; mi++) {
                    const uint32_t aoff =
                        ((wm * 32 + mi * 16 + (lane & 7) + ((lane >> 3) & 1) * 8) * GPAD
                         + k0 + (lane >> 4) * 8) * 2;
                    ldsm4(ah + 4 * mi, Ahs + aoff);
                }
#pragma unroll
                for (int bg = 0; bg < 4; bg++) {
                    const uint32_t boff =
                        ((wn * 64 + bg * 16 + (lane & 7) + (lane >> 4) * 8) * GPAD
                         + k0 + ((lane >> 3) & 1) * 8) * 2;
                    uint32_t bh[4];
                    ldsm4(bh, Bhs + boff);
#pragma unroll
                    for (int tt = 0; tt < 2; tt++) {
                        const int ni = bg * 2 + tt;
                        mma_f16(c[0][ni], ah,     bh[2*tt], bh[2*tt+1]);
                        mma_f16(c[1][ni], ah + 4, bh[2*tt], bh[2*tt+1]);
                    }
                }
            }
            __syncthreads();
            if (kt + 2 < NCHK) issue(kt + 2, (kt + 2) % NSTG);
            else CP_COMMIT();
        }

#pragma unroll
        for (int mi = 0; mi < 2; mi++) {
            const int row0 = bm + wm * 32 + mi * 16 + (lane >> 2);
#pragma unroll
            for (int ni = 0; ni < 8; ni++) {
                const int col = bn + wn * 64 + ni * 8 + (lane & 3) * 2;
                const float b0 = __ldg(bias + col);
                const float b1 = __ldg(bias + col + 1);
                const float y00 = c[mi][ni][0] + b0, y01 = c[mi][ni][1] + b1;
                const float y10 = c[mi][ni][2] + b0, y11 = c[mi][ni][3] + b1;
                if (outH) {
                    *(uint32_t*)(outH + (size_t)row0 * N + col)       = packh2(y00, y01);
                    *(uint32_t*)(outH + (size_t)(row0 + 8) * N + col) = packh2(y10, y11);
                } else {
                    float2 r0, r1;
                    r0.x = y00; r0.y = y01;
                    r1.x = y10; r1.y = y11;
                    *(float2*)(outF + (size_t)row0 * N + col)       = r0;
                    *(float2*)(outF + (size_t)(row0 + 8) * N + col) = r1;
                }
            }
        }
    }
}

// ---------- WO GEMM: grid-stride over 16x32 tiles -------------------------
#define WO_TILES ((HID/128) * (MROWS/128))   // 512

__global__ __launch_bounds__(256) void wo_gemm(
    const __half* __restrict__ Agh, const __half* __restrict__ WTh,
    float* __restrict__ C, int N)
{
    extern __shared__ __half sg[];
    const uint32_t sbase = smem_u32(sg);

    const int tid  = threadIdx.x;
    const int lane = tid & 31;
    const int wid  = tid >> 5;
    const int wm   = wid & 3;
    const int wn   = wid >> 2;

    for (int tile = blockIdx.x; tile < WO_TILES; tile += GRID_PERS) {
        const int bn = (tile % (HID/128)) * 128;
        const int bm = (tile / (HID/128)) * 128;

        float c[2][8][4];
#pragma unroll
        for (int mi = 0; mi < 2; mi++)
#pragma unroll
            for (int ni = 0; ni < 8; ni++)
#pragma unroll
                for (int j = 0; j < 4; j++) c[mi][ni][j] = 0.f;

        auto issue = [&](int kt, int stg) {
            const uint32_t sb = sbase + stg * QSTG_B;
#pragma unroll
            for (int j = 0; j < 2; j++) {
                const int cch = tid * 2 + j;
                const int row = cch >> 2;
                const int off = (cch & 3) * 8;
                const uint32_t d = sb + (row * GPAD + off) * 2;
                cp16(d,            Agh + (size_t)(bm + row) * GK + kt * CHK + off);
                cp16(d + GT_H * 2, WTh + (size_t)(bn + row) * GK + kt * CHK + off);
            }
            CP_COMMIT();
        };

        issue(0, 0);
        issue(1, 1);

        for (int kt = 0; kt < NCHK; kt++) {
            CP_WAIT(1);
            __syncthreads();

            const uint32_t stage = sbase + (kt % NSTG) * QSTG_B;
            const uint32_t Ahs = stage;
            const uint32_t Bhs = Ahs + GT_H * 2;

#pragma unroll
            for (int ks = 0; ks < 2; ks++) {
                const int k0 = ks * 16;
                uint32_t ah[8];
#pragma unroll
                for (int mi = 0; mi < 2; mi++) {
                    const uint32_t aoff =
                        ((wm * 32 + mi * 16 + (lane & 7) + ((lane >> 3) & 1) * 8) * GPAD
                         + k0 + (lane >> 4) * 8) * 2;
                    ldsm4(ah + 4 * mi, Ahs + aoff);
                }
#pragma unroll
                for (int bg = 0; bg < 4; bg++) {
                    const uint32_t boff =
                        ((wn * 64 + bg * 16 + (lane & 7) + (lane >> 4) * 8) * GPAD
                         + k0 + ((lane >> 3) & 1) * 8) * 2;
                    uint32_t bh[4];
                    ldsm4(bh, Bhs + boff);
#pragma unroll
                    for (int tt = 0; tt < 2; tt++) {
                        const int ni = bg * 2 + tt;
                        mma_f16(c[0][ni], ah,     bh[2*tt], bh[2*tt+1]);
                        mma_f16(c[1][ni], ah + 4, bh[2*tt], bh[2*tt+1]);
                    }
                }
            }
            __syncthreads();
            if (kt + 2 < NCHK) issue(kt + 2, (kt + 2) % NSTG);
            else CP_COMMIT();
        }

#pragma unroll
        for (int mi = 0; mi < 2; mi++) {
            const int row0 = bm + wm * 32 + mi * 16 + (lane >> 2);
#pragma unroll
            for (int ni = 0; ni < 8; ni++) {
                const int col = bn + wn * 64 + ni * 8 + (lane & 3) * 2;
                float2 r0, r1;
                r0.x = c[mi][ni][0]; r0.y = c[mi][ni][1];
                r1.x = c[mi][ni][2]; r1.y = c[mi][ni][3];
                *(float2*)(C + (size_t)row0 * N + col)       = r0;
                *(float2*)(C + (size_t)(row0 + 8) * N + col) = r1;
            }
        }
    }
}

// ======================= Flash attention (single fp16 mma) ================
#define FPAD 136
#define FQT_H (128 * FPAD)
#define FKT_H (64 * FPAD)

__global__ __launch_bounds__(256) void flash_mma(
    const __half* __restrict__ Qg, const __half* __restrict__ Kg,
    const __half* __restrict__ Vg, __half* __restrict__ Oh)
{
    extern __shared__ __half sf[];
    const uint32_t uQ = smem_u32(sf);
    const uint32_t uK = uQ + FQT_H * 2;
    const uint32_t uV = uK + FKT_H * 2;

    const int qb = gridDim.x - 1 - blockIdx.x;   // heavy CTAs first
    const int bh = blockIdx.y;
    const int b  = bh >> 4;
    const int h  = bh & 15;
    const int kvh = h >> 2;
    const int tid = threadIdx.x;
    const int lane = tid & 31;
    const int w = tid >> 5;
    const int q0 = qb * 128;
    const int rowbase = b * S_LEN;

    {
#pragma unroll
        for (int j = 0; j < 8; j++) {
            const int cch = tid * 8 + j;
            const int row = cch >> 4;
            const int off = (cch & 15) * 8;
            const size_t g = (size_t)(rowbase + q0 + row) * (NH * HD) + h * HD + off;
            cp16(uQ + (row * FPAD + off) * 2, Qg + g);
        }
    }
    auto issueKV = [&](int nb) {
#pragma unroll
        for (int j = 0; j < 4; j++) {
            const int cch = tid * 4 + j;
            const int row = cch >> 4;
            const int off = (cch & 15) * 8;
            const size_t g = (size_t)(rowbase + nb * 64 + row) * (NKV * HD) + kvh * HD + off;
            const uint32_t d = (row * FPAD + off) * 2;
            cp16(uK + d, Kg + g);
            cp16(uV + d, Vg + g);
        }
        CP_COMMIT();
    };
    issueKV(0);

    float o[16][4];
#pragma unroll
    for (int ni = 0; ni < 16; ni++)
#pragma unroll
        for (int j = 0; j < 4; j++) o[ni][j] = 0.f;
    float m0 = -1.0e30f, m1 = -1.0e30f, l0 = 0.f, l1 = 0.f;

    const float SC2 = 0.12751744900459843f;  // (1/sqrt(128)) * log2(e)
    const int nblocks = 2 * qb + 2;
    const int wrow0 = q0 + w * 16;

    for (int nb = 0; nb < nblocks; nb++) {
        const int n0 = nb * 64;
        CP_WAIT(0);
        __syncthreads();

        if (n0 <= wrow0 + 15) {
            float s[8][4];
#pragma unroll
            for (int ni = 0; ni < 8; ni++)
#pragma unroll
                for (int j = 0; j < 4; j++) s[ni][j] = 0.f;

#pragma unroll
            for (int ks = 0; ks < 8; ks++) {
                const int k0 = ks * 16;
                uint32_t a4[4];
                const uint32_t aoff =
                    ((w * 16 + (lane & 7) + ((lane >> 3) & 1) * 8) * FPAD
                     + k0 + (lane >> 4) * 8) * 2;
                ldsm4(a4, uQ + aoff);
#pragma unroll
                for (int bg = 0; bg < 4; bg++) {
                    const uint32_t boff =
                        ((bg * 16 + (lane & 7) + (lane >> 4) * 8) * FPAD
                         + k0 + ((lane >> 3) & 1) * 8) * 2;
                    uint32_t b4[4];
                    ldsm4(b4, uK + boff);
                    mma_f16(s[bg * 2],     a4, b4[0], b4[1]);
                    mma_f16(s[bg * 2 + 1], a4, b4[2], b4[3]);
                }
            }

            const int r0g = wrow0 + (lane >> 2);
            const int r1g = r0g + 8;
            const bool diag = (n0 + 63 > wrow0);
            float rmax0 = -1.0e30f, rmax1 = -1.0e30f;
#pragma unroll
            for (int ni = 0; ni < 8; ni++) {
                const int colb = n0 + ni * 8 + (lane & 3) * 2;
#pragma unroll
                for (int j = 0; j < 4; j++) {
                    float z = s[ni][j] * SC2;
                    if (diag) {
                        const int col = colb + (j & 1);
                        const int rw  = (j < 2) ? r0g : r1g;
                        if (col > rw) z = -1.0e30f;
                    }
                    s[ni][j] = z;
                }
                rmax0 = fmaxf(rmax0, fmaxf(s[ni][0], s[ni][1]));
                rmax1 = fmaxf(rmax1, fmaxf(s[ni][2], s[ni][3]));
            }
            rmax0 = fmaxf(rmax0, __shfl_xor_sync(0xffffffffu, rmax0, 1));
            rmax0 = fmaxf(rmax0, __shfl_xor_sync(0xffffffffu, rmax0, 2));
            rmax1 = fmaxf(rmax1, __shfl_xor_sync(0xffffffffu, rmax1, 1));
            rmax1 = fmaxf(rmax1, __shfl_xor_sync(0xffffffffu, rmax1, 2));

            const float mn0 = fmaxf(m0, rmax0);
            const float mn1 = fmaxf(m1, rmax1);
            const float al0 = ex2f(m0 - mn0);
            const float al1 = ex2f(m1 - mn1);
            m0 = mn0; m1 = mn1;

            float ls0 = 0.f, ls1 = 0.f;
#pragma unroll
            for (int ni = 0; ni < 8; ni++) {
                s[ni][0] = ex2f(s[ni][0] - mn0);
                s[ni][1] = ex2f(s[ni][1] - mn0);
                s[ni][2] = ex2f(s[ni][2] - mn1);
                s[ni][3] = ex2f(s[ni][3] - mn1);
                ls0 += s[ni][0] + s[ni][1];
                ls1 += s[ni][2] + s[ni][3];
            }
            l0 = l0 * al0 + ls0;
            l1 = l1 * al1 + ls1;
#pragma unroll
            for (int ni = 0; ni < 16; ni++) {
                o[ni][0] *= al0; o[ni][1] *= al0;
                o[ni][2] *= al1; o[ni][3] *= al1;
            }

#pragma unroll
            for (int kk = 0; kk < 4; kk++) {
                uint32_t ph[4];
                ph[0] = packh2(s[2*kk][0],   s[2*kk][1]);
                ph[1] = packh2(s[2*kk][2],   s[2*kk][3]);
                ph[2] = packh2(s[2*kk+1][0], s[2*kk+1][1]);
                ph[3] = packh2(s[2*kk+1][2], s[2*kk+1][3]);
#pragma unroll
                for (int vg = 0; vg < 8; vg++) {
                    const uint32_t voff =
                        ((kk * 16 + (lane & 7) + ((lane >> 3) & 1) * 8) * FPAD
                         + vg * 16 + (lane >> 4) * 8) * 2;
                    uint32_t v4[4];
                    ldsm4t(v4, uV + voff);
                    mma_f16(o[vg * 2],     ph, v4[0], v4[1]);
                    mma_f16(o[vg * 2 + 1], ph, v4[2], v4[3]);
                }
            }
        }

        __syncthreads();
        if (nb + 1 < nblocks) issueKV(nb + 1);
    }

    float lf0 = l0, lf1 = l1;
    lf0 += __shfl_xor_sync(0xffffffffu, lf0, 1);
    lf0 += __shfl_xor_sync(0xffffffffu, lf0, 2);
    lf1 += __shfl_xor_sync(0xffffffffu, lf1, 1);
    lf1 += __shfl_xor_sync(0xffffffffu, lf1, 2);
    const float inv0 = 1.f / lf0;
    const float inv1 = 1.f / lf1;

    const int gr0 = rowbase + wrow0 + (lane >> 2);
    const int gr1 = gr0 + 8;
#pragma unroll
    for (int ni = 0; ni < 16; ni++) {
        const int col = h * HD + ni * 8 + (lane & 3) * 2;
        *(uint32_t*)(Oh + (size_t)gr0 * (NH * HD) + col) =
            packh2(o[ni][0] * inv0, o[ni][1] * inv0);
        *(uint32_t*)(Oh + (size_t)gr1 * (NH * HD) + col) =
            packh2(o[ni][2] * inv1, o[ni][3] * inv1);
    }
}

// ======================= launch ===========================================
extern "C" void kernel_launch(void* const* d_in, const int* in_sizes, int n_in,
                              void* d_out, int out_size)
{
    const float* hidden = (const float*)d_in[0];
    const float* tvals  = (const float*)d_in[1];
    const float* wq     = (const float*)d_in[2];
    const float* bq     = (const float*)d_in[3];
    const float* wk     = (const float*)d_in[4];
    const float* bk     = (const float*)d_in[5];
    const float* wv     = (const float*)d_in[6];
    const float* bv     = (const float*)d_in[7];
    const float* wo     = (const float*)d_in[8];
    const float* rope_w = (const float*)d_in[9];
    float* out = (float*)d_out;

    float *q, *k;
    __half *hh, *qh, *kh, *vh, *oh, *wqh, *wkh, *wvh, *woh;
    cudaGetSymbolAddress((void**)&q,   g_q);
    cudaGetSymbolAddress((void**)&k,   g_k);
    cudaGetSymbolAddress((void**)&hh,  g_hh);
    cudaGetSymbolAddress((void**)&qh,  g_qh);
    cudaGetSymbolAddress((void**)&kh,  g_kh);
    cudaGetSymbolAddress((void**)&vh,  g_vh);
    cudaGetSymbolAddress((void**)&oh,  g_oh);
    cudaGetSymbolAddress((void**)&wqh, g_wqh);
    cudaGetSymbolAddress((void**)&wkh, g_wkh);
    cudaGetSymbolAddress((void**)&wvh, g_wvh);
    cudaGetSymbolAddress((void**)&woh, g_woh);

    // ---- prep: fused weight transpose + hidden convert (one launch) ----
    prep_all<<<PREP_BLKS, 256>>>(wq, wk, wv, wo, hidden, wqh, wkh, wvh, woh, hh);

    // ---- merged QKV projection (grid-stride persistent) ----
    {
        const int qdyn = NSTG * QSTG_B;  // 61440
        cudaFuncSetAttribute(qkv_gemm, cudaFuncAttributeMaxDynamicSharedMemorySize, qdyn);
        qkv_gemm<<<GRID_PERS, 256, qdyn>>>(
            hh, wqh, wkh, wvh, bq, bk, bv, q, k, vh);
    }

    // ---- RoPE: one trig per (bs,i), all heads ----
    {
        int tot = MROWS * 64;
        rope_both<<<(tot + 255) / 256, 256>>>(q, k, tvals, rope_w, qh, kh);
    }

    // ---- Flash attention ----
    {
        const int fdyn = (FQT_H + 2 * FKT_H) * 2;  // 69632 B
        cudaFuncSetAttribute(flash_mma, cudaFuncAttributeMaxDynamicSharedMemorySize, fdyn);
        flash_mma<<<dim3(S_LEN/128, BATCH*NH), 256, fdyn>>>(qh, kh, vh, oh);
    }

    // ---- Output projection (grid-stride persistent) ----
    {
        const int wdyn = NSTG * QSTG_B;
        cudaFuncSetAttribute(wo_gemm, cudaFuncAttributeMaxDynamicSharedMemorySize, wdyn);
        wo_gemm<<<GRID_PERS, 256, wdyn>>>(oh, woh, out, HID);
    }
}